// round 1
// baseline (speedup 1.0000x reference)
#include <cuda_runtime.h>
#include <math.h>

// Problem constants
#define BB 8
#define TT 1024
#define IN_DIM 16
#define DD 256
#define HH 8
#define DK 32
#define LL 4
#define NROW (BB*TT)          // 8192 tokens
#define LN_EPS 1e-5f

// -------- scratch (device globals; no allocations allowed) --------
__device__ float g_h[NROW*DD];        // hidden state (residual stream)
__device__ float g_qkv[NROW*3*DD];    // qkv projection output
__device__ float g_attn[NROW*DD];     // attention output (pre-Wout)
__device__ float g_o[NROW*DD];        // Wout output (pre-LN)

// ============================================================
// 1. Projection: h = x @ Wp + bp + pos
// ============================================================
__global__ void proj_kernel(const float* __restrict__ x,
                            const float* __restrict__ Wp,
                            const float* __restrict__ bp,
                            const float* __restrict__ pos) {
    int idx = blockIdx.x * blockDim.x + threadIdx.x;
    if (idx >= NROW * DD) return;
    int row = idx / DD;
    int col = idx - row * DD;
    int t = row & (TT - 1);
    const float* xr = x + row * IN_DIM;
    float s = bp[col] + pos[t * DD + col];
#pragma unroll
    for (int i = 0; i < IN_DIM; i++)
        s = fmaf(xr[i], Wp[i * DD + col], s);
    g_h[idx] = s;
}

// ============================================================
// 2. Tiled fp32 GEMM with bias epilogue
//    mode 0: C=g_qkv = g_h @ Bmat + bias    (N=768)
//    mode 1: C=g_o   = g_attn @ Bmat + bias (N=256)
//    K = 256 always. M = 8192. Tiles 64x64x16, 256 thr, 4x4/thr.
// ============================================================
#define GBM 64
#define GBN 64
#define GBK 16
__global__ __launch_bounds__(256)
void gemm_bias_kernel(int mode,
                      const float* __restrict__ Bmat,
                      const float* __restrict__ bias,
                      int N) {
    const int K = DD;
    const float* __restrict__ A = (mode == 0) ? g_h : g_attn;
    float* __restrict__ C       = (mode == 0) ? g_qkv : g_o;

    __shared__ float As[GBM][GBK];
    __shared__ float Bs[GBK][GBN + 1];

    int tid = threadIdx.x;
    int tx = tid & 15;          // 0..15 -> N
    int ty = tid >> 4;          // 0..15 -> M
    int blockRow = blockIdx.y * GBM;
    int blockCol = blockIdx.x * GBN;

    float acc[4][4] = {};

    for (int k0 = 0; k0 < K; k0 += GBK) {
        // load A tile: 64x16 = 1024 elems, 4/thread, coalesced along K
#pragma unroll
        for (int i = 0; i < 4; i++) {
            int e = tid + i * 256;
            int r = e >> 4;           // /GBK
            int c = e & 15;
            As[r][c] = A[(blockRow + r) * K + k0 + c];
        }
        // load B tile: 16x64 = 1024 elems, coalesced along N
#pragma unroll
        for (int i = 0; i < 4; i++) {
            int e = tid + i * 256;
            int r = e >> 6;           // /GBN
            int c = e & 63;
            Bs[r][c] = Bmat[(k0 + r) * N + blockCol + c];
        }
        __syncthreads();
#pragma unroll
        for (int kk = 0; kk < GBK; kk++) {
            float a[4], b[4];
#pragma unroll
            for (int i = 0; i < 4; i++) a[i] = As[ty * 4 + i][kk];
#pragma unroll
            for (int j = 0; j < 4; j++) b[j] = Bs[kk][tx * 4 + j];
#pragma unroll
            for (int i = 0; i < 4; i++)
#pragma unroll
                for (int j = 0; j < 4; j++)
                    acc[i][j] = fmaf(a[i], b[j], acc[i][j]);
        }
        __syncthreads();
    }

#pragma unroll
    for (int i = 0; i < 4; i++) {
        int row = blockRow + ty * 4 + i;
#pragma unroll
        for (int j = 0; j < 4; j++) {
            int col = blockCol + tx * 4 + j;
            C[row * N + col] = acc[i][j] + bias[col];
        }
    }
}

// ============================================================
// 3. Flash attention (non-causal, full T x T), online softmax.
//    One thread per query; q[32], acc[32] in registers.
//    grid: (T/128, H, B), block 128. K/V tiles of 32 rows in smem.
// ============================================================
__global__ __launch_bounds__(128)
void attn_kernel() {
    const int t = blockIdx.x * 128 + threadIdx.x;
    const int h = blockIdx.y;
    const int b = blockIdx.z;
    const float scale = 0.17677669529663687f;   // 1/sqrt(32)

    const float* qptr = g_qkv + (size_t)(b * TT + t) * (3 * DD) + h * DK;
    float q[DK];
#pragma unroll
    for (int d = 0; d < DK; d++) q[d] = qptr[d] * scale;

    float m = -1e30f, l = 0.0f;
    float acc[DK];
#pragma unroll
    for (int d = 0; d < DK; d++) acc[d] = 0.0f;

    __shared__ float Ks[32][DK];
    __shared__ float Vs[32][DK];

    for (int k0 = 0; k0 < TT; k0 += 32) {
        __syncthreads();
        // cooperative load of 32 K rows + 32 V rows (1024 floats each)
        for (int i = threadIdx.x; i < 32 * DK; i += 128) {
            int r = i >> 5;     // /DK
            int c = i & 31;
            const float* base = g_qkv + (size_t)(b * TT + k0 + r) * (3 * DD) + h * DK;
            Ks[r][c] = base[DD + c];       // K block = cols [D, 2D)
            Vs[r][c] = base[2 * DD + c];   // V block = cols [2D, 3D)
        }
        __syncthreads();

#pragma unroll 4
        for (int j = 0; j < 32; j++) {
            float s = 0.0f;
#pragma unroll
            for (int d = 0; d < DK; d++)
                s = fmaf(q[d], Ks[j][d], s);       // broadcast smem reads
            float nm = fmaxf(m, s);
            float f = __expf(m - nm);
            float p = __expf(s - nm);
            l = l * f + p;
#pragma unroll
            for (int d = 0; d < DK; d++)
                acc[d] = fmaf(acc[d], f, p * Vs[j][d]);
            m = nm;
        }
    }

    float inv = 1.0f / l;
    float* optr = g_attn + (size_t)(b * TT + t) * DD + h * DK;
#pragma unroll
    for (int d = 0; d < DK; d++) optr[d] = acc[d] * inv;
}

// ============================================================
// 4. Residual add + LayerNorm: h = LN(g_o + g_h) * gamma + beta
//    One block (256 thr) per row.
// ============================================================
__global__ __launch_bounds__(256)
void ln_kernel(const float* __restrict__ gamma,
               const float* __restrict__ beta) {
    int row = blockIdx.x;
    int tid = threadIdx.x;
    float v = g_o[row * DD + tid] + g_h[row * DD + tid];

    __shared__ float ssum[8], ssq[8];
    float s = v, sq = v * v;
#pragma unroll
    for (int o = 16; o > 0; o >>= 1) {
        s  += __shfl_xor_sync(0xffffffffu, s,  o);
        sq += __shfl_xor_sync(0xffffffffu, sq, o);
    }
    int w = tid >> 5, lane = tid & 31;
    if (lane == 0) { ssum[w] = s; ssq[w] = sq; }
    __syncthreads();
    float tot = 0.0f, totq = 0.0f;
#pragma unroll
    for (int i = 0; i < 8; i++) { tot += ssum[i]; totq += ssq[i]; }
    float mu  = tot * (1.0f / DD);
    float var = totq * (1.0f / DD) - mu * mu;
    float rs  = rsqrtf(var + LN_EPS);
    g_h[row * DD + tid] = (v - mu) * rs * gamma[tid] + beta[tid];
}

// ============================================================
// 5. Head: out[b, j] = h[b, T-1, :] . Wo[:, j] + bo[j]
//    grid 24 warps (one per output element)
// ============================================================
__global__ void head_kernel(const float* __restrict__ Wo,
                            const float* __restrict__ bo,
                            float* __restrict__ out) {
    int b = blockIdx.x / 3;
    int j = blockIdx.x - b * 3;
    int lane = threadIdx.x;
    const float* hr = g_h + (size_t)(b * TT + (TT - 1)) * DD;
    float s = 0.0f;
    for (int d = lane; d < DD; d += 32)
        s = fmaf(hr[d], Wo[d * 3 + j], s);
#pragma unroll
    for (int o = 16; o > 0; o >>= 1)
        s += __shfl_xor_sync(0xffffffffu, s, o);
    if (lane == 0) out[b * 3 + j] = s + bo[j];
}

// ============================================================
// launch
// ============================================================
extern "C" void kernel_launch(void* const* d_in, const int* in_sizes, int n_in,
                              void* d_out, int out_size) {
    const float* x    = (const float*)d_in[0];
    const float* Wp   = (const float*)d_in[1];
    const float* bp   = (const float*)d_in[2];
    const float* pos  = (const float*)d_in[3];
    const float* Wqkv = (const float*)d_in[4];
    const float* bqkv = (const float*)d_in[5];
    const float* Wout = (const float*)d_in[6];
    const float* bout = (const float*)d_in[7];
    const float* ln_g = (const float*)d_in[8];
    const float* ln_b = (const float*)d_in[9];
    const float* Wo   = (const float*)d_in[10];
    const float* bo   = (const float*)d_in[11];
    float* out = (float*)d_out;

    proj_kernel<<<(NROW * DD + 255) / 256, 256>>>(x, Wp, bp, pos);

    for (int l = 0; l < LL; l++) {
        // qkv = h @ Wqkv[l] + bqkv[l]
        gemm_bias_kernel<<<dim3((3 * DD) / GBN, NROW / GBM), 256>>>(
            0, Wqkv + (size_t)l * DD * 3 * DD, bqkv + (size_t)l * 3 * DD, 3 * DD);
        // attention
        attn_kernel<<<dim3(TT / 128, HH, BB), 128>>>();
        // o = attn @ Wout[l] + bout[l]
        gemm_bias_kernel<<<dim3(DD / GBN, NROW / GBM), 256>>>(
            1, Wout + (size_t)l * DD * DD, bout + (size_t)l * DD, DD);
        // h = LN(o + h)
        ln_kernel<<<NROW, 256>>>(ln_g + (size_t)l * DD, ln_b + (size_t)l * DD);
    }

    head_kernel<<<24, 32>>>(Wo, bo, out);
}

// round 2
// speedup vs baseline: 1.3527x; 1.3527x over previous
#include <cuda_runtime.h>
#include <math.h>

// Problem constants
#define BB 8
#define TT 1024
#define IN_DIM 16
#define DD 256
#define HH 8
#define DK 32
#define LL 4
#define NROW (BB*TT)          // 8192 tokens
#define LN_EPS 1e-5f

// -------- scratch (device globals; no allocations allowed) --------
__device__ float g_h[NROW*DD];        // hidden state (residual stream)
__device__ float g_qkv[NROW*3*DD];    // qkv projection output
__device__ float g_attn[NROW*DD];     // attention output (pre-Wout)
__device__ float g_o[NROW*DD];        // Wout output (pre-LN)

// ============================================================
// 1. Projection: h = x @ Wp + bp + pos
// ============================================================
__global__ void proj_kernel(const float* __restrict__ x,
                            const float* __restrict__ Wp,
                            const float* __restrict__ bp,
                            const float* __restrict__ pos) {
    int idx = blockIdx.x * blockDim.x + threadIdx.x;
    if (idx >= NROW * DD) return;
    int row = idx / DD;
    int col = idx - row * DD;
    int t = row & (TT - 1);
    const float* xr = x + row * IN_DIM;
    float s = bp[col] + pos[t * DD + col];
#pragma unroll
    for (int i = 0; i < IN_DIM; i++)
        s = fmaf(xr[i], Wp[i * DD + col], s);
    g_h[idx] = s;
}

// ============================================================
// 2. Tiled fp32 GEMM with bias epilogue. 128x64 tile, 256 thr,
//    8x4 per-thread microtile, float4 loads everywhere.
//    mode 0: g_qkv = g_h @ Bmat + bias    (N=768)
//    mode 1: g_o   = g_attn @ Bmat + bias (N=256)
// ============================================================
#define GM 128
#define GN 64
#define GK 16
__global__ __launch_bounds__(256)
void gemm_bias_kernel(int mode,
                      const float* __restrict__ Bmat,
                      const float* __restrict__ bias,
                      int N) {
    const int K = DD;
    const float* __restrict__ A = (mode == 0) ? g_h : g_attn;
    float* __restrict__ C       = (mode == 0) ? g_qkv : g_o;

    __shared__ float As[GM][GK];        // 8 KB
    __shared__ float Bs[GK][GN + 4];    // 4.25 KB (pad avoids st/ld conflicts)

    int tid = threadIdx.x;
    int tx = tid & 15;          // N dir: 4 cols each
    int ty = tid >> 4;          // M dir: 8 rows each
    int bm = blockIdx.y * GM;
    int bn = blockIdx.x * GN;

    float acc[8][4] = {};

    for (int k0 = 0; k0 < K; k0 += GK) {
        // A tile: 128x16 = 512 float4, 2 per thread, coalesced along K
#pragma unroll
        for (int p = 0; p < 2; p++) {
            int idx = tid + p * 256;
            int r = idx >> 2, c = idx & 3;
            float4 v = *(const float4*)&A[(size_t)(bm + r) * K + k0 + c * 4];
            *(float4*)&As[r][c * 4] = v;
        }
        // B tile: 16x64 = 256 float4, 1 per thread, coalesced along N
        {
            int r = tid >> 4, c = tid & 15;
            float4 v = *(const float4*)&Bmat[(size_t)(k0 + r) * N + bn + c * 4];
            *(float4*)&Bs[r][c * 4] = v;
        }
        __syncthreads();
#pragma unroll
        for (int kk = 0; kk < GK; kk++) {
            float a[8], b[4];
#pragma unroll
            for (int i = 0; i < 8; i++) a[i] = As[ty * 8 + i][kk];   // 2-addr broadcast
            float4 b4 = *(const float4*)&Bs[kk][tx * 4];
            b[0] = b4.x; b[1] = b4.y; b[2] = b4.z; b[3] = b4.w;
#pragma unroll
            for (int i = 0; i < 8; i++)
#pragma unroll
                for (int j = 0; j < 4; j++)
                    acc[i][j] = fmaf(a[i], b[j], acc[i][j]);
        }
        __syncthreads();
    }

    float4 bia = *(const float4*)&bias[bn + tx * 4];
#pragma unroll
    for (int i = 0; i < 8; i++) {
        float4 o;
        o.x = acc[i][0] + bia.x;
        o.y = acc[i][1] + bia.y;
        o.z = acc[i][2] + bia.z;
        o.w = acc[i][3] + bia.w;
        *(float4*)&C[(size_t)(bm + ty * 8 + i) * N + bn + tx * 4] = o;
    }
}

// ============================================================
// 3. Flash attention, tile-phase online softmax.
//    One thread per query. 16-key tiles double-buffered in smem.
//    Per tile: (1) 16 scores into regs (4-way split chains),
//    (2) one max + one rescale, (3) AV accumulate, float4 LDS.
//    grid: (T/128, H, B), block 128, 4 blocks/SM -> 1 wave.
// ============================================================
#define TJ 16
__global__ __launch_bounds__(128, 4)
void attn_kernel() {
    const int t = blockIdx.x * 128 + threadIdx.x;
    const int h = blockIdx.y;
    const int b = blockIdx.z;
    const float scale = 0.17677669529663687f;   // 1/sqrt(32)

    __shared__ float4 Ks[2][TJ][8];   // 4 KB
    __shared__ float4 Vs[2][TJ][8];   // 4 KB

    const float* qp = g_qkv + (size_t)(b * TT + t) * (3 * DD) + h * DK;
    float q[DK];
#pragma unroll
    for (int d = 0; d < DK; d += 4) {
        float4 v = *(const float4*)&qp[d];
        q[d] = v.x * scale; q[d+1] = v.y * scale;
        q[d+2] = v.z * scale; q[d+3] = v.w * scale;
    }

    float acc[DK];
#pragma unroll
    for (int d = 0; d < DK; d++) acc[d] = 0.0f;
    float m = -1e30f, l = 0.0f;

    const float* kbase = g_qkv + (size_t)b * TT * (3 * DD) + DD + h * DK;
    const float* vbase = kbase + DD;

    // preload tile 0
    {
        int i = threadIdx.x;                  // 128 threads, 128 float4 per tensor
        int r = i >> 3, c = i & 7;
        Ks[0][r][c] = *(const float4*)(kbase + (size_t)r * (3 * DD) + c * 4);
        Vs[0][r][c] = *(const float4*)(vbase + (size_t)r * (3 * DD) + c * 4);
    }
    __syncthreads();

    for (int tile = 0; tile < TT / TJ; tile++) {
        int cur = tile & 1;

        // prefetch next tile into registers
        float4 kr, vr;
        int nk0 = (tile + 1) * TJ;
        int r = threadIdx.x >> 3, c = threadIdx.x & 7;
        if (nk0 < TT) {
            kr = *(const float4*)(kbase + (size_t)(nk0 + r) * (3 * DD) + c * 4);
            vr = *(const float4*)(vbase + (size_t)(nk0 + r) * (3 * DD) + c * 4);
        }

        // phase 1: 16 scores (4-way split accumulator chains)
        float s[TJ];
#pragma unroll
        for (int j = 0; j < TJ; j++) {
            float s0 = 0.f, s1 = 0.f, s2 = 0.f, s3 = 0.f;
#pragma unroll
            for (int dd = 0; dd < 8; dd++) {
                float4 k4 = Ks[cur][j][dd];      // broadcast
                s0 = fmaf(q[dd*4],   k4.x, s0);
                s1 = fmaf(q[dd*4+1], k4.y, s1);
                s2 = fmaf(q[dd*4+2], k4.z, s2);
                s3 = fmaf(q[dd*4+3], k4.w, s3);
            }
            s[j] = (s0 + s1) + (s2 + s3);
        }

        // phase 2: tile max, single rescale, exp
        float a0 = s[0], a1 = s[1], a2 = s[2], a3 = s[3];
#pragma unroll
        for (int j = 4; j < TJ; j += 4) {
            a0 = fmaxf(a0, s[j]);   a1 = fmaxf(a1, s[j+1]);
            a2 = fmaxf(a2, s[j+2]); a3 = fmaxf(a3, s[j+3]);
        }
        float nm = fmaxf(m, fmaxf(fmaxf(a0, a1), fmaxf(a2, a3)));
        float f = __expf(m - nm);
        m = nm;
        float p0 = 0.f, p1 = 0.f, p2 = 0.f, p3 = 0.f;
#pragma unroll
        for (int j = 0; j < TJ; j += 4) {
            s[j]   = __expf(s[j]   - nm); p0 += s[j];
            s[j+1] = __expf(s[j+1] - nm); p1 += s[j+1];
            s[j+2] = __expf(s[j+2] - nm); p2 += s[j+2];
            s[j+3] = __expf(s[j+3] - nm); p3 += s[j+3];
        }
        l = l * f + ((p0 + p1) + (p2 + p3));
#pragma unroll
        for (int d = 0; d < DK; d++) acc[d] *= f;

        // phase 3: AV accumulate
#pragma unroll
        for (int j = 0; j < TJ; j++) {
            float pj = s[j];
#pragma unroll
            for (int dd = 0; dd < 8; dd++) {
                float4 v4 = Vs[cur][j][dd];      // broadcast
                acc[dd*4]   = fmaf(pj, v4.x, acc[dd*4]);
                acc[dd*4+1] = fmaf(pj, v4.y, acc[dd*4+1]);
                acc[dd*4+2] = fmaf(pj, v4.z, acc[dd*4+2]);
                acc[dd*4+3] = fmaf(pj, v4.w, acc[dd*4+3]);
            }
        }

        // commit prefetched tile to the other buffer
        if (nk0 < TT) {
            int nb = cur ^ 1;
            Ks[nb][r][c] = kr;
            Vs[nb][r][c] = vr;
        }
        __syncthreads();
    }

    float inv = 1.0f / l;
    float* op = g_attn + (size_t)(b * TT + t) * DD + h * DK;
#pragma unroll
    for (int d = 0; d < DK; d += 4) {
        float4 o;
        o.x = acc[d] * inv;   o.y = acc[d+1] * inv;
        o.z = acc[d+2] * inv; o.w = acc[d+3] * inv;
        *(float4*)&op[d] = o;
    }
}

// ============================================================
// 4. Residual add + LayerNorm: h = LN(g_o + g_h) * gamma + beta
// ============================================================
__global__ __launch_bounds__(256)
void ln_kernel(const float* __restrict__ gamma,
               const float* __restrict__ beta) {
    int row = blockIdx.x;
    int tid = threadIdx.x;
    float v = g_o[row * DD + tid] + g_h[row * DD + tid];

    __shared__ float ssum[8], ssq[8];
    float s = v, sq = v * v;
#pragma unroll
    for (int o = 16; o > 0; o >>= 1) {
        s  += __shfl_xor_sync(0xffffffffu, s,  o);
        sq += __shfl_xor_sync(0xffffffffu, sq, o);
    }
    int w = tid >> 5, lane = tid & 31;
    if (lane == 0) { ssum[w] = s; ssq[w] = sq; }
    __syncthreads();
    float tot = 0.0f, totq = 0.0f;
#pragma unroll
    for (int i = 0; i < 8; i++) { tot += ssum[i]; totq += ssq[i]; }
    float mu  = tot * (1.0f / DD);
    float var = totq * (1.0f / DD) - mu * mu;
    float rs  = rsqrtf(var + LN_EPS);
    g_h[row * DD + tid] = (v - mu) * rs * gamma[tid] + beta[tid];
}

// ============================================================
// 5. Head: out[b, j] = h[b, T-1, :] . Wo[:, j] + bo[j]
// ============================================================
__global__ void head_kernel(const float* __restrict__ Wo,
                            const float* __restrict__ bo,
                            float* __restrict__ out) {
    int b = blockIdx.x / 3;
    int j = blockIdx.x - b * 3;
    int lane = threadIdx.x;
    const float* hr = g_h + (size_t)(b * TT + (TT - 1)) * DD;
    float s = 0.0f;
    for (int d = lane; d < DD; d += 32)
        s = fmaf(hr[d], Wo[d * 3 + j], s);
#pragma unroll
    for (int o = 16; o > 0; o >>= 1)
        s += __shfl_xor_sync(0xffffffffu, s, o);
    if (lane == 0) out[b * 3 + j] = s + bo[j];
}

// ============================================================
// launch
// ============================================================
extern "C" void kernel_launch(void* const* d_in, const int* in_sizes, int n_in,
                              void* d_out, int out_size) {
    const float* x    = (const float*)d_in[0];
    const float* Wp   = (const float*)d_in[1];
    const float* bp   = (const float*)d_in[2];
    const float* pos  = (const float*)d_in[3];
    const float* Wqkv = (const float*)d_in[4];
    const float* bqkv = (const float*)d_in[5];
    const float* Wout = (const float*)d_in[6];
    const float* bout = (const float*)d_in[7];
    const float* ln_g = (const float*)d_in[8];
    const float* ln_b = (const float*)d_in[9];
    const float* Wo   = (const float*)d_in[10];
    const float* bo   = (const float*)d_in[11];
    float* out = (float*)d_out;

    proj_kernel<<<(NROW * DD + 255) / 256, 256>>>(x, Wp, bp, pos);

    for (int l = 0; l < LL; l++) {
        // qkv = h @ Wqkv[l] + bqkv[l]
        gemm_bias_kernel<<<dim3((3 * DD) / GN, NROW / GM), 256>>>(
            0, Wqkv + (size_t)l * DD * 3 * DD, bqkv + (size_t)l * 3 * DD, 3 * DD);
        // attention
        attn_kernel<<<dim3(TT / 128, HH, BB), 128>>>();
        // o = attn @ Wout[l] + bout[l]
        gemm_bias_kernel<<<dim3(DD / GN, NROW / GM), 256>>>(
            1, Wout + (size_t)l * DD * DD, bout + (size_t)l * DD, DD);
        // h = LN(o + h)
        ln_kernel<<<NROW, 256>>>(ln_g + (size_t)l * DD, ln_b + (size_t)l * DD);
    }

    head_kernel<<<24, 32>>>(Wo, bo, out);
}

// round 3
// speedup vs baseline: 3.8956x; 2.8799x over previous
#include <cuda_runtime.h>
#include <math.h>

// Problem constants
#define BB 8
#define TT 1024
#define IN_DIM 16
#define DD 256
#define HH 8
#define DK 32
#define LL 4
#define NROW (BB*TT)
#define LN_EPS 1e-5f

// -------- scratch (device globals) --------
__device__ float g_h[NROW*DD];
__device__ float g_qkv[NROW*3*DD];
__device__ float g_attn[NROW*DD];
__device__ float g_o[NROW*DD];

// -------- tf32 helpers --------
__device__ __forceinline__ unsigned f2tf32(float x) {
    unsigned r;
    asm("cvt.rna.tf32.f32 %0, %1;" : "=r"(r) : "f"(x));
    return r;
}

__device__ __forceinline__ void mma8(float* d, const unsigned* a, unsigned b0, unsigned b1) {
    asm volatile(
        "mma.sync.aligned.m16n8k8.row.col.f32.tf32.tf32.f32 "
        "{%0,%1,%2,%3}, {%4,%5,%6,%7}, {%8,%9}, {%0,%1,%2,%3};\n"
        : "+f"(d[0]), "+f"(d[1]), "+f"(d[2]), "+f"(d[3])
        : "r"(a[0]), "r"(a[1]), "r"(a[2]), "r"(a[3]), "r"(b0), "r"(b1));
}

__device__ __forceinline__ void cp16(void* smem, const void* g) {
    unsigned a = (unsigned)__cvta_generic_to_shared(smem);
    asm volatile("cp.async.cg.shared.global [%0], [%1], 16;\n" :: "r"(a), "l"(g));
}
__device__ __forceinline__ void cp_commit() {
    asm volatile("cp.async.commit_group;\n");
}

// ============================================================
// 1. Projection: h = x @ Wp + bp + pos
// ============================================================
__global__ void proj_kernel(const float* __restrict__ x,
                            const float* __restrict__ Wp,
                            const float* __restrict__ bp,
                            const float* __restrict__ pos) {
    int idx = blockIdx.x * blockDim.x + threadIdx.x;
    if (idx >= NROW * DD) return;
    int row = idx / DD;
    int col = idx - row * DD;
    int t = row & (TT - 1);
    const float* xr = x + row * IN_DIM;
    float s = bp[col] + pos[t * DD + col];
#pragma unroll
    for (int i = 0; i < IN_DIM; i++)
        s = fmaf(xr[i], Wp[i * DD + col], s);
    g_h[idx] = s;
}

// ============================================================
// 2. tf32 tensor-core GEMM + bias.  Block tile 128x64, 8 warps
//    (4x2), warp tile 32x32, K staged 16 at a time, double-buffered
//    with register prefetch. Smem strides 20/72 words: conflict-free.
//    mode 0: g_qkv = g_h @ Bmat + bias    (N=768)
//    mode 1: g_o   = g_attn @ Bmat + bias (N=256)
// ============================================================
#define GMM 128
#define GNN 64
__global__ __launch_bounds__(256)
void gemm_tc_kernel(int mode, const float* __restrict__ Bmat,
                    const float* __restrict__ bias, int N) {
    const int K = DD;
    const float* __restrict__ A = (mode == 0) ? g_h : g_attn;
    float* __restrict__ C       = (mode == 0) ? g_qkv : g_o;

    __shared__ unsigned As[2][GMM][20];   // 128 x 16 tf32, stride 20
    __shared__ unsigned Bs[2][16][72];    // 16 x 64 tf32, stride 72

    const int tid  = threadIdx.x;
    const int lane = tid & 31;
    const int g    = lane >> 2;
    const int q    = lane & 3;
    const int warp = tid >> 5;
    const int wm   = (warp & 3) * 32;
    const int wn   = (warp >> 2) * 32;
    const int bm   = blockIdx.y * GMM;
    const int bn   = blockIdx.x * GNN;

    float acc[2][4][4];
#pragma unroll
    for (int mc = 0; mc < 2; mc++)
#pragma unroll
        for (int nc = 0; nc < 4; nc++)
#pragma unroll
            for (int i = 0; i < 4; i++) acc[mc][nc][i] = 0.0f;

    // staging indices
    const int ar0 = tid >> 2;            // 0..63
    const int ac  = (tid & 3) * 4;       // 0,4,8,12
    const int br  = tid >> 4;            // 0..15
    const int bc  = (tid & 15) * 4;      // 0..60

    float4 pa0, pa1, pb0;
    // prefetch stage 0
    pa0 = *(const float4*)&A[(size_t)(bm + ar0) * K + ac];
    pa1 = *(const float4*)&A[(size_t)(bm + ar0 + 64) * K + ac];
    pb0 = *(const float4*)&Bmat[(size_t)br * N + bn + bc];
    *(uint4*)&As[0][ar0][ac]      = make_uint4(f2tf32(pa0.x), f2tf32(pa0.y), f2tf32(pa0.z), f2tf32(pa0.w));
    *(uint4*)&As[0][ar0 + 64][ac] = make_uint4(f2tf32(pa1.x), f2tf32(pa1.y), f2tf32(pa1.z), f2tf32(pa1.w));
    *(uint4*)&Bs[0][br][bc]       = make_uint4(f2tf32(pb0.x), f2tf32(pb0.y), f2tf32(pb0.z), f2tf32(pb0.w));
    __syncthreads();

    const int NSTAGE = K / 16;   // 16
    for (int s = 0; s < NSTAGE; s++) {
        int buf = s & 1;
        if (s + 1 < NSTAGE) {
            int k0 = (s + 1) * 16;
            pa0 = *(const float4*)&A[(size_t)(bm + ar0) * K + k0 + ac];
            pa1 = *(const float4*)&A[(size_t)(bm + ar0 + 64) * K + k0 + ac];
            pb0 = *(const float4*)&Bmat[(size_t)(k0 + br) * N + bn + bc];
        }

#pragma unroll
        for (int kk = 0; kk < 2; kk++) {
            int kb = kk * 8;
            unsigned af[2][4], bf[4][2];
#pragma unroll
            for (int mc = 0; mc < 2; mc++) {
                int r = wm + mc * 16 + g;
                af[mc][0] = As[buf][r][kb + q];
                af[mc][1] = As[buf][r + 8][kb + q];
                af[mc][2] = As[buf][r][kb + q + 4];
                af[mc][3] = As[buf][r + 8][kb + q + 4];
            }
#pragma unroll
            for (int nc = 0; nc < 4; nc++) {
                int cc = wn + nc * 8 + g;
                bf[nc][0] = Bs[buf][kb + q][cc];
                bf[nc][1] = Bs[buf][kb + q + 4][cc];
            }
#pragma unroll
            for (int mc = 0; mc < 2; mc++)
#pragma unroll
                for (int nc = 0; nc < 4; nc++)
                    mma8(acc[mc][nc], af[mc], bf[nc][0], bf[nc][1]);
        }

        if (s + 1 < NSTAGE) {
            int nb = buf ^ 1;
            *(uint4*)&As[nb][ar0][ac]      = make_uint4(f2tf32(pa0.x), f2tf32(pa0.y), f2tf32(pa0.z), f2tf32(pa0.w));
            *(uint4*)&As[nb][ar0 + 64][ac] = make_uint4(f2tf32(pa1.x), f2tf32(pa1.y), f2tf32(pa1.z), f2tf32(pa1.w));
            *(uint4*)&Bs[nb][br][bc]       = make_uint4(f2tf32(pb0.x), f2tf32(pb0.y), f2tf32(pb0.z), f2tf32(pb0.w));
        }
        __syncthreads();
    }

    // epilogue: C layout c0/c1 = (row, 2q/2q+1), c2/c3 = row+8
#pragma unroll
    for (int mc = 0; mc < 2; mc++) {
#pragma unroll
        for (int nc = 0; nc < 4; nc++) {
            int row = bm + wm + mc * 16 + g;
            int col = bn + wn + nc * 8 + 2 * q;
            float2 bi = *(const float2*)&bias[col];
            float2 o0 = make_float2(acc[mc][nc][0] + bi.x, acc[mc][nc][1] + bi.y);
            float2 o1 = make_float2(acc[mc][nc][2] + bi.x, acc[mc][nc][3] + bi.y);
            *(float2*)&C[(size_t)row * N + col]       = o0;
            *(float2*)&C[(size_t)(row + 8) * N + col] = o1;
        }
    }
}

// ============================================================
// 3. Tensor-core flash attention (tf32).
//    Block: 128 thr / 4 warps, 128 queries (32/warp) of one (b,h).
//    Key tiles of 32, cp.async double-buffered in smem (fp32,
//    converted to tf32 at fragment load). Online softmax on C frags.
//    grid (T/128, H, B) = 512 blocks, 4/SM -> 1 wave.
// ============================================================
__global__ __launch_bounds__(128, 4)
void attn_tc_kernel() {
    __shared__ float Ks[2][32][36];
    __shared__ float Vs[2][32][40];

    const int tid  = threadIdx.x;
    const int lane = tid & 31;
    const int g    = lane >> 2;
    const int q    = lane & 3;
    const int warp = tid >> 5;
    const int h    = blockIdx.y;
    const int b    = blockIdx.z;
    const int qrow0 = blockIdx.x * 128 + warp * 32;   // warp's first query

    const float qscale = 0.17677669529663687f * 1.4426950408889634f; // 1/sqrt(32)*log2e

    const float* kg = g_qkv + (size_t)b * TT * (3 * DD) + DD + h * DK;
    const float* vg = g_qkv + (size_t)b * TT * (3 * DD) + 2 * DD + h * DK;
    const float* qg = g_qkv + (size_t)(b * TT + qrow0) * (3 * DD) + h * DK;

    // staging indices: 128 thr cover 32 rows x 32 cols (2 chunks of 16 rows)
    const int sr = tid >> 3;            // 0..15
    const int sc = (tid & 7) * 4;       // 0..28

    // prefetch tile 0
    cp16(&Ks[0][sr][sc],      kg + (size_t)sr * (3 * DD) + sc);
    cp16(&Ks[0][sr + 16][sc], kg + (size_t)(sr + 16) * (3 * DD) + sc);
    cp16(&Vs[0][sr][sc],      vg + (size_t)sr * (3 * DD) + sc);
    cp16(&Vs[0][sr + 16][sc], vg + (size_t)(sr + 16) * (3 * DD) + sc);
    cp_commit();

    // Q A-fragments (scaled, tf32), resident in registers
    unsigned qa[2][4][4];
#pragma unroll
    for (int mc = 0; mc < 2; mc++)
#pragma unroll
        for (int kc = 0; kc < 4; kc++) {
            int r = mc * 16 + g;
            qa[mc][kc][0] = f2tf32(qg[(size_t)r * (3 * DD) + kc * 8 + q] * qscale);
            qa[mc][kc][1] = f2tf32(qg[(size_t)(r + 8) * (3 * DD) + kc * 8 + q] * qscale);
            qa[mc][kc][2] = f2tf32(qg[(size_t)r * (3 * DD) + kc * 8 + q + 4] * qscale);
            qa[mc][kc][3] = f2tf32(qg[(size_t)(r + 8) * (3 * DD) + kc * 8 + q + 4] * qscale);
        }

    float oacc[2][4][4];
    float mrow[2][2], lrow[2][2];
#pragma unroll
    for (int mc = 0; mc < 2; mc++) {
        mrow[mc][0] = -1e30f; mrow[mc][1] = -1e30f;
        lrow[mc][0] = 0.0f;   lrow[mc][1] = 0.0f;
#pragma unroll
        for (int nc = 0; nc < 4; nc++)
#pragma unroll
            for (int i = 0; i < 4; i++) oacc[mc][nc][i] = 0.0f;
    }

    const int src1 = (lane & ~3) | (q >> 1);
    const int src2 = src1 + 2;

    const int NT = TT / 32;   // 32 tiles
    for (int t = 0; t < NT; t++) {
        int buf = t & 1;
        if (t + 1 < NT) {
            int k0 = (t + 1) * 32;
            int nb = buf ^ 1;
            cp16(&Ks[nb][sr][sc],      kg + (size_t)(k0 + sr) * (3 * DD) + sc);
            cp16(&Ks[nb][sr + 16][sc], kg + (size_t)(k0 + sr + 16) * (3 * DD) + sc);
            cp16(&Vs[nb][sr][sc],      vg + (size_t)(k0 + sr) * (3 * DD) + sc);
            cp16(&Vs[nb][sr + 16][sc], vg + (size_t)(k0 + sr + 16) * (3 * DD) + sc);
            cp_commit();
            asm volatile("cp.async.wait_group 1;\n");
        } else {
            asm volatile("cp.async.wait_group 0;\n");
        }
        __syncthreads();

        // ---- S = Q K^T (32q x 32k per warp) ----
        float sf[2][4][4];
#pragma unroll
        for (int mc = 0; mc < 2; mc++)
#pragma unroll
            for (int nc = 0; nc < 4; nc++)
#pragma unroll
                for (int i = 0; i < 4; i++) sf[mc][nc][i] = 0.0f;

#pragma unroll
        for (int nc = 0; nc < 4; nc++) {
#pragma unroll
            for (int kc = 0; kc < 4; kc++) {
                unsigned b0 = f2tf32(Ks[buf][nc * 8 + g][kc * 8 + q]);
                unsigned b1 = f2tf32(Ks[buf][nc * 8 + g][kc * 8 + q + 4]);
                mma8(sf[0][nc], qa[0][kc], b0, b1);
                mma8(sf[1][nc], qa[1][kc], b0, b1);
            }
        }

        // ---- online softmax (rows g / g+8 per mc) ----
#pragma unroll
        for (int mc = 0; mc < 2; mc++) {
            float mx0 = sf[mc][0][0], mx1 = sf[mc][0][2];
#pragma unroll
            for (int nc = 0; nc < 4; nc++) {
                mx0 = fmaxf(mx0, fmaxf(sf[mc][nc][0], sf[mc][nc][1]));
                mx1 = fmaxf(mx1, fmaxf(sf[mc][nc][2], sf[mc][nc][3]));
            }
            mx0 = fmaxf(mx0, __shfl_xor_sync(0xffffffffu, mx0, 1));
            mx0 = fmaxf(mx0, __shfl_xor_sync(0xffffffffu, mx0, 2));
            mx1 = fmaxf(mx1, __shfl_xor_sync(0xffffffffu, mx1, 1));
            mx1 = fmaxf(mx1, __shfl_xor_sync(0xffffffffu, mx1, 2));
            float nm0 = fmaxf(mrow[mc][0], mx0);
            float nm1 = fmaxf(mrow[mc][1], mx1);
            float f0 = exp2f(mrow[mc][0] - nm0);
            float f1 = exp2f(mrow[mc][1] - nm1);
            mrow[mc][0] = nm0; mrow[mc][1] = nm1;
            float s0 = 0.0f, s1 = 0.0f;
#pragma unroll
            for (int nc = 0; nc < 4; nc++) {
                sf[mc][nc][0] = exp2f(sf[mc][nc][0] - nm0);
                sf[mc][nc][1] = exp2f(sf[mc][nc][1] - nm0);
                sf[mc][nc][2] = exp2f(sf[mc][nc][2] - nm1);
                sf[mc][nc][3] = exp2f(sf[mc][nc][3] - nm1);
                s0 += sf[mc][nc][0] + sf[mc][nc][1];
                s1 += sf[mc][nc][2] + sf[mc][nc][3];
            }
            s0 += __shfl_xor_sync(0xffffffffu, s0, 1);
            s0 += __shfl_xor_sync(0xffffffffu, s0, 2);
            s1 += __shfl_xor_sync(0xffffffffu, s1, 1);
            s1 += __shfl_xor_sync(0xffffffffu, s1, 2);
            lrow[mc][0] = lrow[mc][0] * f0 + s0;
            lrow[mc][1] = lrow[mc][1] * f1 + s1;
#pragma unroll
            for (int nc = 0; nc < 4; nc++) {
                oacc[mc][nc][0] *= f0; oacc[mc][nc][1] *= f0;
                oacc[mc][nc][2] *= f1; oacc[mc][nc][3] *= f1;
            }
        }

        // ---- P: C-layout -> A-layout via quad shuffles, tf32 ----
        unsigned pa[2][4][4];
#pragma unroll
        for (int mc = 0; mc < 2; mc++)
#pragma unroll
            for (int kc = 0; kc < 4; kc++) {
                float u0 = __shfl_sync(0xffffffffu, sf[mc][kc][0], src1);
                float u1 = __shfl_sync(0xffffffffu, sf[mc][kc][1], src1);
                float w0 = __shfl_sync(0xffffffffu, sf[mc][kc][0], src2);
                float w1 = __shfl_sync(0xffffffffu, sf[mc][kc][1], src2);
                pa[mc][kc][0] = f2tf32((q & 1) ? u1 : u0);
                pa[mc][kc][2] = f2tf32((q & 1) ? w1 : w0);
                float x0 = __shfl_sync(0xffffffffu, sf[mc][kc][2], src1);
                float x1 = __shfl_sync(0xffffffffu, sf[mc][kc][3], src1);
                float y0 = __shfl_sync(0xffffffffu, sf[mc][kc][2], src2);
                float y1 = __shfl_sync(0xffffffffu, sf[mc][kc][3], src2);
                pa[mc][kc][1] = f2tf32((q & 1) ? x1 : x0);
                pa[mc][kc][3] = f2tf32((q & 1) ? y1 : y0);
            }

        // ---- O += P V ----
#pragma unroll
        for (int dn = 0; dn < 4; dn++) {
#pragma unroll
            for (int kc = 0; kc < 4; kc++) {
                unsigned b0 = f2tf32(Vs[buf][kc * 8 + q][dn * 8 + g]);
                unsigned b1 = f2tf32(Vs[buf][kc * 8 + q + 4][dn * 8 + g]);
                mma8(oacc[0][dn], pa[0][kc], b0, b1);
                mma8(oacc[1][dn], pa[1][kc], b0, b1);
            }
        }
        __syncthreads();
    }

    // ---- epilogue: normalize and store ----
#pragma unroll
    for (int mc = 0; mc < 2; mc++) {
        float inv0 = 1.0f / lrow[mc][0];
        float inv1 = 1.0f / lrow[mc][1];
        int r0 = b * TT + qrow0 + mc * 16 + g;
#pragma unroll
        for (int dn = 0; dn < 4; dn++) {
            int col = h * DK + dn * 8 + 2 * q;
            float2 o0 = make_float2(oacc[mc][dn][0] * inv0, oacc[mc][dn][1] * inv0);
            float2 o1 = make_float2(oacc[mc][dn][2] * inv1, oacc[mc][dn][3] * inv1);
            *(float2*)&g_attn[(size_t)r0 * DD + col]       = o0;
            *(float2*)&g_attn[(size_t)(r0 + 8) * DD + col] = o1;
        }
    }
}

// ============================================================
// 4. Residual add + LayerNorm
// ============================================================
__global__ __launch_bounds__(256)
void ln_kernel(const float* __restrict__ gamma,
               const float* __restrict__ beta) {
    int row = blockIdx.x;
    int tid = threadIdx.x;
    float v = g_o[row * DD + tid] + g_h[row * DD + tid];

    __shared__ float ssum[8], ssq[8];
    float s = v, sq = v * v;
#pragma unroll
    for (int o = 16; o > 0; o >>= 1) {
        s  += __shfl_xor_sync(0xffffffffu, s,  o);
        sq += __shfl_xor_sync(0xffffffffu, sq, o);
    }
    int w = tid >> 5, lane = tid & 31;
    if (lane == 0) { ssum[w] = s; ssq[w] = sq; }
    __syncthreads();
    float tot = 0.0f, totq = 0.0f;
#pragma unroll
    for (int i = 0; i < 8; i++) { tot += ssum[i]; totq += ssq[i]; }
    float mu  = tot * (1.0f / DD);
    float var = totq * (1.0f / DD) - mu * mu;
    float rs  = rsqrtf(var + LN_EPS);
    g_h[row * DD + tid] = (v - mu) * rs * gamma[tid] + beta[tid];
}

// ============================================================
// 5. Head
// ============================================================
__global__ void head_kernel(const float* __restrict__ Wo,
                            const float* __restrict__ bo,
                            float* __restrict__ out) {
    int b = blockIdx.x / 3;
    int j = blockIdx.x - b * 3;
    int lane = threadIdx.x;
    const float* hr = g_h + (size_t)(b * TT + (TT - 1)) * DD;
    float s = 0.0f;
    for (int d = lane; d < DD; d += 32)
        s = fmaf(hr[d], Wo[d * 3 + j], s);
#pragma unroll
    for (int o = 16; o > 0; o >>= 1)
        s += __shfl_xor_sync(0xffffffffu, s, o);
    if (lane == 0) out[b * 3 + j] = s + bo[j];
}

// ============================================================
// launch
// ============================================================
extern "C" void kernel_launch(void* const* d_in, const int* in_sizes, int n_in,
                              void* d_out, int out_size) {
    const float* x    = (const float*)d_in[0];
    const float* Wp   = (const float*)d_in[1];
    const float* bp   = (const float*)d_in[2];
    const float* pos  = (const float*)d_in[3];
    const float* Wqkv = (const float*)d_in[4];
    const float* bqkv = (const float*)d_in[5];
    const float* Wout = (const float*)d_in[6];
    const float* bout = (const float*)d_in[7];
    const float* ln_g = (const float*)d_in[8];
    const float* ln_b = (const float*)d_in[9];
    const float* Wo   = (const float*)d_in[10];
    const float* bo   = (const float*)d_in[11];
    float* out = (float*)d_out;

    proj_kernel<<<(NROW * DD + 255) / 256, 256>>>(x, Wp, bp, pos);

    for (int l = 0; l < LL; l++) {
        gemm_tc_kernel<<<dim3((3 * DD) / GNN, NROW / GMM), 256>>>(
            0, Wqkv + (size_t)l * DD * 3 * DD, bqkv + (size_t)l * 3 * DD, 3 * DD);
        attn_tc_kernel<<<dim3(TT / 128, HH, BB), 128>>>();
        gemm_tc_kernel<<<dim3(DD / GNN, NROW / GMM), 256>>>(
            1, Wout + (size_t)l * DD * DD, bout + (size_t)l * DD, DD);
        ln_kernel<<<NROW, 256>>>(ln_g + (size_t)l * DD, ln_b + (size_t)l * DD);
    }

    head_kernel<<<24, 32>>>(Wo, bo, out);
}

// round 5
// speedup vs baseline: 4.4714x; 1.1478x over previous
#include <cuda_runtime.h>
#include <math.h>

// Problem constants
#define BB 8
#define TT 1024
#define IN_DIM 16
#define DD 256
#define HH 8
#define DK 32
#define LL 4
#define NROW (BB*TT)
#define LN_EPS 1e-5f

// -------- scratch (device globals) --------
__device__ float g_h[NROW*DD];          // fp32 residual stream
__device__ float g_h32[NROW*DD];        // tf32-rounded copy (GEMM A input)
__device__ float g_qkv[NROW*3*DD];      // tf32-rounded qkv
__device__ float g_attn[NROW*DD];       // tf32-rounded attention out
__device__ float g_wqkv32[LL*DD*3*DD];  // tf32-rounded weights
__device__ float g_wout32[LL*DD*DD];

// -------- helpers --------
__device__ __forceinline__ unsigned f2tf32(float x) {
    unsigned r;
    asm("cvt.rna.tf32.f32 %0, %1;" : "=r"(r) : "f"(x));
    return r;
}
__device__ __forceinline__ void mma8(float* d, const unsigned* a, unsigned b0, unsigned b1) {
    asm volatile(
        "mma.sync.aligned.m16n8k8.row.col.f32.tf32.tf32.f32 "
        "{%0,%1,%2,%3}, {%4,%5,%6,%7}, {%8,%9}, {%0,%1,%2,%3};\n"
        : "+f"(d[0]), "+f"(d[1]), "+f"(d[2]), "+f"(d[3])
        : "r"(a[0]), "r"(a[1]), "r"(a[2]), "r"(a[3]), "r"(b0), "r"(b1));
}
__device__ __forceinline__ void cp16(void* smem, const void* g) {
    unsigned a = (unsigned)__cvta_generic_to_shared(smem);
    asm volatile("cp.async.cg.shared.global [%0], [%1], 16;\n" :: "r"(a), "l"(g));
}
__device__ __forceinline__ void cp_commit() { asm volatile("cp.async.commit_group;\n"); }
template<int N> __device__ __forceinline__ void cp_wait() {
    asm volatile("cp.async.wait_group %0;\n" :: "n"(N));
}
__device__ __forceinline__ unsigned fbits(float x) { return __float_as_uint(x); }

// ============================================================
// 0. Weight conversion to tf32 (once per launch)
// ============================================================
__global__ void convw_kernel(const float* __restrict__ Wqkv,
                             const float* __restrict__ Wout) {
    int i = blockIdx.x * 256 + threadIdx.x;
    if (i < LL * DD * 3 * DD) g_wqkv32[i] = __uint_as_float(f2tf32(Wqkv[i]));
    if (i < LL * DD * DD)     g_wout32[i] = __uint_as_float(f2tf32(Wout[i]));
}

// ============================================================
// 1. Projection: h = x @ Wp + bp + pos  (fp32 + tf32 copy)
// ============================================================
__global__ void proj_kernel(const float* __restrict__ x,
                            const float* __restrict__ Wp,
                            const float* __restrict__ bp,
                            const float* __restrict__ pos) {
    int idx = blockIdx.x * blockDim.x + threadIdx.x;
    if (idx >= NROW * DD) return;
    int row = idx / DD;
    int col = idx - row * DD;
    int t = row & (TT - 1);
    const float* xr = x + row * IN_DIM;
    float s = bp[col] + pos[t * DD + col];
#pragma unroll
    for (int i = 0; i < IN_DIM; i++)
        s = fmaf(xr[i], Wp[i * DD + col], s);
    g_h[idx] = s;
    g_h32[idx] = __uint_as_float(f2tf32(s));
}

// ============================================================
// 2. QKV GEMM: g_qkv = g_h32 @ Wqkv32[l] + bqkv[l]  (tf32 out)
//    Block 128x128, 8 warps (2m x 4n), warp 64x32.
//    4-stage cp.async, K staged 16. Conflict-free strides 20/136.
// ============================================================
#define QBM 128
#define QBN 128
#define QGK 16
#define QAS_STRIDE 20
#define QBS_STRIDE 136
#define QAS_WORDS (4*QBM*QAS_STRIDE)
#define QBS_WORDS (4*QGK*QBS_STRIDE)
#define QSMEM_BYTES ((QAS_WORDS+QBS_WORDS)*4)

extern __shared__ float dynsmem[];

__global__ __launch_bounds__(256, 2)
void qkv_gemm_kernel(int layer, const float* __restrict__ bias) {
    float* As = dynsmem;                 // [4][128][20]
    float* Bs = dynsmem + QAS_WORDS;     // [4][16][136]
    const float* __restrict__ A = g_h32;
    const float* __restrict__ Bmat = g_wqkv32 + (size_t)layer * DD * 3 * DD;
    const int N = 3 * DD;

    const int tid  = threadIdx.x;
    const int lane = tid & 31;
    const int g    = lane >> 2;
    const int q    = lane & 3;
    const int warp = tid >> 5;
    const int wm   = (warp & 1) * 64;
    const int wn   = (warp >> 1) * 32;
    const int bm   = blockIdx.y * QBM;
    const int bn   = blockIdx.x * QBN;

    auto issue = [&](int s) {
        int k0 = s * QGK;
        float* Asb = As + (s & 3) * QBM * QAS_STRIDE;
        float* Bsb = Bs + (s & 3) * QGK * QBS_STRIDE;
#pragma unroll
        for (int p = 0; p < 2; p++) {
            int c = tid + p * 256;
            int r = c >> 2, cc = (c & 3) * 4;
            cp16(&Asb[r * QAS_STRIDE + cc], &A[(size_t)(bm + r) * DD + k0 + cc]);
        }
#pragma unroll
        for (int p = 0; p < 2; p++) {
            int c = tid + p * 256;
            int r = c >> 5, cc = (c & 31) * 4;
            cp16(&Bsb[r * QBS_STRIDE + cc], &Bmat[(size_t)(k0 + r) * N + bn + cc]);
        }
    };

    float acc[4][4][4];
#pragma unroll
    for (int mc = 0; mc < 4; mc++)
#pragma unroll
        for (int nc = 0; nc < 4; nc++)
#pragma unroll
            for (int i = 0; i < 4; i++) acc[mc][nc][i] = 0.0f;

    issue(0); cp_commit();
    issue(1); cp_commit();
    issue(2); cp_commit();

    const int NS = DD / QGK;   // 16
    for (int s = 0; s < NS; s++) {
        cp_wait<2>();
        __syncthreads();
        if (s + 3 < NS) issue(s + 3);
        cp_commit();

        const float* Asb = As + (s & 3) * QBM * QAS_STRIDE;
        const float* Bsb = Bs + (s & 3) * QGK * QBS_STRIDE;
#pragma unroll
        for (int kk = 0; kk < 2; kk++) {
            int kb = kk * 8;
            unsigned af[4][4], bf[4][2];
#pragma unroll
            for (int mc = 0; mc < 4; mc++) {
                int r = wm + mc * 16 + g;
                af[mc][0] = fbits(Asb[r * QAS_STRIDE + kb + q]);
                af[mc][1] = fbits(Asb[(r + 8) * QAS_STRIDE + kb + q]);
                af[mc][2] = fbits(Asb[r * QAS_STRIDE + kb + q + 4]);
                af[mc][3] = fbits(Asb[(r + 8) * QAS_STRIDE + kb + q + 4]);
            }
#pragma unroll
            for (int nc = 0; nc < 4; nc++) {
                int cc = wn + nc * 8 + g;
                bf[nc][0] = fbits(Bsb[(kb + q) * QBS_STRIDE + cc]);
                bf[nc][1] = fbits(Bsb[(kb + q + 4) * QBS_STRIDE + cc]);
            }
#pragma unroll
            for (int mc = 0; mc < 4; mc++)
#pragma unroll
                for (int nc = 0; nc < 4; nc++)
                    mma8(acc[mc][nc], af[mc], bf[nc][0], bf[nc][1]);
        }
    }

    // epilogue: + bias, round to tf32, store
#pragma unroll
    for (int mc = 0; mc < 4; mc++) {
#pragma unroll
        for (int nc = 0; nc < 4; nc++) {
            int row = bm + wm + mc * 16 + g;
            int col = bn + wn + nc * 8 + 2 * q;
            float2 bi = *(const float2*)&bias[col];
            float2 o0, o1;
            o0.x = __uint_as_float(f2tf32(acc[mc][nc][0] + bi.x));
            o0.y = __uint_as_float(f2tf32(acc[mc][nc][1] + bi.y));
            o1.x = __uint_as_float(f2tf32(acc[mc][nc][2] + bi.x));
            o1.y = __uint_as_float(f2tf32(acc[mc][nc][3] + bi.y));
            *(float2*)&g_qkv[(size_t)row * N + col]       = o0;
            *(float2*)&g_qkv[(size_t)(row + 8) * N + col] = o1;
        }
    }
}

// ============================================================
// 3. Tensor-core flash attention (tf32 inputs already rounded).
//    No cvt in hot loop; softmax scale folded into exp argument.
// ============================================================
__global__ __launch_bounds__(128, 4)
void attn_tc_kernel() {
    __shared__ float Ks[2][32][36];
    __shared__ float Vs[2][32][40];

    const int tid  = threadIdx.x;
    const int lane = tid & 31;
    const int g    = lane >> 2;
    const int q    = lane & 3;
    const int warp = tid >> 5;
    const int h    = blockIdx.y;
    const int b    = blockIdx.z;
    const int qrow0 = blockIdx.x * 128 + warp * 32;

    const float qs = 0.17677669529663687f * 1.4426950408889634f; // scale*log2e

    const float* kg = g_qkv + (size_t)b * TT * (3 * DD) + DD + h * DK;
    const float* vg = g_qkv + (size_t)b * TT * (3 * DD) + 2 * DD + h * DK;
    const float* qg = g_qkv + (size_t)(b * TT + qrow0) * (3 * DD) + h * DK;

    const int sr = tid >> 3;
    const int sc = (tid & 7) * 4;

    cp16(&Ks[0][sr][sc],      kg + (size_t)sr * (3 * DD) + sc);
    cp16(&Ks[0][sr + 16][sc], kg + (size_t)(sr + 16) * (3 * DD) + sc);
    cp16(&Vs[0][sr][sc],      vg + (size_t)sr * (3 * DD) + sc);
    cp16(&Vs[0][sr + 16][sc], vg + (size_t)(sr + 16) * (3 * DD) + sc);
    cp_commit();

    // Q fragments (already tf32 bits)
    unsigned qa[2][4][4];
#pragma unroll
    for (int mc = 0; mc < 2; mc++)
#pragma unroll
        for (int kc = 0; kc < 4; kc++) {
            int r = mc * 16 + g;
            qa[mc][kc][0] = fbits(qg[(size_t)r * (3 * DD) + kc * 8 + q]);
            qa[mc][kc][1] = fbits(qg[(size_t)(r + 8) * (3 * DD) + kc * 8 + q]);
            qa[mc][kc][2] = fbits(qg[(size_t)r * (3 * DD) + kc * 8 + q + 4]);
            qa[mc][kc][3] = fbits(qg[(size_t)(r + 8) * (3 * DD) + kc * 8 + q + 4]);
        }

    float oacc[2][4][4];
    float mrow[2][2], lrow[2][2];
#pragma unroll
    for (int mc = 0; mc < 2; mc++) {
        mrow[mc][0] = -1e30f; mrow[mc][1] = -1e30f;
        lrow[mc][0] = 0.0f;   lrow[mc][1] = 0.0f;
#pragma unroll
        for (int nc = 0; nc < 4; nc++)
#pragma unroll
            for (int i = 0; i < 4; i++) oacc[mc][nc][i] = 0.0f;
    }

    const int src1 = (lane & ~3) | (q >> 1);
    const int src2 = src1 + 2;

    const int NT = TT / 32;
    for (int t = 0; t < NT; t++) {
        int buf = t & 1;
        if (t + 1 < NT) {
            int k0 = (t + 1) * 32;
            int nb = buf ^ 1;
            cp16(&Ks[nb][sr][sc],      kg + (size_t)(k0 + sr) * (3 * DD) + sc);
            cp16(&Ks[nb][sr + 16][sc], kg + (size_t)(k0 + sr + 16) * (3 * DD) + sc);
            cp16(&Vs[nb][sr][sc],      vg + (size_t)(k0 + sr) * (3 * DD) + sc);
            cp16(&Vs[nb][sr + 16][sc], vg + (size_t)(k0 + sr + 16) * (3 * DD) + sc);
            cp_commit();
            cp_wait<1>();
        } else {
            cp_wait<0>();
        }
        __syncthreads();

        // S = Q K^T (raw, unscaled)
        float sf[2][4][4];
#pragma unroll
        for (int mc = 0; mc < 2; mc++)
#pragma unroll
            for (int nc = 0; nc < 4; nc++)
#pragma unroll
                for (int i = 0; i < 4; i++) sf[mc][nc][i] = 0.0f;

#pragma unroll
        for (int nc = 0; nc < 4; nc++) {
#pragma unroll
            for (int kc = 0; kc < 4; kc++) {
                unsigned b0 = fbits(Ks[buf][nc * 8 + g][kc * 8 + q]);
                unsigned b1 = fbits(Ks[buf][nc * 8 + g][kc * 8 + q + 4]);
                mma8(sf[0][nc], qa[0][kc], b0, b1);
                mma8(sf[1][nc], qa[1][kc], b0, b1);
            }
        }

        // online softmax (raw-unit max; scale applied in exp arg)
#pragma unroll
        for (int mc = 0; mc < 2; mc++) {
            float mx0 = sf[mc][0][0], mx1 = sf[mc][0][2];
#pragma unroll
            for (int nc = 0; nc < 4; nc++) {
                mx0 = fmaxf(mx0, fmaxf(sf[mc][nc][0], sf[mc][nc][1]));
                mx1 = fmaxf(mx1, fmaxf(sf[mc][nc][2], sf[mc][nc][3]));
            }
            mx0 = fmaxf(mx0, __shfl_xor_sync(0xffffffffu, mx0, 1));
            mx0 = fmaxf(mx0, __shfl_xor_sync(0xffffffffu, mx0, 2));
            mx1 = fmaxf(mx1, __shfl_xor_sync(0xffffffffu, mx1, 1));
            mx1 = fmaxf(mx1, __shfl_xor_sync(0xffffffffu, mx1, 2));
            float nm0 = fmaxf(mrow[mc][0], mx0);
            float nm1 = fmaxf(mrow[mc][1], mx1);
            float f0 = exp2f((mrow[mc][0] - nm0) * qs);
            float f1 = exp2f((mrow[mc][1] - nm1) * qs);
            mrow[mc][0] = nm0; mrow[mc][1] = nm1;
            float c0 = nm0 * qs, c1 = nm1 * qs;
            float s0 = 0.0f, s1 = 0.0f;
#pragma unroll
            for (int nc = 0; nc < 4; nc++) {
                sf[mc][nc][0] = exp2f(fmaf(sf[mc][nc][0], qs, -c0));
                sf[mc][nc][1] = exp2f(fmaf(sf[mc][nc][1], qs, -c0));
                sf[mc][nc][2] = exp2f(fmaf(sf[mc][nc][2], qs, -c1));
                sf[mc][nc][3] = exp2f(fmaf(sf[mc][nc][3], qs, -c1));
                s0 += sf[mc][nc][0] + sf[mc][nc][1];
                s1 += sf[mc][nc][2] + sf[mc][nc][3];
            }
            s0 += __shfl_xor_sync(0xffffffffu, s0, 1);
            s0 += __shfl_xor_sync(0xffffffffu, s0, 2);
            s1 += __shfl_xor_sync(0xffffffffu, s1, 1);
            s1 += __shfl_xor_sync(0xffffffffu, s1, 2);
            lrow[mc][0] = lrow[mc][0] * f0 + s0;
            lrow[mc][1] = lrow[mc][1] * f1 + s1;
#pragma unroll
            for (int nc = 0; nc < 4; nc++) {
                oacc[mc][nc][0] *= f0; oacc[mc][nc][1] *= f0;
                oacc[mc][nc][2] *= f1; oacc[mc][nc][3] *= f1;
            }
        }

        // P: C-layout -> A-layout (quad shuffles), cvt to tf32
        unsigned pa[2][4][4];
#pragma unroll
        for (int mc = 0; mc < 2; mc++)
#pragma unroll
            for (int kc = 0; kc < 4; kc++) {
                float u0 = __shfl_sync(0xffffffffu, sf[mc][kc][0], src1);
                float u1 = __shfl_sync(0xffffffffu, sf[mc][kc][1], src1);
                float w0 = __shfl_sync(0xffffffffu, sf[mc][kc][0], src2);
                float w1 = __shfl_sync(0xffffffffu, sf[mc][kc][1], src2);
                pa[mc][kc][0] = f2tf32((q & 1) ? u1 : u0);
                pa[mc][kc][2] = f2tf32((q & 1) ? w1 : w0);
                float x0 = __shfl_sync(0xffffffffu, sf[mc][kc][2], src1);
                float x1 = __shfl_sync(0xffffffffu, sf[mc][kc][3], src1);
                float y0 = __shfl_sync(0xffffffffu, sf[mc][kc][2], src2);
                float y1 = __shfl_sync(0xffffffffu, sf[mc][kc][3], src2);
                pa[mc][kc][1] = f2tf32((q & 1) ? x1 : x0);
                pa[mc][kc][3] = f2tf32((q & 1) ? y1 : y0);
            }

        // O += P V
#pragma unroll
        for (int dn = 0; dn < 4; dn++) {
#pragma unroll
            for (int kc = 0; kc < 4; kc++) {
                unsigned b0 = fbits(Vs[buf][kc * 8 + q][dn * 8 + g]);
                unsigned b1 = fbits(Vs[buf][kc * 8 + q + 4][dn * 8 + g]);
                mma8(oacc[0][dn], pa[0][kc], b0, b1);
                mma8(oacc[1][dn], pa[1][kc], b0, b1);
            }
        }
        __syncthreads();
    }

    // epilogue: normalize, round to tf32, store
#pragma unroll
    for (int mc = 0; mc < 2; mc++) {
        float inv0 = 1.0f / lrow[mc][0];
        float inv1 = 1.0f / lrow[mc][1];
        int r0 = b * TT + qrow0 + mc * 16 + g;
#pragma unroll
        for (int dn = 0; dn < 4; dn++) {
            int col = h * DK + dn * 8 + 2 * q;
            float2 o0, o1;
            o0.x = __uint_as_float(f2tf32(oacc[mc][dn][0] * inv0));
            o0.y = __uint_as_float(f2tf32(oacc[mc][dn][1] * inv0));
            o1.x = __uint_as_float(f2tf32(oacc[mc][dn][2] * inv1));
            o1.y = __uint_as_float(f2tf32(oacc[mc][dn][3] * inv1));
            *(float2*)&g_attn[(size_t)r0 * DD + col]       = o0;
            *(float2*)&g_attn[(size_t)(r0 + 8) * DD + col] = o1;
        }
    }
}

// ============================================================
// 4. Wout GEMM + bias + residual + LayerNorm, fused.
//    Block 64x256 (full rows), 8 warps (2m x 4n), warp 32x64.
//    4-stage cp.async. Epilogue: row stats via shfl + smem.
// ============================================================
#define WBM 64
#define WBN 256
#define WGK 16
#define WAS_STRIDE 20
#define WBS_STRIDE 264
#define WAS_WORDS (4*WBM*WAS_STRIDE)
#define WBS_WORDS (4*WGK*WBS_STRIDE)
#define WSMEM_BYTES ((WAS_WORDS+WBS_WORDS+512)*4)

__global__ __launch_bounds__(256, 2)
void wout_ln_kernel(int layer, const float* __restrict__ bias,
                    const float* __restrict__ gamma,
                    const float* __restrict__ beta) {
    float* As   = dynsmem;
    float* Bs   = dynsmem + WAS_WORDS;
    float* redS = dynsmem + WAS_WORDS + WBS_WORDS;      // [64][4]
    float* redQ = redS + 256;                            // [64][4]
    const float* __restrict__ A = g_attn;
    const float* __restrict__ Bmat = g_wout32 + (size_t)layer * DD * DD;

    const int tid  = threadIdx.x;
    const int lane = tid & 31;
    const int g    = lane >> 2;
    const int q    = lane & 3;
    const int warp = tid >> 5;
    const int wm   = (warp & 1) * 32;
    const int wn   = (warp >> 1) * 64;
    const int bm   = blockIdx.x * WBM;

    auto issue = [&](int s) {
        int k0 = s * WGK;
        float* Asb = As + (s & 3) * WBM * WAS_STRIDE;
        float* Bsb = Bs + (s & 3) * WGK * WBS_STRIDE;
        {
            int r = tid >> 2, cc = (tid & 3) * 4;
            cp16(&Asb[r * WAS_STRIDE + cc], &A[(size_t)(bm + r) * DD + k0 + cc]);
        }
#pragma unroll
        for (int p = 0; p < 4; p++) {
            int c = tid + p * 256;
            int r = c >> 6, cc = (c & 63) * 4;
            cp16(&Bsb[r * WBS_STRIDE + cc], &Bmat[(size_t)(k0 + r) * DD + cc]);
        }
    };

    float acc[2][8][4];
#pragma unroll
    for (int mc = 0; mc < 2; mc++)
#pragma unroll
        for (int nc = 0; nc < 8; nc++)
#pragma unroll
            for (int i = 0; i < 4; i++) acc[mc][nc][i] = 0.0f;

    issue(0); cp_commit();
    issue(1); cp_commit();
    issue(2); cp_commit();

    const int NS = DD / WGK;    // 16
    for (int s = 0; s < NS; s++) {
        cp_wait<2>();
        __syncthreads();
        if (s + 3 < NS) issue(s + 3);
        cp_commit();

        const float* Asb = As + (s & 3) * WBM * WAS_STRIDE;
        const float* Bsb = Bs + (s & 3) * WGK * WBS_STRIDE;
#pragma unroll
        for (int kk = 0; kk < 2; kk++) {
            int kb = kk * 8;
            unsigned af[2][4], bf[8][2];
#pragma unroll
            for (int mc = 0; mc < 2; mc++) {
                int r = wm + mc * 16 + g;
                af[mc][0] = fbits(Asb[r * WAS_STRIDE + kb + q]);
                af[mc][1] = fbits(Asb[(r + 8) * WAS_STRIDE + kb + q]);
                af[mc][2] = fbits(Asb[r * WAS_STRIDE + kb + q + 4]);
                af[mc][3] = fbits(Asb[(r + 8) * WAS_STRIDE + kb + q + 4]);
            }
#pragma unroll
            for (int nc = 0; nc < 8; nc++) {
                int cc = wn + nc * 8 + g;
                bf[nc][0] = fbits(Bsb[(kb + q) * WBS_STRIDE + cc]);
                bf[nc][1] = fbits(Bsb[(kb + q + 4) * WBS_STRIDE + cc]);
            }
#pragma unroll
            for (int mc = 0; mc < 2; mc++)
#pragma unroll
                for (int nc = 0; nc < 8; nc++)
                    mma8(acc[mc][nc], af[mc], bf[nc][0], bf[nc][1]);
        }
    }
    __syncthreads();   // staging smem free; safe before reduction reuse

    // epilogue part 1: + bias + residual (fp32)
#pragma unroll
    for (int mc = 0; mc < 2; mc++) {
        int rlo = bm + wm + mc * 16 + g;
#pragma unroll
        for (int nc = 0; nc < 8; nc++) {
            int col = wn + nc * 8 + 2 * q;
            float2 bi = *(const float2*)&bias[col];
            float2 h0 = *(const float2*)&g_h[(size_t)rlo * DD + col];
            float2 h1 = *(const float2*)&g_h[(size_t)(rlo + 8) * DD + col];
            acc[mc][nc][0] += bi.x + h0.x;
            acc[mc][nc][1] += bi.y + h0.y;
            acc[mc][nc][2] += bi.x + h1.x;
            acc[mc][nc][3] += bi.y + h1.y;
        }
    }

    // epilogue part 2: row stats
    const int ng = warp >> 1;
#pragma unroll
    for (int mc = 0; mc < 2; mc++) {
        float slo = 0.f, qlo = 0.f, shi = 0.f, qhi = 0.f;
#pragma unroll
        for (int nc = 0; nc < 8; nc++) {
            slo += acc[mc][nc][0] + acc[mc][nc][1];
            qlo += acc[mc][nc][0] * acc[mc][nc][0] + acc[mc][nc][1] * acc[mc][nc][1];
            shi += acc[mc][nc][2] + acc[mc][nc][3];
            qhi += acc[mc][nc][2] * acc[mc][nc][2] + acc[mc][nc][3] * acc[mc][nc][3];
        }
        slo += __shfl_xor_sync(0xffffffffu, slo, 1); slo += __shfl_xor_sync(0xffffffffu, slo, 2);
        qlo += __shfl_xor_sync(0xffffffffu, qlo, 1); qlo += __shfl_xor_sync(0xffffffffu, qlo, 2);
        shi += __shfl_xor_sync(0xffffffffu, shi, 1); shi += __shfl_xor_sync(0xffffffffu, shi, 2);
        qhi += __shfl_xor_sync(0xffffffffu, qhi, 1); qhi += __shfl_xor_sync(0xffffffffu, qhi, 2);
        if (q == 0) {
            int rlo = wm + mc * 16 + g;
            redS[rlo * 4 + ng] = slo;  redQ[rlo * 4 + ng] = qlo;
            redS[(rlo + 8) * 4 + ng] = shi;  redQ[(rlo + 8) * 4 + ng] = qhi;
        }
    }
    __syncthreads();

    // epilogue part 3: normalize + store (fp32 + tf32)
#pragma unroll
    for (int mc = 0; mc < 2; mc++) {
        int rl = wm + mc * 16 + g;
        float slo = redS[rl*4] + redS[rl*4+1] + redS[rl*4+2] + redS[rl*4+3];
        float qlo = redQ[rl*4] + redQ[rl*4+1] + redQ[rl*4+2] + redQ[rl*4+3];
        float shi = redS[(rl+8)*4] + redS[(rl+8)*4+1] + redS[(rl+8)*4+2] + redS[(rl+8)*4+3];
        float qhi = redQ[(rl+8)*4] + redQ[(rl+8)*4+1] + redQ[(rl+8)*4+2] + redQ[(rl+8)*4+3];
        float mulo = slo * (1.0f / DD);
        float muhi = shi * (1.0f / DD);
        float rslo = rsqrtf(qlo * (1.0f / DD) - mulo * mulo + LN_EPS);
        float rshi = rsqrtf(qhi * (1.0f / DD) - muhi * muhi + LN_EPS);
        int rowlo = bm + rl;
#pragma unroll
        for (int nc = 0; nc < 8; nc++) {
            int col = wn + nc * 8 + 2 * q;
            float2 ga = *(const float2*)&gamma[col];
            float2 be = *(const float2*)&beta[col];
            float v0 = (acc[mc][nc][0] - mulo) * rslo * ga.x + be.x;
            float v1 = (acc[mc][nc][1] - mulo) * rslo * ga.y + be.y;
            float v2 = (acc[mc][nc][2] - muhi) * rshi * ga.x + be.x;
            float v3 = (acc[mc][nc][3] - muhi) * rshi * ga.y + be.y;
            *(float2*)&g_h[(size_t)rowlo * DD + col]       = make_float2(v0, v1);
            *(float2*)&g_h[(size_t)(rowlo + 8) * DD + col] = make_float2(v2, v3);
            float2 t0, t1;
            t0.x = __uint_as_float(f2tf32(v0)); t0.y = __uint_as_float(f2tf32(v1));
            t1.x = __uint_as_float(f2tf32(v2)); t1.y = __uint_as_float(f2tf32(v3));
            *(float2*)&g_h32[(size_t)rowlo * DD + col]       = t0;
            *(float2*)&g_h32[(size_t)(rowlo + 8) * DD + col] = t1;
        }
    }
}

// ============================================================
// 5. Head
// ============================================================
__global__ void head_kernel(const float* __restrict__ Wo,
                            const float* __restrict__ bo,
                            float* __restrict__ out) {
    int b = blockIdx.x / 3;
    int j = blockIdx.x - b * 3;
    int lane = threadIdx.x;
    const float* hr = g_h + (size_t)(b * TT + (TT - 1)) * DD;
    float s = 0.0f;
    for (int d = lane; d < DD; d += 32)
        s = fmaf(hr[d], Wo[d * 3 + j], s);
#pragma unroll
    for (int o = 16; o > 0; o >>= 1)
        s += __shfl_xor_sync(0xffffffffu, s, o);
    if (lane == 0) out[b * 3 + j] = s + bo[j];
}

// ============================================================
// launch
// ============================================================
extern "C" void kernel_launch(void* const* d_in, const int* in_sizes, int n_in,
                              void* d_out, int out_size) {
    const float* x    = (const float*)d_in[0];
    const float* Wp   = (const float*)d_in[1];
    const float* bp   = (const float*)d_in[2];
    const float* pos  = (const float*)d_in[3];
    const float* Wqkv = (const float*)d_in[4];
    const float* bqkv = (const float*)d_in[5];
    const float* Wout = (const float*)d_in[6];
    const float* bout = (const float*)d_in[7];
    const float* ln_g = (const float*)d_in[8];
    const float* ln_b = (const float*)d_in[9];
    const float* Wo   = (const float*)d_in[10];
    const float* bo   = (const float*)d_in[11];
    float* out = (float*)d_out;

    cudaFuncSetAttribute(qkv_gemm_kernel, cudaFuncAttributeMaxDynamicSharedMemorySize, QSMEM_BYTES);
    cudaFuncSetAttribute(wout_ln_kernel,  cudaFuncAttributeMaxDynamicSharedMemorySize, WSMEM_BYTES);

    convw_kernel<<<(LL * DD * 3 * DD + 255) / 256, 256>>>(Wqkv, Wout);
    proj_kernel<<<(NROW * DD + 255) / 256, 256>>>(x, Wp, bp, pos);

    for (int l = 0; l < LL; l++) {
        qkv_gemm_kernel<<<dim3((3 * DD) / QBN, NROW / QBM), 256, QSMEM_BYTES>>>(
            l, bqkv + (size_t)l * 3 * DD);
        attn_tc_kernel<<<dim3(TT / 128, HH, BB), 128>>>();
        wout_ln_kernel<<<NROW / WBM, 256, WSMEM_BYTES>>>(
            l, bout + (size_t)l * DD, ln_g + (size_t)l * DD, ln_b + (size_t)l * DD);
    }

    head_kernel<<<24, 32>>>(Wo, bo, out);
}

// round 6
// speedup vs baseline: 5.0709x; 1.1341x over previous
#include <cuda_runtime.h>
#include <cuda_fp16.h>
#include <math.h>

// Problem constants
#define BB 8
#define TT 1024
#define IN_DIM 16
#define DD 256
#define HH 8
#define DK 32
#define LL 4
#define NROW (BB*TT)
#define LN_EPS 1e-5f

// -------- scratch (device globals) --------
__device__ float g_h[NROW*DD];          // fp32 residual stream
__device__ float g_h32[NROW*DD];        // tf32-rounded copy (GEMM A input)
__device__ float g_qkv[NROW*3*DD];      // tf32-rounded qkv
__device__ float g_attn[NROW*DD];       // tf32-rounded attention out
__device__ float g_wqkv32[LL*DD*3*DD];  // tf32-rounded weights
__device__ float g_wout32[LL*DD*DD];

// -------- helpers --------
__device__ __forceinline__ unsigned f2tf32(float x) {
    unsigned r;
    asm("cvt.rna.tf32.f32 %0, %1;" : "=r"(r) : "f"(x));
    return r;
}
__device__ __forceinline__ void mma8(float* d, const unsigned* a, unsigned b0, unsigned b1) {
    asm volatile(
        "mma.sync.aligned.m16n8k8.row.col.f32.tf32.tf32.f32 "
        "{%0,%1,%2,%3}, {%4,%5,%6,%7}, {%8,%9}, {%0,%1,%2,%3};\n"
        : "+f"(d[0]), "+f"(d[1]), "+f"(d[2]), "+f"(d[3])
        : "r"(a[0]), "r"(a[1]), "r"(a[2]), "r"(a[3]), "r"(b0), "r"(b1));
}
// fp16 m16n8k16 with fp32 accumulate (same mantissa width as tf32)
__device__ __forceinline__ void mma16h(float* d, const unsigned* a, unsigned b0, unsigned b1) {
    asm volatile(
        "mma.sync.aligned.m16n8k16.row.col.f32.f16.f16.f32 "
        "{%0,%1,%2,%3}, {%4,%5,%6,%7}, {%8,%9}, {%0,%1,%2,%3};\n"
        : "+f"(d[0]), "+f"(d[1]), "+f"(d[2]), "+f"(d[3])
        : "r"(a[0]), "r"(a[1]), "r"(a[2]), "r"(a[3]), "r"(b0), "r"(b1));
}
__device__ __forceinline__ unsigned pkh2(float lo, float hi) {
    __half2 h = __floats2half2_rn(lo, hi);   // .x = lo, .y = hi
    return *reinterpret_cast<unsigned*>(&h);
}
__device__ __forceinline__ void cp16(void* smem, const void* g) {
    unsigned a = (unsigned)__cvta_generic_to_shared(smem);
    asm volatile("cp.async.cg.shared.global [%0], [%1], 16;\n" :: "r"(a), "l"(g));
}
__device__ __forceinline__ void cp_commit() { asm volatile("cp.async.commit_group;\n"); }
template<int N> __device__ __forceinline__ void cp_wait() {
    asm volatile("cp.async.wait_group %0;\n" :: "n"(N));
}
__device__ __forceinline__ unsigned fbits(float x) { return __float_as_uint(x); }

// ============================================================
// 0. Weight conversion to tf32 (once per launch)
// ============================================================
__global__ void convw_kernel(const float* __restrict__ Wqkv,
                             const float* __restrict__ Wout) {
    int i = blockIdx.x * 256 + threadIdx.x;
    if (i < LL * DD * 3 * DD) g_wqkv32[i] = __uint_as_float(f2tf32(Wqkv[i]));
    if (i < LL * DD * DD)     g_wout32[i] = __uint_as_float(f2tf32(Wout[i]));
}

// ============================================================
// 1. Projection: h = x @ Wp + bp + pos  (fp32 + tf32 copy)
// ============================================================
__global__ void proj_kernel(const float* __restrict__ x,
                            const float* __restrict__ Wp,
                            const float* __restrict__ bp,
                            const float* __restrict__ pos) {
    int idx = blockIdx.x * blockDim.x + threadIdx.x;
    if (idx >= NROW * DD) return;
    int row = idx / DD;
    int col = idx - row * DD;
    int t = row & (TT - 1);
    const float* xr = x + row * IN_DIM;
    float s = bp[col] + pos[t * DD + col];
#pragma unroll
    for (int i = 0; i < IN_DIM; i++)
        s = fmaf(xr[i], Wp[i * DD + col], s);
    g_h[idx] = s;
    g_h32[idx] = __uint_as_float(f2tf32(s));
}

// ============================================================
// 2. QKV GEMM: g_qkv = g_h32 @ Wqkv32[l] + bqkv[l]  (tf32 out)
//    Block 128x128, 8 warps (2m x 4n), warp 64x32.
//    4-stage cp.async, K staged 16. Conflict-free strides 20/136.
// ============================================================
#define QBM 128
#define QBN 128
#define QGK 16
#define QAS_STRIDE 20
#define QBS_STRIDE 136
#define QAS_WORDS (4*QBM*QAS_STRIDE)
#define QBS_WORDS (4*QGK*QBS_STRIDE)
#define QSMEM_BYTES ((QAS_WORDS+QBS_WORDS)*4)

extern __shared__ float dynsmem[];

__global__ __launch_bounds__(256, 2)
void qkv_gemm_kernel(int layer, const float* __restrict__ bias) {
    float* As = dynsmem;                 // [4][128][20]
    float* Bs = dynsmem + QAS_WORDS;     // [4][16][136]
    const float* __restrict__ A = g_h32;
    const float* __restrict__ Bmat = g_wqkv32 + (size_t)layer * DD * 3 * DD;
    const int N = 3 * DD;

    const int tid  = threadIdx.x;
    const int lane = tid & 31;
    const int g    = lane >> 2;
    const int q    = lane & 3;
    const int warp = tid >> 5;
    const int wm   = (warp & 1) * 64;
    const int wn   = (warp >> 1) * 32;
    const int bm   = blockIdx.y * QBM;
    const int bn   = blockIdx.x * QBN;

    auto issue = [&](int s) {
        int k0 = s * QGK;
        float* Asb = As + (s & 3) * QBM * QAS_STRIDE;
        float* Bsb = Bs + (s & 3) * QGK * QBS_STRIDE;
#pragma unroll
        for (int p = 0; p < 2; p++) {
            int c = tid + p * 256;
            int r = c >> 2, cc = (c & 3) * 4;
            cp16(&Asb[r * QAS_STRIDE + cc], &A[(size_t)(bm + r) * DD + k0 + cc]);
        }
#pragma unroll
        for (int p = 0; p < 2; p++) {
            int c = tid + p * 256;
            int r = c >> 5, cc = (c & 31) * 4;
            cp16(&Bsb[r * QBS_STRIDE + cc], &Bmat[(size_t)(k0 + r) * N + bn + cc]);
        }
    };

    float acc[4][4][4];
#pragma unroll
    for (int mc = 0; mc < 4; mc++)
#pragma unroll
        for (int nc = 0; nc < 4; nc++)
#pragma unroll
            for (int i = 0; i < 4; i++) acc[mc][nc][i] = 0.0f;

    issue(0); cp_commit();
    issue(1); cp_commit();
    issue(2); cp_commit();

    const int NS = DD / QGK;   // 16
    for (int s = 0; s < NS; s++) {
        cp_wait<2>();
        __syncthreads();
        if (s + 3 < NS) issue(s + 3);
        cp_commit();

        const float* Asb = As + (s & 3) * QBM * QAS_STRIDE;
        const float* Bsb = Bs + (s & 3) * QGK * QBS_STRIDE;
#pragma unroll
        for (int kk = 0; kk < 2; kk++) {
            int kb = kk * 8;
            unsigned af[4][4], bf[4][2];
#pragma unroll
            for (int mc = 0; mc < 4; mc++) {
                int r = wm + mc * 16 + g;
                af[mc][0] = fbits(Asb[r * QAS_STRIDE + kb + q]);
                af[mc][1] = fbits(Asb[(r + 8) * QAS_STRIDE + kb + q]);
                af[mc][2] = fbits(Asb[r * QAS_STRIDE + kb + q + 4]);
                af[mc][3] = fbits(Asb[(r + 8) * QAS_STRIDE + kb + q + 4]);
            }
#pragma unroll
            for (int nc = 0; nc < 4; nc++) {
                int cc = wn + nc * 8 + g;
                bf[nc][0] = fbits(Bsb[(kb + q) * QBS_STRIDE + cc]);
                bf[nc][1] = fbits(Bsb[(kb + q + 4) * QBS_STRIDE + cc]);
            }
#pragma unroll
            for (int mc = 0; mc < 4; mc++)
#pragma unroll
                for (int nc = 0; nc < 4; nc++)
                    mma8(acc[mc][nc], af[mc], bf[nc][0], bf[nc][1]);
        }
    }

    // epilogue: + bias, round to tf32, store
#pragma unroll
    for (int mc = 0; mc < 4; mc++) {
#pragma unroll
        for (int nc = 0; nc < 4; nc++) {
            int row = bm + wm + mc * 16 + g;
            int col = bn + wn + nc * 8 + 2 * q;
            float2 bi = *(const float2*)&bias[col];
            float2 o0, o1;
            o0.x = __uint_as_float(f2tf32(acc[mc][nc][0] + bi.x));
            o0.y = __uint_as_float(f2tf32(acc[mc][nc][1] + bi.y));
            o1.x = __uint_as_float(f2tf32(acc[mc][nc][2] + bi.x));
            o1.y = __uint_as_float(f2tf32(acc[mc][nc][3] + bi.y));
            *(float2*)&g_qkv[(size_t)row * N + col]       = o0;
            *(float2*)&g_qkv[(size_t)(row + 8) * N + col] = o1;
        }
    }
}

// ============================================================
// 3. Tensor-core flash attention.
//    QK^T in tf32 (score precision). PV in fp16 m16n8k16 with
//    fp32 accumulate (fp16 mantissa == tf32 mantissa, so no
//    precision loss; P in [0,1], V ~ O(1)).
//    KEY TRICK: S C-fragment layout (g, 2q/2q+1) IS the fp16
//    m16n8k16 A-fragment layout -> P needs NO shuffles, just
//    cvt.rn.f16x2 packs. V staged half2-packed along keys
//    (stride-40 rows: bank = (8q+g+8dn)%32, conflict-free).
// ============================================================
__global__ __launch_bounds__(128, 4)
void attn_tc_kernel() {
    __shared__ float    Ks[2][32][36];     // K fp32 tiles (cp.async)
    __shared__ unsigned Vhs[2][16][40];    // V half2 pairs: [keypair][col], stride 40

    const int tid  = threadIdx.x;
    const int lane = tid & 31;
    const int g    = lane >> 2;
    const int q    = lane & 3;
    const int warp = tid >> 5;
    const int h    = blockIdx.y;
    const int b    = blockIdx.z;
    const int qrow0 = blockIdx.x * 128 + warp * 32;

    const float qs = 0.17677669529663687f * 1.4426950408889634f; // scale*log2e

    const float* kg = g_qkv + (size_t)b * TT * (3 * DD) + DD + h * DK;
    const float* vg = g_qkv + (size_t)b * TT * (3 * DD) + 2 * DD + h * DK;
    const float* qg = g_qkv + (size_t)(b * TT + qrow0) * (3 * DD) + h * DK;

    // K staging indices (cp.async): 128 thr cover 32 rows x 32 cols
    const int sr = tid >> 3;            // 0..15
    const int sc = (tid & 7) * 4;       // 0..28
    // V staging indices (LDG+pack+STS): thread -> (key pair vj, col group vc)
    const int vj = tid >> 3;            // 0..15 (keys 2vj, 2vj+1)
    const int vc = (tid & 7) * 4;       // 0..28

    // prologue: K tile 0 via cp.async
    cp16(&Ks[0][sr][sc],      kg + (size_t)sr * (3 * DD) + sc);
    cp16(&Ks[0][sr + 16][sc], kg + (size_t)(sr + 16) * (3 * DD) + sc);
    cp_commit();
    // prologue: V tile 0 -> half2 packed
    {
        const float* vr = vg + (size_t)(2 * vj) * (3 * DD) + vc;
        float4 va = *(const float4*)vr;
        float4 vb = *(const float4*)(vr + 3 * DD);
        uint4 p;
        p.x = pkh2(va.x, vb.x); p.y = pkh2(va.y, vb.y);
        p.z = pkh2(va.z, vb.z); p.w = pkh2(va.w, vb.w);
        *(uint4*)&Vhs[0][vj][vc] = p;
    }

    // Q A-fragments (tf32 bits, resident)
    unsigned qa[2][4][4];
#pragma unroll
    for (int mc = 0; mc < 2; mc++)
#pragma unroll
        for (int kc = 0; kc < 4; kc++) {
            int r = mc * 16 + g;
            qa[mc][kc][0] = fbits(qg[(size_t)r * (3 * DD) + kc * 8 + q]);
            qa[mc][kc][1] = fbits(qg[(size_t)(r + 8) * (3 * DD) + kc * 8 + q]);
            qa[mc][kc][2] = fbits(qg[(size_t)r * (3 * DD) + kc * 8 + q + 4]);
            qa[mc][kc][3] = fbits(qg[(size_t)(r + 8) * (3 * DD) + kc * 8 + q + 4]);
        }

    float oacc[2][4][4];
    float mrow[2][2], lrow[2][2];
#pragma unroll
    for (int mc = 0; mc < 2; mc++) {
        mrow[mc][0] = -1e30f; mrow[mc][1] = -1e30f;
        lrow[mc][0] = 0.0f;   lrow[mc][1] = 0.0f;
#pragma unroll
        for (int nc = 0; nc < 4; nc++)
#pragma unroll
            for (int i = 0; i < 4; i++) oacc[mc][nc][i] = 0.0f;
    }

    const int NT = TT / 32;
    for (int t = 0; t < NT; t++) {
        int buf = t & 1;
        int nb  = buf ^ 1;
        float4 va, vb;
        if (t + 1 < NT) {
            int k0 = (t + 1) * 32;
            cp16(&Ks[nb][sr][sc],      kg + (size_t)(k0 + sr) * (3 * DD) + sc);
            cp16(&Ks[nb][sr + 16][sc], kg + (size_t)(k0 + sr + 16) * (3 * DD) + sc);
            cp_commit();
            const float* vr = vg + (size_t)(k0 + 2 * vj) * (3 * DD) + vc;
            va = *(const float4*)vr;
            vb = *(const float4*)(vr + 3 * DD);
            cp_wait<1>();
        } else {
            cp_wait<0>();
        }
        __syncthreads();

        // ---- S = Q K^T (tf32, raw/unscaled) ----
        float sf[2][4][4];
#pragma unroll
        for (int mc = 0; mc < 2; mc++)
#pragma unroll
            for (int nc = 0; nc < 4; nc++)
#pragma unroll
                for (int i = 0; i < 4; i++) sf[mc][nc][i] = 0.0f;

#pragma unroll
        for (int nc = 0; nc < 4; nc++) {
#pragma unroll
            for (int kc = 0; kc < 4; kc++) {
                unsigned b0 = fbits(Ks[buf][nc * 8 + g][kc * 8 + q]);
                unsigned b1 = fbits(Ks[buf][nc * 8 + g][kc * 8 + q + 4]);
                mma8(sf[0][nc], qa[0][kc], b0, b1);
                mma8(sf[1][nc], qa[1][kc], b0, b1);
            }
        }

        // ---- online softmax (scale folded into exp2 argument) ----
#pragma unroll
        for (int mc = 0; mc < 2; mc++) {
            float mx0 = sf[mc][0][0], mx1 = sf[mc][0][2];
#pragma unroll
            for (int nc = 0; nc < 4; nc++) {
                mx0 = fmaxf(mx0, fmaxf(sf[mc][nc][0], sf[mc][nc][1]));
                mx1 = fmaxf(mx1, fmaxf(sf[mc][nc][2], sf[mc][nc][3]));
            }
            mx0 = fmaxf(mx0, __shfl_xor_sync(0xffffffffu, mx0, 1));
            mx0 = fmaxf(mx0, __shfl_xor_sync(0xffffffffu, mx0, 2));
            mx1 = fmaxf(mx1, __shfl_xor_sync(0xffffffffu, mx1, 1));
            mx1 = fmaxf(mx1, __shfl_xor_sync(0xffffffffu, mx1, 2));
            float nm0 = fmaxf(mrow[mc][0], mx0);
            float nm1 = fmaxf(mrow[mc][1], mx1);
            float f0 = exp2f((mrow[mc][0] - nm0) * qs);
            float f1 = exp2f((mrow[mc][1] - nm1) * qs);
            mrow[mc][0] = nm0; mrow[mc][1] = nm1;
            float c0 = nm0 * qs, c1 = nm1 * qs;
            float s0 = 0.0f, s1 = 0.0f;
#pragma unroll
            for (int nc = 0; nc < 4; nc++) {
                sf[mc][nc][0] = exp2f(fmaf(sf[mc][nc][0], qs, -c0));
                sf[mc][nc][1] = exp2f(fmaf(sf[mc][nc][1], qs, -c0));
                sf[mc][nc][2] = exp2f(fmaf(sf[mc][nc][2], qs, -c1));
                sf[mc][nc][3] = exp2f(fmaf(sf[mc][nc][3], qs, -c1));
                s0 += sf[mc][nc][0] + sf[mc][nc][1];
                s1 += sf[mc][nc][2] + sf[mc][nc][3];
            }
            s0 += __shfl_xor_sync(0xffffffffu, s0, 1);
            s0 += __shfl_xor_sync(0xffffffffu, s0, 2);
            s1 += __shfl_xor_sync(0xffffffffu, s1, 1);
            s1 += __shfl_xor_sync(0xffffffffu, s1, 2);
            lrow[mc][0] = lrow[mc][0] * f0 + s0;
            lrow[mc][1] = lrow[mc][1] * f1 + s1;
#pragma unroll
            for (int nc = 0; nc < 4; nc++) {
                oacc[mc][nc][0] *= f0; oacc[mc][nc][1] *= f0;
                oacc[mc][nc][2] *= f1; oacc[mc][nc][3] *= f1;
            }
        }

        // ---- O += P V  (fp16 m16n8k16; P pack = C-frag identity) ----
#pragma unroll
        for (int kk = 0; kk < 2; kk++) {
            unsigned pa0[4], pa1[4];
            pa0[0] = pkh2(sf[0][2*kk][0],   sf[0][2*kk][1]);
            pa0[1] = pkh2(sf[0][2*kk][2],   sf[0][2*kk][3]);
            pa0[2] = pkh2(sf[0][2*kk+1][0], sf[0][2*kk+1][1]);
            pa0[3] = pkh2(sf[0][2*kk+1][2], sf[0][2*kk+1][3]);
            pa1[0] = pkh2(sf[1][2*kk][0],   sf[1][2*kk][1]);
            pa1[1] = pkh2(sf[1][2*kk][2],   sf[1][2*kk][3]);
            pa1[2] = pkh2(sf[1][2*kk+1][0], sf[1][2*kk+1][1]);
            pa1[3] = pkh2(sf[1][2*kk+1][2], sf[1][2*kk+1][3]);
#pragma unroll
            for (int dn = 0; dn < 4; dn++) {
                unsigned b0 = Vhs[buf][8*kk + q][dn * 8 + g];
                unsigned b1 = Vhs[buf][8*kk + q + 4][dn * 8 + g];
                mma16h(oacc[0][dn], pa0, b0, b1);
                mma16h(oacc[1][dn], pa1, b0, b1);
            }
        }

        // commit prefetched V tile (half2 packed) into other buffer
        if (t + 1 < NT) {
            uint4 p;
            p.x = pkh2(va.x, vb.x); p.y = pkh2(va.y, vb.y);
            p.z = pkh2(va.z, vb.z); p.w = pkh2(va.w, vb.w);
            *(uint4*)&Vhs[nb][vj][vc] = p;
        }
        __syncthreads();
    }

    // ---- epilogue: normalize, round to tf32, store ----
#pragma unroll
    for (int mc = 0; mc < 2; mc++) {
        float inv0 = 1.0f / lrow[mc][0];
        float inv1 = 1.0f / lrow[mc][1];
        int r0 = b * TT + qrow0 + mc * 16 + g;
#pragma unroll
        for (int dn = 0; dn < 4; dn++) {
            int col = h * DK + dn * 8 + 2 * q;
            float2 o0, o1;
            o0.x = __uint_as_float(f2tf32(oacc[mc][dn][0] * inv0));
            o0.y = __uint_as_float(f2tf32(oacc[mc][dn][1] * inv0));
            o1.x = __uint_as_float(f2tf32(oacc[mc][dn][2] * inv1));
            o1.y = __uint_as_float(f2tf32(oacc[mc][dn][3] * inv1));
            *(float2*)&g_attn[(size_t)r0 * DD + col]       = o0;
            *(float2*)&g_attn[(size_t)(r0 + 8) * DD + col] = o1;
        }
    }
}

// ============================================================
// 4. Wout GEMM + bias + residual + LayerNorm, fused.
//    Block 64x256 (full rows), 8 warps (2m x 4n), warp 32x64.
//    4-stage cp.async. Epilogue: row stats via shfl + smem.
// ============================================================
#define WBM 64
#define WBN 256
#define WGK 16
#define WAS_STRIDE 20
#define WBS_STRIDE 264
#define WAS_WORDS (4*WBM*WAS_STRIDE)
#define WBS_WORDS (4*WGK*WBS_STRIDE)
#define WSMEM_BYTES ((WAS_WORDS+WBS_WORDS+512)*4)

__global__ __launch_bounds__(256, 2)
void wout_ln_kernel(int layer, const float* __restrict__ bias,
                    const float* __restrict__ gamma,
                    const float* __restrict__ beta) {
    float* As   = dynsmem;
    float* Bs   = dynsmem + WAS_WORDS;
    float* redS = dynsmem + WAS_WORDS + WBS_WORDS;      // [64][4]
    float* redQ = redS + 256;                            // [64][4]
    const float* __restrict__ A = g_attn;
    const float* __restrict__ Bmat = g_wout32 + (size_t)layer * DD * DD;

    const int tid  = threadIdx.x;
    const int lane = tid & 31;
    const int g    = lane >> 2;
    const int q    = lane & 3;
    const int warp = tid >> 5;
    const int wm   = (warp & 1) * 32;
    const int wn   = (warp >> 1) * 64;
    const int bm   = blockIdx.x * WBM;

    auto issue = [&](int s) {
        int k0 = s * WGK;
        float* Asb = As + (s & 3) * WBM * WAS_STRIDE;
        float* Bsb = Bs + (s & 3) * WGK * WBS_STRIDE;
        {
            int r = tid >> 2, cc = (tid & 3) * 4;
            cp16(&Asb[r * WAS_STRIDE + cc], &A[(size_t)(bm + r) * DD + k0 + cc]);
        }
#pragma unroll
        for (int p = 0; p < 4; p++) {
            int c = tid + p * 256;
            int r = c >> 6, cc = (c & 63) * 4;
            cp16(&Bsb[r * WBS_STRIDE + cc], &Bmat[(size_t)(k0 + r) * DD + cc]);
        }
    };

    float acc[2][8][4];
#pragma unroll
    for (int mc = 0; mc < 2; mc++)
#pragma unroll
        for (int nc = 0; nc < 8; nc++)
#pragma unroll
            for (int i = 0; i < 4; i++) acc[mc][nc][i] = 0.0f;

    issue(0); cp_commit();
    issue(1); cp_commit();
    issue(2); cp_commit();

    const int NS = DD / WGK;    // 16
    for (int s = 0; s < NS; s++) {
        cp_wait<2>();
        __syncthreads();
        if (s + 3 < NS) issue(s + 3);
        cp_commit();

        const float* Asb = As + (s & 3) * WBM * WAS_STRIDE;
        const float* Bsb = Bs + (s & 3) * WGK * WBS_STRIDE;
#pragma unroll
        for (int kk = 0; kk < 2; kk++) {
            int kb = kk * 8;
            unsigned af[2][4], bf[8][2];
#pragma unroll
            for (int mc = 0; mc < 2; mc++) {
                int r = wm + mc * 16 + g;
                af[mc][0] = fbits(Asb[r * WAS_STRIDE + kb + q]);
                af[mc][1] = fbits(Asb[(r + 8) * WAS_STRIDE + kb + q]);
                af[mc][2] = fbits(Asb[r * WAS_STRIDE + kb + q + 4]);
                af[mc][3] = fbits(Asb[(r + 8) * WAS_STRIDE + kb + q + 4]);
            }
#pragma unroll
            for (int nc = 0; nc < 8; nc++) {
                int cc = wn + nc * 8 + g;
                bf[nc][0] = fbits(Bsb[(kb + q) * WBS_STRIDE + cc]);
                bf[nc][1] = fbits(Bsb[(kb + q + 4) * WBS_STRIDE + cc]);
            }
#pragma unroll
            for (int mc = 0; mc < 2; mc++)
#pragma unroll
                for (int nc = 0; nc < 8; nc++)
                    mma8(acc[mc][nc], af[mc], bf[nc][0], bf[nc][1]);
        }
    }
    __syncthreads();   // staging smem free; safe before reduction reuse

    // epilogue part 1: + bias + residual (fp32)
#pragma unroll
    for (int mc = 0; mc < 2; mc++) {
        int rlo = bm + wm + mc * 16 + g;
#pragma unroll
        for (int nc = 0; nc < 8; nc++) {
            int col = wn + nc * 8 + 2 * q;
            float2 bi = *(const float2*)&bias[col];
            float2 h0 = *(const float2*)&g_h[(size_t)rlo * DD + col];
            float2 h1 = *(const float2*)&g_h[(size_t)(rlo + 8) * DD + col];
            acc[mc][nc][0] += bi.x + h0.x;
            acc[mc][nc][1] += bi.y + h0.y;
            acc[mc][nc][2] += bi.x + h1.x;
            acc[mc][nc][3] += bi.y + h1.y;
        }
    }

    // epilogue part 2: row stats
    const int ng = warp >> 1;
#pragma unroll
    for (int mc = 0; mc < 2; mc++) {
        float slo = 0.f, qlo = 0.f, shi = 0.f, qhi = 0.f;
#pragma unroll
        for (int nc = 0; nc < 8; nc++) {
            slo += acc[mc][nc][0] + acc[mc][nc][1];
            qlo += acc[mc][nc][0] * acc[mc][nc][0] + acc[mc][nc][1] * acc[mc][nc][1];
            shi += acc[mc][nc][2] + acc[mc][nc][3];
            qhi += acc[mc][nc][2] * acc[mc][nc][2] + acc[mc][nc][3] * acc[mc][nc][3];
        }
        slo += __shfl_xor_sync(0xffffffffu, slo, 1); slo += __shfl_xor_sync(0xffffffffu, slo, 2);
        qlo += __shfl_xor_sync(0xffffffffu, qlo, 1); qlo += __shfl_xor_sync(0xffffffffu, qlo, 2);
        shi += __shfl_xor_sync(0xffffffffu, shi, 1); shi += __shfl_xor_sync(0xffffffffu, shi, 2);
        qhi += __shfl_xor_sync(0xffffffffu, qhi, 1); qhi += __shfl_xor_sync(0xffffffffu, qhi, 2);
        if (q == 0) {
            int rlo = wm + mc * 16 + g;
            redS[rlo * 4 + ng] = slo;  redQ[rlo * 4 + ng] = qlo;
            redS[(rlo + 8) * 4 + ng] = shi;  redQ[(rlo + 8) * 4 + ng] = qhi;
        }
    }
    __syncthreads();

    // epilogue part 3: normalize + store (fp32 + tf32)
#pragma unroll
    for (int mc = 0; mc < 2; mc++) {
        int rl = wm + mc * 16 + g;
        float slo = redS[rl*4] + redS[rl*4+1] + redS[rl*4+2] + redS[rl*4+3];
        float qlo = redQ[rl*4] + redQ[rl*4+1] + redQ[rl*4+2] + redQ[rl*4+3];
        float shi = redS[(rl+8)*4] + redS[(rl+8)*4+1] + redS[(rl+8)*4+2] + redS[(rl+8)*4+3];
        float qhi = redQ[(rl+8)*4] + redQ[(rl+8)*4+1] + redQ[(rl+8)*4+2] + redQ[(rl+8)*4+3];
        float mulo = slo * (1.0f / DD);
        float muhi = shi * (1.0f / DD);
        float rslo = rsqrtf(qlo * (1.0f / DD) - mulo * mulo + LN_EPS);
        float rshi = rsqrtf(qhi * (1.0f / DD) - muhi * muhi + LN_EPS);
        int rowlo = bm + rl;
#pragma unroll
        for (int nc = 0; nc < 8; nc++) {
            int col = wn + nc * 8 + 2 * q;
            float2 ga = *(const float2*)&gamma[col];
            float2 be = *(const float2*)&beta[col];
            float v0 = (acc[mc][nc][0] - mulo) * rslo * ga.x + be.x;
            float v1 = (acc[mc][nc][1] - mulo) * rslo * ga.y + be.y;
            float v2 = (acc[mc][nc][2] - muhi) * rshi * ga.x + be.x;
            float v3 = (acc[mc][nc][3] - muhi) * rshi * ga.y + be.y;
            *(float2*)&g_h[(size_t)rowlo * DD + col]       = make_float2(v0, v1);
            *(float2*)&g_h[(size_t)(rowlo + 8) * DD + col] = make_float2(v2, v3);
            float2 t0, t1;
            t0.x = __uint_as_float(f2tf32(v0)); t0.y = __uint_as_float(f2tf32(v1));
            t1.x = __uint_as_float(f2tf32(v2)); t1.y = __uint_as_float(f2tf32(v3));
            *(float2*)&g_h32[(size_t)rowlo * DD + col]       = t0;
            *(float2*)&g_h32[(size_t)(rowlo + 8) * DD + col] = t1;
        }
    }
}

// ============================================================
// 5. Head
// ============================================================
__global__ void head_kernel(const float* __restrict__ Wo,
                            const float* __restrict__ bo,
                            float* __restrict__ out) {
    int b = blockIdx.x / 3;
    int j = blockIdx.x - b * 3;
    int lane = threadIdx.x;
    const float* hr = g_h + (size_t)(b * TT + (TT - 1)) * DD;
    float s = 0.0f;
    for (int d = lane; d < DD; d += 32)
        s = fmaf(hr[d], Wo[d * 3 + j], s);
#pragma unroll
    for (int o = 16; o > 0; o >>= 1)
        s += __shfl_xor_sync(0xffffffffu, s, o);
    if (lane == 0) out[b * 3 + j] = s + bo[j];
}

// ============================================================
// launch
// ============================================================
extern "C" void kernel_launch(void* const* d_in, const int* in_sizes, int n_in,
                              void* d_out, int out_size) {
    const float* x    = (const float*)d_in[0];
    const float* Wp   = (const float*)d_in[1];
    const float* bp   = (const float*)d_in[2];
    const float* pos  = (const float*)d_in[3];
    const float* Wqkv = (const float*)d_in[4];
    const float* bqkv = (const float*)d_in[5];
    const float* Wout = (const float*)d_in[6];
    const float* bout = (const float*)d_in[7];
    const float* ln_g = (const float*)d_in[8];
    const float* ln_b = (const float*)d_in[9];
    const float* Wo   = (const float*)d_in[10];
    const float* bo   = (const float*)d_in[11];
    float* out = (float*)d_out;

    cudaFuncSetAttribute(qkv_gemm_kernel, cudaFuncAttributeMaxDynamicSharedMemorySize, QSMEM_BYTES);
    cudaFuncSetAttribute(wout_ln_kernel,  cudaFuncAttributeMaxDynamicSharedMemorySize, WSMEM_BYTES);

    convw_kernel<<<(LL * DD * 3 * DD + 255) / 256, 256>>>(Wqkv, Wout);
    proj_kernel<<<(NROW * DD + 255) / 256, 256>>>(x, Wp, bp, pos);

    for (int l = 0; l < LL; l++) {
        qkv_gemm_kernel<<<dim3((3 * DD) / QBN, NROW / QBM), 256, QSMEM_BYTES>>>(
            l, bqkv + (size_t)l * 3 * DD);
        attn_tc_kernel<<<dim3(TT / 128, HH, BB), 128>>>();
        wout_ln_kernel<<<NROW / WBM, 256, WSMEM_BYTES>>>(
            l, bout + (size_t)l * DD, ln_g + (size_t)l * DD, ln_b + (size_t)l * DD);
    }

    head_kernel<<<24, 32>>>(Wo, bo, out);
}

// round 8
// speedup vs baseline: 6.0901x; 1.2010x over previous
#include <cuda_runtime.h>
#include <cuda_fp16.h>
#include <math.h>

// Problem constants
#define BB 8
#define TT 1024
#define IN_DIM 16
#define DD 256
#define HH 8
#define DK 32
#define LL 4
#define NROW (BB*TT)
#define LN_EPS 1e-5f

// -------- scratch (device globals) --------
__device__ float  g_h[NROW*DD];          // fp32 residual stream
__device__ float  g_h32[NROW*DD];        // tf32-rounded copy (GEMM A input)
__device__ __half g_qkvh[NROW*3*DD];     // fp16 qkv (same mantissa as tf32)
__device__ float  g_attn[NROW*DD];       // tf32-rounded attention out
__device__ float  g_wqkv32[LL*DD*3*DD];  // tf32-rounded weights
__device__ float  g_wout32[LL*DD*DD];

// -------- helpers --------
__device__ __forceinline__ unsigned f2tf32(float x) {
    unsigned r;
    asm("cvt.rna.tf32.f32 %0, %1;" : "=r"(r) : "f"(x));
    return r;
}
__device__ __forceinline__ void mma8(float* d, const unsigned* a, unsigned b0, unsigned b1) {
    asm volatile(
        "mma.sync.aligned.m16n8k8.row.col.f32.tf32.tf32.f32 "
        "{%0,%1,%2,%3}, {%4,%5,%6,%7}, {%8,%9}, {%0,%1,%2,%3};\n"
        : "+f"(d[0]), "+f"(d[1]), "+f"(d[2]), "+f"(d[3])
        : "r"(a[0]), "r"(a[1]), "r"(a[2]), "r"(a[3]), "r"(b0), "r"(b1));
}
// fp16 m16n8k16 with fp32 accumulate
__device__ __forceinline__ void mma16h(float* d, const unsigned* a, unsigned b0, unsigned b1) {
    asm volatile(
        "mma.sync.aligned.m16n8k16.row.col.f32.f16.f16.f32 "
        "{%0,%1,%2,%3}, {%4,%5,%6,%7}, {%8,%9}, {%0,%1,%2,%3};\n"
        : "+f"(d[0]), "+f"(d[1]), "+f"(d[2]), "+f"(d[3])
        : "r"(a[0]), "r"(a[1]), "r"(a[2]), "r"(a[3]), "r"(b0), "r"(b1));
}
__device__ __forceinline__ unsigned pkh2(float lo, float hi) {
    __half2 h = __floats2half2_rn(lo, hi);
    return *reinterpret_cast<unsigned*>(&h);
}
__device__ __forceinline__ unsigned prmt(unsigned a, unsigned b, unsigned sel) {
    unsigned r;
    asm("prmt.b32 %0, %1, %2, %3;" : "=r"(r) : "r"(a), "r"(b), "r"(sel));
    return r;
}
__device__ __forceinline__ void cp16(void* smem, const void* g) {
    unsigned a = (unsigned)__cvta_generic_to_shared(smem);
    asm volatile("cp.async.cg.shared.global [%0], [%1], 16;\n" :: "r"(a), "l"(g));
}
__device__ __forceinline__ void cp_commit() { asm volatile("cp.async.commit_group;\n"); }
template<int N> __device__ __forceinline__ void cp_wait() {
    asm volatile("cp.async.wait_group %0;\n" :: "n"(N));
}
__device__ __forceinline__ unsigned fbits(float x) { return __float_as_uint(x); }

// ============================================================
// 0. Weight conversion to tf32 (once per launch)
// ============================================================
__global__ void convw_kernel(const float* __restrict__ Wqkv,
                             const float* __restrict__ Wout) {
    int i = blockIdx.x * 256 + threadIdx.x;
    if (i < LL * DD * 3 * DD) g_wqkv32[i] = __uint_as_float(f2tf32(Wqkv[i]));
    if (i < LL * DD * DD)     g_wout32[i] = __uint_as_float(f2tf32(Wout[i]));
}

// ============================================================
// 1. Projection: h = x @ Wp + bp + pos  (fp32 + tf32 copy)
// ============================================================
__global__ void proj_kernel(const float* __restrict__ x,
                            const float* __restrict__ Wp,
                            const float* __restrict__ bp,
                            const float* __restrict__ pos) {
    int idx = blockIdx.x * blockDim.x + threadIdx.x;
    if (idx >= NROW * DD) return;
    int row = idx / DD;
    int col = idx - row * DD;
    int t = row & (TT - 1);
    const float* xr = x + row * IN_DIM;
    float s = bp[col] + pos[t * DD + col];
#pragma unroll
    for (int i = 0; i < IN_DIM; i++)
        s = fmaf(xr[i], Wp[i * DD + col], s);
    g_h[idx] = s;
    g_h32[idx] = __uint_as_float(f2tf32(s));
}

// ============================================================
// 2. QKV GEMM: g_qkvh = half(g_h32 @ Wqkv32[l] + bqkv[l])
//    Block 128x128, 8 warps (2m x 4n), warp 64x32.
//    4-stage cp.async, K staged 16. Conflict-free strides 20/136.
// ============================================================
#define QBM 128
#define QBN 128
#define QGK 16
#define QAS_STRIDE 20
#define QBS_STRIDE 136
#define QAS_WORDS (4*QBM*QAS_STRIDE)
#define QBS_WORDS (4*QGK*QBS_STRIDE)
#define QSMEM_BYTES ((QAS_WORDS+QBS_WORDS)*4)

extern __shared__ float dynsmem[];

__global__ __launch_bounds__(256, 2)
void qkv_gemm_kernel(int layer, const float* __restrict__ bias) {
    float* As = dynsmem;                 // [4][128][20]
    float* Bs = dynsmem + QAS_WORDS;     // [4][16][136]
    const float* __restrict__ A = g_h32;
    const float* __restrict__ Bmat = g_wqkv32 + (size_t)layer * DD * 3 * DD;
    const int N = 3 * DD;

    const int tid  = threadIdx.x;
    const int lane = tid & 31;
    const int g    = lane >> 2;
    const int q    = lane & 3;
    const int warp = tid >> 5;
    const int wm   = (warp & 1) * 64;
    const int wn   = (warp >> 1) * 32;
    const int bm   = blockIdx.y * QBM;
    const int bn   = blockIdx.x * QBN;

    auto issue = [&](int s) {
        int k0 = s * QGK;
        float* Asb = As + (s & 3) * QBM * QAS_STRIDE;
        float* Bsb = Bs + (s & 3) * QGK * QBS_STRIDE;
#pragma unroll
        for (int p = 0; p < 2; p++) {
            int c = tid + p * 256;
            int r = c >> 2, cc = (c & 3) * 4;
            cp16(&Asb[r * QAS_STRIDE + cc], &A[(size_t)(bm + r) * DD + k0 + cc]);
        }
#pragma unroll
        for (int p = 0; p < 2; p++) {
            int c = tid + p * 256;
            int r = c >> 5, cc = (c & 31) * 4;
            cp16(&Bsb[r * QBS_STRIDE + cc], &Bmat[(size_t)(k0 + r) * N + bn + cc]);
        }
    };

    float acc[4][4][4];
#pragma unroll
    for (int mc = 0; mc < 4; mc++)
#pragma unroll
        for (int nc = 0; nc < 4; nc++)
#pragma unroll
            for (int i = 0; i < 4; i++) acc[mc][nc][i] = 0.0f;

    issue(0); cp_commit();
    issue(1); cp_commit();
    issue(2); cp_commit();

    const int NS = DD / QGK;   // 16
    for (int s = 0; s < NS; s++) {
        cp_wait<2>();
        __syncthreads();
        if (s + 3 < NS) issue(s + 3);
        cp_commit();

        const float* Asb = As + (s & 3) * QBM * QAS_STRIDE;
        const float* Bsb = Bs + (s & 3) * QGK * QBS_STRIDE;
#pragma unroll
        for (int kk = 0; kk < 2; kk++) {
            int kb = kk * 8;
            unsigned af[4][4], bf[4][2];
#pragma unroll
            for (int mc = 0; mc < 4; mc++) {
                int r = wm + mc * 16 + g;
                af[mc][0] = fbits(Asb[r * QAS_STRIDE + kb + q]);
                af[mc][1] = fbits(Asb[(r + 8) * QAS_STRIDE + kb + q]);
                af[mc][2] = fbits(Asb[r * QAS_STRIDE + kb + q + 4]);
                af[mc][3] = fbits(Asb[(r + 8) * QAS_STRIDE + kb + q + 4]);
            }
#pragma unroll
            for (int nc = 0; nc < 4; nc++) {
                int cc = wn + nc * 8 + g;
                bf[nc][0] = fbits(Bsb[(kb + q) * QBS_STRIDE + cc]);
                bf[nc][1] = fbits(Bsb[(kb + q + 4) * QBS_STRIDE + cc]);
            }
#pragma unroll
            for (int mc = 0; mc < 4; mc++)
#pragma unroll
                for (int nc = 0; nc < 4; nc++)
                    mma8(acc[mc][nc], af[mc], bf[nc][0], bf[nc][1]);
        }
    }

    // epilogue: + bias, pack to fp16
    unsigned* qkw = reinterpret_cast<unsigned*>(g_qkvh);
#pragma unroll
    for (int mc = 0; mc < 4; mc++) {
#pragma unroll
        for (int nc = 0; nc < 4; nc++) {
            int row = bm + wm + mc * 16 + g;
            int col = bn + wn + nc * 8 + 2 * q;
            float2 bi = *(const float2*)&bias[col];
            qkw[(size_t)row * (N/2) + col/2] =
                pkh2(acc[mc][nc][0] + bi.x, acc[mc][nc][1] + bi.y);
            qkw[(size_t)(row + 8) * (N/2) + col/2] =
                pkh2(acc[mc][nc][2] + bi.x, acc[mc][nc][3] + bi.y);
        }
    }
}

// ============================================================
// 3. Flash attention, all-fp16 MMA (m16n8k16, fp32 accum).
//    Running-max online softmax (bounded: p <= 1, fp16-safe).
//    l kept as per-thread partial (rescaled on max update),
//    quad-reduced ONCE at the end.
//    P C-frag layout == fp16 A-frag layout -> pack only, no shfl.
// ============================================================
__global__ __launch_bounds__(128, 4)
void attn_tc_kernel() {
    __shared__ unsigned Khs[2][32][20];   // [key][dim half2-word]
    __shared__ unsigned Vhs[2][16][40];   // [keypair][dim]

    const int tid  = threadIdx.x;
    const int lane = tid & 31;
    const int g    = lane >> 2;
    const int q    = lane & 3;
    const int warp = tid >> 5;
    const int h    = blockIdx.y;
    const int b    = blockIdx.z;
    const int qrow0 = blockIdx.x * 128 + warp * 32;

    const float qs = 0.17677669529663687f * 1.4426950408889634f; // scale*log2e
    const int RW = 3 * DD;
    const int RWW = RW / 2;

    const __half* kg = g_qkvh + (size_t)b * TT * RW + DD + h * DK;
    const __half* vg = g_qkvh + (size_t)b * TT * RW + 2 * DD + h * DK;
    const unsigned* qw = reinterpret_cast<const unsigned*>(
        g_qkvh + (size_t)(b * TT + qrow0) * RW + h * DK);

    const int kkey = tid >> 2;            // 0..31
    const int kwg  = (tid & 3) * 4;       // word offset 0,4,8,12
    const int vj  = tid >> 3;             // 0..15
    const int vdg = (tid & 7) * 4;        // dims vdg..vdg+3

    // prologue tile 0
    cp16(&Khs[0][kkey][kwg], kg + (size_t)kkey * RW + kwg * 2);
    cp_commit();
    {
        uint2 wa = *(const uint2*)(vg + (size_t)(2 * vj) * RW + vdg);
        uint2 wb = *(const uint2*)(vg + (size_t)(2 * vj + 1) * RW + vdg);
        uint4 p;
        p.x = prmt(wa.x, wb.x, 0x5410); p.y = prmt(wa.x, wb.x, 0x7632);
        p.z = prmt(wa.y, wb.y, 0x5410); p.w = prmt(wa.y, wb.y, 0x7632);
        *(uint4*)&Vhs[0][vj][vdg] = p;
    }

    // Q A-fragments (fp16 words straight from memory)
    unsigned qa[2][2][4];
#pragma unroll
    for (int mc = 0; mc < 2; mc++)
#pragma unroll
        for (int kc = 0; kc < 2; kc++) {
            int r = mc * 16 + g;
            qa[mc][kc][0] = qw[(size_t)r * RWW + kc * 8 + q];
            qa[mc][kc][1] = qw[(size_t)(r + 8) * RWW + kc * 8 + q];
            qa[mc][kc][2] = qw[(size_t)r * RWW + kc * 8 + q + 4];
            qa[mc][kc][3] = qw[(size_t)(r + 8) * RWW + kc * 8 + q + 4];
        }

    float oacc[2][4][4];
    float mrow[2][2], lp[2][2];
#pragma unroll
    for (int mc = 0; mc < 2; mc++) {
        mrow[mc][0] = -1e30f; mrow[mc][1] = -1e30f;
        lp[mc][0] = 0.0f; lp[mc][1] = 0.0f;
#pragma unroll
        for (int nc = 0; nc < 4; nc++)
#pragma unroll
            for (int i = 0; i < 4; i++) oacc[mc][nc][i] = 0.0f;
    }

    const int NT = TT / 32;
    for (int t = 0; t < NT; t++) {
        int buf = t & 1;
        int nb  = buf ^ 1;
        uint2 wa, wb;
        if (t + 1 < NT) {
            int k0 = (t + 1) * 32;
            cp16(&Khs[nb][kkey][kwg], kg + (size_t)(k0 + kkey) * RW + kwg * 2);
            cp_commit();
            wa = *(const uint2*)(vg + (size_t)(k0 + 2 * vj) * RW + vdg);
            wb = *(const uint2*)(vg + (size_t)(k0 + 2 * vj + 1) * RW + vdg);
            cp_wait<1>();
        } else {
            cp_wait<0>();
        }
        __syncthreads();

        // ---- S = Q K^T (fp16 k16) ----
        float sf[2][4][4];
#pragma unroll
        for (int mc = 0; mc < 2; mc++)
#pragma unroll
            for (int nc = 0; nc < 4; nc++)
#pragma unroll
                for (int i = 0; i < 4; i++) sf[mc][nc][i] = 0.0f;

#pragma unroll
        for (int nc = 0; nc < 4; nc++) {
#pragma unroll
            for (int kc = 0; kc < 2; kc++) {
                unsigned b0 = Khs[buf][nc * 8 + g][kc * 8 + q];
                unsigned b1 = Khs[buf][nc * 8 + g][kc * 8 + q + 4];
                mma16h(sf[0][nc], qa[0][kc], b0, b1);
                mma16h(sf[1][nc], qa[1][kc], b0, b1);
            }
        }

        // ---- online softmax w/ running max (p <= 1 guaranteed) ----
#pragma unroll
        for (int mc = 0; mc < 2; mc++) {
            float mx0 = sf[mc][0][0], mx1 = sf[mc][0][2];
#pragma unroll
            for (int nc = 0; nc < 4; nc++) {
                mx0 = fmaxf(mx0, fmaxf(sf[mc][nc][0], sf[mc][nc][1]));
                mx1 = fmaxf(mx1, fmaxf(sf[mc][nc][2], sf[mc][nc][3]));
            }
            mx0 = fmaxf(mx0, __shfl_xor_sync(0xffffffffu, mx0, 1));
            mx0 = fmaxf(mx0, __shfl_xor_sync(0xffffffffu, mx0, 2));
            mx1 = fmaxf(mx1, __shfl_xor_sync(0xffffffffu, mx1, 1));
            mx1 = fmaxf(mx1, __shfl_xor_sync(0xffffffffu, mx1, 2));
            float nm0 = fmaxf(mrow[mc][0], mx0);
            float nm1 = fmaxf(mrow[mc][1], mx1);
            float f0 = exp2f((mrow[mc][0] - nm0) * qs);
            float f1 = exp2f((mrow[mc][1] - nm1) * qs);
            mrow[mc][0] = nm0; mrow[mc][1] = nm1;
            float c0 = nm0 * qs, c1 = nm1 * qs;
            float s0 = 0.0f, s1 = 0.0f;
#pragma unroll
            for (int nc = 0; nc < 4; nc++) {
                sf[mc][nc][0] = exp2f(fmaf(sf[mc][nc][0], qs, -c0));
                sf[mc][nc][1] = exp2f(fmaf(sf[mc][nc][1], qs, -c0));
                sf[mc][nc][2] = exp2f(fmaf(sf[mc][nc][2], qs, -c1));
                sf[mc][nc][3] = exp2f(fmaf(sf[mc][nc][3], qs, -c1));
                s0 += sf[mc][nc][0] + sf[mc][nc][1];
                s1 += sf[mc][nc][2] + sf[mc][nc][3];
            }
            // per-thread partial l (deferred quad reduction)
            lp[mc][0] = lp[mc][0] * f0 + s0;
            lp[mc][1] = lp[mc][1] * f1 + s1;
#pragma unroll
            for (int nc = 0; nc < 4; nc++) {
                oacc[mc][nc][0] *= f0; oacc[mc][nc][1] *= f0;
                oacc[mc][nc][2] *= f1; oacc[mc][nc][3] *= f1;
            }
        }

        // ---- O += P V  (fp16; P pack = C-frag identity) ----
#pragma unroll
        for (int kk = 0; kk < 2; kk++) {
            unsigned pa0[4], pa1[4];
            pa0[0] = pkh2(sf[0][2*kk][0],   sf[0][2*kk][1]);
            pa0[1] = pkh2(sf[0][2*kk][2],   sf[0][2*kk][3]);
            pa0[2] = pkh2(sf[0][2*kk+1][0], sf[0][2*kk+1][1]);
            pa0[3] = pkh2(sf[0][2*kk+1][2], sf[0][2*kk+1][3]);
            pa1[0] = pkh2(sf[1][2*kk][0],   sf[1][2*kk][1]);
            pa1[1] = pkh2(sf[1][2*kk][2],   sf[1][2*kk][3]);
            pa1[2] = pkh2(sf[1][2*kk+1][0], sf[1][2*kk+1][1]);
            pa1[3] = pkh2(sf[1][2*kk+1][2], sf[1][2*kk+1][3]);
#pragma unroll
            for (int dn = 0; dn < 4; dn++) {
                unsigned b0 = Vhs[buf][8*kk + q][dn * 8 + g];
                unsigned b1 = Vhs[buf][8*kk + q + 4][dn * 8 + g];
                mma16h(oacc[0][dn], pa0, b0, b1);
                mma16h(oacc[1][dn], pa1, b0, b1);
            }
        }

        // commit prefetched V tile
        if (t + 1 < NT) {
            uint4 p;
            p.x = prmt(wa.x, wb.x, 0x5410); p.y = prmt(wa.x, wb.x, 0x7632);
            p.z = prmt(wa.y, wb.y, 0x5410); p.w = prmt(wa.y, wb.y, 0x7632);
            *(uint4*)&Vhs[nb][vj][vdg] = p;
        }
        __syncthreads();
    }

    // ---- deferred l reduction (once), normalize, store tf32 ----
#pragma unroll
    for (int mc = 0; mc < 2; mc++) {
        float l0 = lp[mc][0], l1 = lp[mc][1];
        l0 += __shfl_xor_sync(0xffffffffu, l0, 1);
        l0 += __shfl_xor_sync(0xffffffffu, l0, 2);
        l1 += __shfl_xor_sync(0xffffffffu, l1, 1);
        l1 += __shfl_xor_sync(0xffffffffu, l1, 2);
        float inv0 = 1.0f / l0;
        float inv1 = 1.0f / l1;
        int r0 = b * TT + qrow0 + mc * 16 + g;
#pragma unroll
        for (int dn = 0; dn < 4; dn++) {
            int col = h * DK + dn * 8 + 2 * q;
            float2 o0, o1;
            o0.x = __uint_as_float(f2tf32(oacc[mc][dn][0] * inv0));
            o0.y = __uint_as_float(f2tf32(oacc[mc][dn][1] * inv0));
            o1.x = __uint_as_float(f2tf32(oacc[mc][dn][2] * inv1));
            o1.y = __uint_as_float(f2tf32(oacc[mc][dn][3] * inv1));
            *(float2*)&g_attn[(size_t)r0 * DD + col]       = o0;
            *(float2*)&g_attn[(size_t)(r0 + 8) * DD + col] = o1;
        }
    }
}

// ============================================================
// 4. Wout GEMM + bias + residual + LayerNorm, fused.
// ============================================================
#define WBM 64
#define WBN 256
#define WGK 16
#define WAS_STRIDE 20
#define WBS_STRIDE 264
#define WAS_WORDS (4*WBM*WAS_STRIDE)
#define WBS_WORDS (4*WGK*WBS_STRIDE)
#define WSMEM_BYTES ((WAS_WORDS+WBS_WORDS+512)*4)

__global__ __launch_bounds__(256, 2)
void wout_ln_kernel(int layer, const float* __restrict__ bias,
                    const float* __restrict__ gamma,
                    const float* __restrict__ beta) {
    float* As   = dynsmem;
    float* Bs   = dynsmem + WAS_WORDS;
    float* redS = dynsmem + WAS_WORDS + WBS_WORDS;      // [64][4]
    float* redQ = redS + 256;                            // [64][4]
    const float* __restrict__ A = g_attn;
    const float* __restrict__ Bmat = g_wout32 + (size_t)layer * DD * DD;

    const int tid  = threadIdx.x;
    const int lane = tid & 31;
    const int g    = lane >> 2;
    const int q    = lane & 3;
    const int warp = tid >> 5;
    const int wm   = (warp & 1) * 32;
    const int wn   = (warp >> 1) * 64;
    const int bm   = blockIdx.x * WBM;

    auto issue = [&](int s) {
        int k0 = s * WGK;
        float* Asb = As + (s & 3) * WBM * WAS_STRIDE;
        float* Bsb = Bs + (s & 3) * WGK * WBS_STRIDE;
        {
            int r = tid >> 2, cc = (tid & 3) * 4;
            cp16(&Asb[r * WAS_STRIDE + cc], &A[(size_t)(bm + r) * DD + k0 + cc]);
        }
#pragma unroll
        for (int p = 0; p < 4; p++) {
            int c = tid + p * 256;
            int r = c >> 6, cc = (c & 63) * 4;
            cp16(&Bsb[r * WBS_STRIDE + cc], &Bmat[(size_t)(k0 + r) * DD + cc]);
        }
    };

    float acc[2][8][4];
#pragma unroll
    for (int mc = 0; mc < 2; mc++)
#pragma unroll
        for (int nc = 0; nc < 8; nc++)
#pragma unroll
            for (int i = 0; i < 4; i++) acc[mc][nc][i] = 0.0f;

    issue(0); cp_commit();
    issue(1); cp_commit();
    issue(2); cp_commit();

    const int NS = DD / WGK;    // 16
    for (int s = 0; s < NS; s++) {
        cp_wait<2>();
        __syncthreads();
        if (s + 3 < NS) issue(s + 3);
        cp_commit();

        const float* Asb = As + (s & 3) * WBM * WAS_STRIDE;
        const float* Bsb = Bs + (s & 3) * WGK * WBS_STRIDE;
#pragma unroll
        for (int kk = 0; kk < 2; kk++) {
            int kb = kk * 8;
            unsigned af[2][4], bf[8][2];
#pragma unroll
            for (int mc = 0; mc < 2; mc++) {
                int r = wm + mc * 16 + g;
                af[mc][0] = fbits(Asb[r * WAS_STRIDE + kb + q]);
                af[mc][1] = fbits(Asb[(r + 8) * WAS_STRIDE + kb + q]);
                af[mc][2] = fbits(Asb[r * WAS_STRIDE + kb + q + 4]);
                af[mc][3] = fbits(Asb[(r + 8) * WAS_STRIDE + kb + q + 4]);
            }
#pragma unroll
            for (int nc = 0; nc < 8; nc++) {
                int cc = wn + nc * 8 + g;
                bf[nc][0] = fbits(Bsb[(kb + q) * WBS_STRIDE + cc]);
                bf[nc][1] = fbits(Bsb[(kb + q + 4) * WBS_STRIDE + cc]);
            }
#pragma unroll
            for (int mc = 0; mc < 2; mc++)
#pragma unroll
                for (int nc = 0; nc < 8; nc++)
                    mma8(acc[mc][nc], af[mc], bf[nc][0], bf[nc][1]);
        }
    }
    __syncthreads();

    // epilogue part 1: + bias + residual (fp32)
#pragma unroll
    for (int mc = 0; mc < 2; mc++) {
        int rlo = bm + wm + mc * 16 + g;
#pragma unroll
        for (int nc = 0; nc < 8; nc++) {
            int col = wn + nc * 8 + 2 * q;
            float2 bi = *(const float2*)&bias[col];
            float2 h0 = *(const float2*)&g_h[(size_t)rlo * DD + col];
            float2 h1 = *(const float2*)&g_h[(size_t)(rlo + 8) * DD + col];
            acc[mc][nc][0] += bi.x + h0.x;
            acc[mc][nc][1] += bi.y + h0.y;
            acc[mc][nc][2] += bi.x + h1.x;
            acc[mc][nc][3] += bi.y + h1.y;
        }
    }

    // epilogue part 2: row stats
    const int ng = warp >> 1;
#pragma unroll
    for (int mc = 0; mc < 2; mc++) {
        float slo = 0.f, qlo = 0.f, shi = 0.f, qhi = 0.f;
#pragma unroll
        for (int nc = 0; nc < 8; nc++) {
            slo += acc[mc][nc][0] + acc[mc][nc][1];
            qlo += acc[mc][nc][0] * acc[mc][nc][0] + acc[mc][nc][1] * acc[mc][nc][1];
            shi += acc[mc][nc][2] + acc[mc][nc][3];
            qhi += acc[mc][nc][2] * acc[mc][nc][2] + acc[mc][nc][3] * acc[mc][nc][3];
        }
        slo += __shfl_xor_sync(0xffffffffu, slo, 1); slo += __shfl_xor_sync(0xffffffffu, slo, 2);
        qlo += __shfl_xor_sync(0xffffffffu, qlo, 1); qlo += __shfl_xor_sync(0xffffffffu, qlo, 2);
        shi += __shfl_xor_sync(0xffffffffu, shi, 1); shi += __shfl_xor_sync(0xffffffffu, shi, 2);
        qhi += __shfl_xor_sync(0xffffffffu, qhi, 1); qhi += __shfl_xor_sync(0xffffffffu, qhi, 2);
        if (q == 0) {
            int rlo = wm + mc * 16 + g;
            redS[rlo * 4 + ng] = slo;  redQ[rlo * 4 + ng] = qlo;
            redS[(rlo + 8) * 4 + ng] = shi;  redQ[(rlo + 8) * 4 + ng] = qhi;
        }
    }
    __syncthreads();

    // epilogue part 3: normalize + store (fp32 + tf32)
#pragma unroll
    for (int mc = 0; mc < 2; mc++) {
        int rl = wm + mc * 16 + g;
        float slo = redS[rl*4] + redS[rl*4+1] + redS[rl*4+2] + redS[rl*4+3];
        float qlo = redQ[rl*4] + redQ[rl*4+1] + redQ[rl*4+2] + redQ[rl*4+3];
        float shi = redS[(rl+8)*4] + redS[(rl+8)*4+1] + redS[(rl+8)*4+2] + redS[(rl+8)*4+3];
        float qhi = redQ[(rl+8)*4] + redQ[(rl+8)*4+1] + redQ[(rl+8)*4+2] + redQ[(rl+8)*4+3];
        float mulo = slo * (1.0f / DD);
        float muhi = shi * (1.0f / DD);
        float rslo = rsqrtf(qlo * (1.0f / DD) - mulo * mulo + LN_EPS);
        float rshi = rsqrtf(qhi * (1.0f / DD) - muhi * muhi + LN_EPS);
        int rowlo = bm + rl;
#pragma unroll
        for (int nc = 0; nc < 8; nc++) {
            int col = wn + nc * 8 + 2 * q;
            float2 ga = *(const float2*)&gamma[col];
            float2 be = *(const float2*)&beta[col];
            float v0 = (acc[mc][nc][0] - mulo) * rslo * ga.x + be.x;
            float v1 = (acc[mc][nc][1] - mulo) * rslo * ga.y + be.y;
            float v2 = (acc[mc][nc][2] - muhi) * rshi * ga.x + be.x;
            float v3 = (acc[mc][nc][3] - muhi) * rshi * ga.y + be.y;
            *(float2*)&g_h[(size_t)rowlo * DD + col]       = make_float2(v0, v1);
            *(float2*)&g_h[(size_t)(rowlo + 8) * DD + col] = make_float2(v2, v3);
            float2 t0, t1;
            t0.x = __uint_as_float(f2tf32(v0)); t0.y = __uint_as_float(f2tf32(v1));
            t1.x = __uint_as_float(f2tf32(v2)); t1.y = __uint_as_float(f2tf32(v3));
            *(float2*)&g_h32[(size_t)rowlo * DD + col]       = t0;
            *(float2*)&g_h32[(size_t)(rowlo + 8) * DD + col] = t1;
        }
    }
}

// ============================================================
// 5. Head
// ============================================================
__global__ void head_kernel(const float* __restrict__ Wo,
                            const float* __restrict__ bo,
                            float* __restrict__ out) {
    int b = blockIdx.x / 3;
    int j = blockIdx.x - b * 3;
    int lane = threadIdx.x;
    const float* hr = g_h + (size_t)(b * TT + (TT - 1)) * DD;
    float s = 0.0f;
    for (int d = lane; d < DD; d += 32)
        s = fmaf(hr[d], Wo[d * 3 + j], s);
#pragma unroll
    for (int o = 16; o > 0; o >>= 1)
        s += __shfl_xor_sync(0xffffffffu, s, o);
    if (lane == 0) out[b * 3 + j] = s + bo[j];
}

// ============================================================
// launch
// ============================================================
extern "C" void kernel_launch(void* const* d_in, const int* in_sizes, int n_in,
                              void* d_out, int out_size) {
    const float* x    = (const float*)d_in[0];
    const float* Wp   = (const float*)d_in[1];
    const float* bp   = (const float*)d_in[2];
    const float* pos  = (const float*)d_in[3];
    const float* Wqkv = (const float*)d_in[4];
    const float* bqkv = (const float*)d_in[5];
    const float* Wout = (const float*)d_in[6];
    const float* bout = (const float*)d_in[7];
    const float* ln_g = (const float*)d_in[8];
    const float* ln_b = (const float*)d_in[9];
    const float* Wo   = (const float*)d_in[10];
    const float* bo   = (const float*)d_in[11];
    float* out = (float*)d_out;

    cudaFuncSetAttribute(qkv_gemm_kernel, cudaFuncAttributeMaxDynamicSharedMemorySize, QSMEM_BYTES);
    cudaFuncSetAttribute(wout_ln_kernel,  cudaFuncAttributeMaxDynamicSharedMemorySize, WSMEM_BYTES);

    convw_kernel<<<(LL * DD * 3 * DD + 255) / 256, 256>>>(Wqkv, Wout);
    proj_kernel<<<(NROW * DD + 255) / 256, 256>>>(x, Wp, bp, pos);

    for (int l = 0; l < LL; l++) {
        qkv_gemm_kernel<<<dim3((3 * DD) / QBN, NROW / QBM), 256, QSMEM_BYTES>>>(
            l, bqkv + (size_t)l * 3 * DD);
        attn_tc_kernel<<<dim3(TT / 128, HH, BB), 128>>>();
        wout_ln_kernel<<<NROW / WBM, 256, WSMEM_BYTES>>>(
            l, bout + (size_t)l * DD, ln_g + (size_t)l * DD, ln_b + (size_t)l * DD);
    }

    head_kernel<<<24, 32>>>(Wo, bo, out);
}

// round 9
// speedup vs baseline: 6.9619x; 1.1432x over previous
#include <cuda_runtime.h>
#include <cuda_fp16.h>
#include <math.h>

// Problem constants
#define BB 8
#define TT 1024
#define IN_DIM 16
#define DD 256
#define HH 8
#define DK 32
#define LL 4
#define NROW (BB*TT)
#define LN_EPS 1e-5f

// -------- scratch (device globals) --------
__device__ float  g_h[NROW*DD];           // fp32 residual stream
__device__ __half g_h16[NROW*DD];         // fp16 hidden (GEMM A input)
__device__ __half g_qkvh[NROW*3*DD];      // fp16 qkv
__device__ __half g_attnh[NROW*DD];       // fp16 attention out
__device__ __half g_wqkv16[LL*3*DD*DD];   // fp16 Wqkv TRANSPOSED [l][n][k]
__device__ __half g_wout16[LL*DD*DD];     // fp16 Wout TRANSPOSED [l][n][k]

// -------- helpers --------
// fp16 m16n8k16 with fp32 accumulate (mantissa == tf32)
__device__ __forceinline__ void mma16h(float* d, const unsigned* a, unsigned b0, unsigned b1) {
    asm volatile(
        "mma.sync.aligned.m16n8k16.row.col.f32.f16.f16.f32 "
        "{%0,%1,%2,%3}, {%4,%5,%6,%7}, {%8,%9}, {%0,%1,%2,%3};\n"
        : "+f"(d[0]), "+f"(d[1]), "+f"(d[2]), "+f"(d[3])
        : "r"(a[0]), "r"(a[1]), "r"(a[2]), "r"(a[3]), "r"(b0), "r"(b1));
}
__device__ __forceinline__ unsigned pkh2(float lo, float hi) {
    __half2 h = __floats2half2_rn(lo, hi);
    return *reinterpret_cast<unsigned*>(&h);
}
__device__ __forceinline__ unsigned prmt(unsigned a, unsigned b, unsigned sel) {
    unsigned r;
    asm("prmt.b32 %0, %1, %2, %3;" : "=r"(r) : "r"(a), "r"(b), "r"(sel));
    return r;
}
__device__ __forceinline__ void cp16(void* smem, const void* g) {
    unsigned a = (unsigned)__cvta_generic_to_shared(smem);
    asm volatile("cp.async.cg.shared.global [%0], [%1], 16;\n" :: "r"(a), "l"(g));
}
__device__ __forceinline__ void cp_commit() { asm volatile("cp.async.commit_group;\n"); }
template<int N> __device__ __forceinline__ void cp_wait() {
    asm volatile("cp.async.wait_group %0;\n" :: "n"(N));
}

// ============================================================
// 0. Weight transpose + fp16 convert (once per launch).
//    src [l][K=DD][N] row-major -> dst [l][N][K] fp16 (k-major).
// ============================================================
__global__ void transp_kernel(const float* __restrict__ src,
                              __half* __restrict__ dst, int N) {
    __shared__ float tile[32][33];
    int k0 = blockIdx.x * 32, n0 = blockIdx.y * 32;
    const float* s = src + (size_t)blockIdx.z * DD * N;
    __half* d = dst + (size_t)blockIdx.z * DD * N;
    for (int i = threadIdx.y; i < 32; i += 8)
        tile[i][threadIdx.x] = s[(size_t)(k0 + i) * N + n0 + threadIdx.x];
    __syncthreads();
    for (int i = threadIdx.y; i < 32; i += 8)
        d[(size_t)(n0 + i) * DD + k0 + threadIdx.x] = __float2half_rn(tile[threadIdx.x][i]);
}

// ============================================================
// 1. Projection: h = x @ Wp + bp + pos  (fp32 + fp16 copy)
// ============================================================
__global__ void proj_kernel(const float* __restrict__ x,
                            const float* __restrict__ Wp,
                            const float* __restrict__ bp,
                            const float* __restrict__ pos) {
    int idx = blockIdx.x * blockDim.x + threadIdx.x;
    if (idx >= NROW * DD) return;
    int row = idx / DD;
    int col = idx - row * DD;
    int t = row & (TT - 1);
    const float* xr = x + row * IN_DIM;
    float s = bp[col] + pos[t * DD + col];
#pragma unroll
    for (int i = 0; i < IN_DIM; i++)
        s = fmaf(xr[i], Wp[i * DD + col], s);
    g_h[idx] = s;
    g_h16[idx] = __float2half_rn(s);
}

// ============================================================
// 2. QKV GEMM (fp16 m16n8k16): g_qkvh = g_h16 @ W^T + bqkv
//    Block 128x128, 8 warps (2m x 4n), warp 64x32.
//    K staged 32/stage (16 words, stride 20 = conflict-free),
//    4-stage cp.async ring over 8 k-stages.
// ============================================================
#define QST_A 2560      // words per A stage (128*20)
#define QST_B 2560      // words per B stage (128*20)
#define QSMEM_BYTES ((4*(QST_A+QST_B))*4)

extern __shared__ float dynsmem[];

__global__ __launch_bounds__(256, 2)
void qkv_gemm_kernel(int layer, const float* __restrict__ bias) {
    unsigned* As = (unsigned*)dynsmem;          // [4][128][20]
    unsigned* Bs = As + 4 * QST_A;              // [4][128][20]
    const __half* __restrict__ A = g_h16;
    const __half* __restrict__ Bmat = g_wqkv16 + (size_t)layer * 3 * DD * DD; // [n][k]
    const int N = 3 * DD;

    const int tid  = threadIdx.x;
    const int lane = tid & 31;
    const int g    = lane >> 2;
    const int q    = lane & 3;
    const int warp = tid >> 5;
    const int wm   = (warp & 1) * 64;
    const int wn   = (warp >> 1) * 32;
    const int bm   = blockIdx.y * 128;
    const int bn   = blockIdx.x * 128;

    auto issue = [&](int s) {
        int k0 = s * 32;
        unsigned* Asb = As + (s & 3) * QST_A;
        unsigned* Bsb = Bs + (s & 3) * QST_B;
#pragma unroll
        for (int p = 0; p < 2; p++) {
            int c = tid + p * 256;
            int r = c >> 2, cw = (c & 3) * 4;
            cp16(&Asb[r * 20 + cw], A + (size_t)(bm + r) * DD + k0 + cw * 2);
        }
#pragma unroll
        for (int p = 0; p < 2; p++) {
            int c = tid + p * 256;
            int r = c >> 2, cw = (c & 3) * 4;
            cp16(&Bsb[r * 20 + cw], Bmat + (size_t)(bn + r) * DD + k0 + cw * 2);
        }
    };

    float acc[4][4][4];
#pragma unroll
    for (int mc = 0; mc < 4; mc++)
#pragma unroll
        for (int nc = 0; nc < 4; nc++)
#pragma unroll
            for (int i = 0; i < 4; i++) acc[mc][nc][i] = 0.0f;

    issue(0); cp_commit();
    issue(1); cp_commit();
    issue(2); cp_commit();

    const int NS = DD / 32;   // 8
    for (int s = 0; s < NS; s++) {
        cp_wait<2>();
        __syncthreads();
        if (s + 3 < NS) issue(s + 3);
        cp_commit();

        const unsigned* Asb = As + (s & 3) * QST_A;
        const unsigned* Bsb = Bs + (s & 3) * QST_B;
#pragma unroll
        for (int kc = 0; kc < 2; kc++) {
            int kb = kc * 8;
            unsigned af[4][4], bf[4][2];
#pragma unroll
            for (int mc = 0; mc < 4; mc++) {
                int r = wm + mc * 16 + g;
                af[mc][0] = Asb[r * 20 + kb + q];
                af[mc][1] = Asb[(r + 8) * 20 + kb + q];
                af[mc][2] = Asb[r * 20 + kb + q + 4];
                af[mc][3] = Asb[(r + 8) * 20 + kb + q + 4];
            }
#pragma unroll
            for (int nc = 0; nc < 4; nc++) {
                int cc = wn + nc * 8 + g;
                bf[nc][0] = Bsb[cc * 20 + kb + q];
                bf[nc][1] = Bsb[cc * 20 + kb + q + 4];
            }
#pragma unroll
            for (int mc = 0; mc < 4; mc++)
#pragma unroll
                for (int nc = 0; nc < 4; nc++)
                    mma16h(acc[mc][nc], af[mc], bf[nc][0], bf[nc][1]);
        }
    }

    // epilogue: + bias, pack to fp16
    unsigned* qkw = reinterpret_cast<unsigned*>(g_qkvh);
#pragma unroll
    for (int mc = 0; mc < 4; mc++) {
#pragma unroll
        for (int nc = 0; nc < 4; nc++) {
            int row = bm + wm + mc * 16 + g;
            int col = bn + wn + nc * 8 + 2 * q;
            float2 bi = *(const float2*)&bias[col];
            qkw[(size_t)row * (N/2) + col/2] =
                pkh2(acc[mc][nc][0] + bi.x, acc[mc][nc][1] + bi.y);
            qkw[(size_t)(row + 8) * (N/2) + col/2] =
                pkh2(acc[mc][nc][2] + bi.x, acc[mc][nc][3] + bi.y);
        }
    }
}

// ============================================================
// 3. Flash attention, all-fp16 MMA (unchanged from round 8
//    except: output stored fp16 to g_attnh).
// ============================================================
__global__ __launch_bounds__(128, 4)
void attn_tc_kernel() {
    __shared__ unsigned Khs[2][32][20];   // [key][dim half2-word]
    __shared__ unsigned Vhs[2][16][40];   // [keypair][dim]

    const int tid  = threadIdx.x;
    const int lane = tid & 31;
    const int g    = lane >> 2;
    const int q    = lane & 3;
    const int warp = tid >> 5;
    const int h    = blockIdx.y;
    const int b    = blockIdx.z;
    const int qrow0 = blockIdx.x * 128 + warp * 32;

    const float qs = 0.17677669529663687f * 1.4426950408889634f; // scale*log2e
    const int RW = 3 * DD;
    const int RWW = RW / 2;

    const __half* kg = g_qkvh + (size_t)b * TT * RW + DD + h * DK;
    const __half* vg = g_qkvh + (size_t)b * TT * RW + 2 * DD + h * DK;
    const unsigned* qw = reinterpret_cast<const unsigned*>(
        g_qkvh + (size_t)(b * TT + qrow0) * RW + h * DK);

    const int kkey = tid >> 2;            // 0..31
    const int kwg  = (tid & 3) * 4;       // word offset 0,4,8,12
    const int vj  = tid >> 3;             // 0..15
    const int vdg = (tid & 7) * 4;        // dims vdg..vdg+3

    // prologue tile 0
    cp16(&Khs[0][kkey][kwg], kg + (size_t)kkey * RW + kwg * 2);
    cp_commit();
    {
        uint2 wa = *(const uint2*)(vg + (size_t)(2 * vj) * RW + vdg);
        uint2 wb = *(const uint2*)(vg + (size_t)(2 * vj + 1) * RW + vdg);
        uint4 p;
        p.x = prmt(wa.x, wb.x, 0x5410); p.y = prmt(wa.x, wb.x, 0x7632);
        p.z = prmt(wa.y, wb.y, 0x5410); p.w = prmt(wa.y, wb.y, 0x7632);
        *(uint4*)&Vhs[0][vj][vdg] = p;
    }

    // Q A-fragments (fp16 words straight from memory)
    unsigned qa[2][2][4];
#pragma unroll
    for (int mc = 0; mc < 2; mc++)
#pragma unroll
        for (int kc = 0; kc < 2; kc++) {
            int r = mc * 16 + g;
            qa[mc][kc][0] = qw[(size_t)r * RWW + kc * 8 + q];
            qa[mc][kc][1] = qw[(size_t)(r + 8) * RWW + kc * 8 + q];
            qa[mc][kc][2] = qw[(size_t)r * RWW + kc * 8 + q + 4];
            qa[mc][kc][3] = qw[(size_t)(r + 8) * RWW + kc * 8 + q + 4];
        }

    float oacc[2][4][4];
    float mrow[2][2], lp[2][2];
#pragma unroll
    for (int mc = 0; mc < 2; mc++) {
        mrow[mc][0] = -1e30f; mrow[mc][1] = -1e30f;
        lp[mc][0] = 0.0f; lp[mc][1] = 0.0f;
#pragma unroll
        for (int nc = 0; nc < 4; nc++)
#pragma unroll
            for (int i = 0; i < 4; i++) oacc[mc][nc][i] = 0.0f;
    }

    const int NT = TT / 32;
    for (int t = 0; t < NT; t++) {
        int buf = t & 1;
        int nb  = buf ^ 1;
        uint2 wa, wb;
        if (t + 1 < NT) {
            int k0 = (t + 1) * 32;
            cp16(&Khs[nb][kkey][kwg], kg + (size_t)(k0 + kkey) * RW + kwg * 2);
            cp_commit();
            wa = *(const uint2*)(vg + (size_t)(k0 + 2 * vj) * RW + vdg);
            wb = *(const uint2*)(vg + (size_t)(k0 + 2 * vj + 1) * RW + vdg);
            cp_wait<1>();
        } else {
            cp_wait<0>();
        }
        __syncthreads();

        // ---- S = Q K^T (fp16 k16) ----
        float sf[2][4][4];
#pragma unroll
        for (int mc = 0; mc < 2; mc++)
#pragma unroll
            for (int nc = 0; nc < 4; nc++)
#pragma unroll
                for (int i = 0; i < 4; i++) sf[mc][nc][i] = 0.0f;

#pragma unroll
        for (int nc = 0; nc < 4; nc++) {
#pragma unroll
            for (int kc = 0; kc < 2; kc++) {
                unsigned b0 = Khs[buf][nc * 8 + g][kc * 8 + q];
                unsigned b1 = Khs[buf][nc * 8 + g][kc * 8 + q + 4];
                mma16h(sf[0][nc], qa[0][kc], b0, b1);
                mma16h(sf[1][nc], qa[1][kc], b0, b1);
            }
        }

        // ---- online softmax w/ running max (p <= 1 guaranteed) ----
#pragma unroll
        for (int mc = 0; mc < 2; mc++) {
            float mx0 = sf[mc][0][0], mx1 = sf[mc][0][2];
#pragma unroll
            for (int nc = 0; nc < 4; nc++) {
                mx0 = fmaxf(mx0, fmaxf(sf[mc][nc][0], sf[mc][nc][1]));
                mx1 = fmaxf(mx1, fmaxf(sf[mc][nc][2], sf[mc][nc][3]));
            }
            mx0 = fmaxf(mx0, __shfl_xor_sync(0xffffffffu, mx0, 1));
            mx0 = fmaxf(mx0, __shfl_xor_sync(0xffffffffu, mx0, 2));
            mx1 = fmaxf(mx1, __shfl_xor_sync(0xffffffffu, mx1, 1));
            mx1 = fmaxf(mx1, __shfl_xor_sync(0xffffffffu, mx1, 2));
            float nm0 = fmaxf(mrow[mc][0], mx0);
            float nm1 = fmaxf(mrow[mc][1], mx1);
            float f0 = exp2f((mrow[mc][0] - nm0) * qs);
            float f1 = exp2f((mrow[mc][1] - nm1) * qs);
            mrow[mc][0] = nm0; mrow[mc][1] = nm1;
            float c0 = nm0 * qs, c1 = nm1 * qs;
            float s0 = 0.0f, s1 = 0.0f;
#pragma unroll
            for (int nc = 0; nc < 4; nc++) {
                sf[mc][nc][0] = exp2f(fmaf(sf[mc][nc][0], qs, -c0));
                sf[mc][nc][1] = exp2f(fmaf(sf[mc][nc][1], qs, -c0));
                sf[mc][nc][2] = exp2f(fmaf(sf[mc][nc][2], qs, -c1));
                sf[mc][nc][3] = exp2f(fmaf(sf[mc][nc][3], qs, -c1));
                s0 += sf[mc][nc][0] + sf[mc][nc][1];
                s1 += sf[mc][nc][2] + sf[mc][nc][3];
            }
            lp[mc][0] = lp[mc][0] * f0 + s0;
            lp[mc][1] = lp[mc][1] * f1 + s1;
#pragma unroll
            for (int nc = 0; nc < 4; nc++) {
                oacc[mc][nc][0] *= f0; oacc[mc][nc][1] *= f0;
                oacc[mc][nc][2] *= f1; oacc[mc][nc][3] *= f1;
            }
        }

        // ---- O += P V  (fp16; P pack = C-frag identity) ----
#pragma unroll
        for (int kk = 0; kk < 2; kk++) {
            unsigned pa0[4], pa1[4];
            pa0[0] = pkh2(sf[0][2*kk][0],   sf[0][2*kk][1]);
            pa0[1] = pkh2(sf[0][2*kk][2],   sf[0][2*kk][3]);
            pa0[2] = pkh2(sf[0][2*kk+1][0], sf[0][2*kk+1][1]);
            pa0[3] = pkh2(sf[0][2*kk+1][2], sf[0][2*kk+1][3]);
            pa1[0] = pkh2(sf[1][2*kk][0],   sf[1][2*kk][1]);
            pa1[1] = pkh2(sf[1][2*kk][2],   sf[1][2*kk][3]);
            pa1[2] = pkh2(sf[1][2*kk+1][0], sf[1][2*kk+1][1]);
            pa1[3] = pkh2(sf[1][2*kk+1][2], sf[1][2*kk+1][3]);
#pragma unroll
            for (int dn = 0; dn < 4; dn++) {
                unsigned b0 = Vhs[buf][8*kk + q][dn * 8 + g];
                unsigned b1 = Vhs[buf][8*kk + q + 4][dn * 8 + g];
                mma16h(oacc[0][dn], pa0, b0, b1);
                mma16h(oacc[1][dn], pa1, b0, b1);
            }
        }

        // commit prefetched V tile
        if (t + 1 < NT) {
            uint4 p;
            p.x = prmt(wa.x, wb.x, 0x5410); p.y = prmt(wa.x, wb.x, 0x7632);
            p.z = prmt(wa.y, wb.y, 0x5410); p.w = prmt(wa.y, wb.y, 0x7632);
            *(uint4*)&Vhs[nb][vj][vdg] = p;
        }
        __syncthreads();
    }

    // ---- deferred l reduction (once), normalize, store fp16 ----
    unsigned* ow = reinterpret_cast<unsigned*>(g_attnh);
#pragma unroll
    for (int mc = 0; mc < 2; mc++) {
        float l0 = lp[mc][0], l1 = lp[mc][1];
        l0 += __shfl_xor_sync(0xffffffffu, l0, 1);
        l0 += __shfl_xor_sync(0xffffffffu, l0, 2);
        l1 += __shfl_xor_sync(0xffffffffu, l1, 1);
        l1 += __shfl_xor_sync(0xffffffffu, l1, 2);
        float inv0 = 1.0f / l0;
        float inv1 = 1.0f / l1;
        int r0 = b * TT + qrow0 + mc * 16 + g;
#pragma unroll
        for (int dn = 0; dn < 4; dn++) {
            int col = h * DK + dn * 8 + 2 * q;
            ow[(size_t)r0 * (DD/2) + col/2] =
                pkh2(oacc[mc][dn][0] * inv0, oacc[mc][dn][1] * inv0);
            ow[(size_t)(r0 + 8) * (DD/2) + col/2] =
                pkh2(oacc[mc][dn][2] * inv1, oacc[mc][dn][3] * inv1);
        }
    }
}

// ============================================================
// 4. Wout GEMM (fp16) + bias + residual + LayerNorm, fused.
//    Block 64x256 (full rows), 8 warps (2m x 4n), warp 32x64.
//    K staged 32/stage, 4-stage cp.async.
// ============================================================
#define WST_A 1280      // words per A stage (64*20)
#define WST_B 5120      // words per B stage (256*20)
#define WRED_OFF (4*(WST_A+WST_B))
#define WSMEM_BYTES ((WRED_OFF+512)*4)

__global__ __launch_bounds__(256, 2)
void wout_ln_kernel(int layer, const float* __restrict__ bias,
                    const float* __restrict__ gamma,
                    const float* __restrict__ beta) {
    unsigned* As = (unsigned*)dynsmem;
    unsigned* Bs = As + 4 * WST_A;
    float* redS = dynsmem + WRED_OFF;       // [64][4]
    float* redQ = redS + 256;               // [64][4]
    const __half* __restrict__ A = g_attnh;
    const __half* __restrict__ Bmat = g_wout16 + (size_t)layer * DD * DD; // [n][k]

    const int tid  = threadIdx.x;
    const int lane = tid & 31;
    const int g    = lane >> 2;
    const int q    = lane & 3;
    const int warp = tid >> 5;
    const int wm   = (warp & 1) * 32;
    const int wn   = (warp >> 1) * 64;
    const int bm   = blockIdx.x * 64;

    auto issue = [&](int s) {
        int k0 = s * 32;
        unsigned* Asb = As + (s & 3) * WST_A;
        unsigned* Bsb = Bs + (s & 3) * WST_B;
        {
            int r = tid >> 2, cw = (tid & 3) * 4;
            cp16(&Asb[r * 20 + cw], A + (size_t)(bm + r) * DD + k0 + cw * 2);
        }
#pragma unroll
        for (int p = 0; p < 4; p++) {
            int c = tid + p * 256;
            int r = c >> 2, cw = (c & 3) * 4;
            cp16(&Bsb[r * 20 + cw], Bmat + (size_t)r * DD + k0 + cw * 2);
        }
    };

    float acc[2][8][4];
#pragma unroll
    for (int mc = 0; mc < 2; mc++)
#pragma unroll
        for (int nc = 0; nc < 8; nc++)
#pragma unroll
            for (int i = 0; i < 4; i++) acc[mc][nc][i] = 0.0f;

    issue(0); cp_commit();
    issue(1); cp_commit();
    issue(2); cp_commit();

    const int NS = DD / 32;    // 8
    for (int s = 0; s < NS; s++) {
        cp_wait<2>();
        __syncthreads();
        if (s + 3 < NS) issue(s + 3);
        cp_commit();

        const unsigned* Asb = As + (s & 3) * WST_A;
        const unsigned* Bsb = Bs + (s & 3) * WST_B;
#pragma unroll
        for (int kc = 0; kc < 2; kc++) {
            int kb = kc * 8;
            unsigned af[2][4], bf[8][2];
#pragma unroll
            for (int mc = 0; mc < 2; mc++) {
                int r = wm + mc * 16 + g;
                af[mc][0] = Asb[r * 20 + kb + q];
                af[mc][1] = Asb[(r + 8) * 20 + kb + q];
                af[mc][2] = Asb[r * 20 + kb + q + 4];
                af[mc][3] = Asb[(r + 8) * 20 + kb + q + 4];
            }
#pragma unroll
            for (int nc = 0; nc < 8; nc++) {
                int cc = wn + nc * 8 + g;
                bf[nc][0] = Bsb[cc * 20 + kb + q];
                bf[nc][1] = Bsb[cc * 20 + kb + q + 4];
            }
#pragma unroll
            for (int mc = 0; mc < 2; mc++)
#pragma unroll
                for (int nc = 0; nc < 8; nc++)
                    mma16h(acc[mc][nc], af[mc], bf[nc][0], bf[nc][1]);
        }
    }
    __syncthreads();

    // epilogue part 1: + bias + residual (fp32)
#pragma unroll
    for (int mc = 0; mc < 2; mc++) {
        int rlo = bm + wm + mc * 16 + g;
#pragma unroll
        for (int nc = 0; nc < 8; nc++) {
            int col = wn + nc * 8 + 2 * q;
            float2 bi = *(const float2*)&bias[col];
            float2 h0 = *(const float2*)&g_h[(size_t)rlo * DD + col];
            float2 h1 = *(const float2*)&g_h[(size_t)(rlo + 8) * DD + col];
            acc[mc][nc][0] += bi.x + h0.x;
            acc[mc][nc][1] += bi.y + h0.y;
            acc[mc][nc][2] += bi.x + h1.x;
            acc[mc][nc][3] += bi.y + h1.y;
        }
    }

    // epilogue part 2: row stats
    const int ng = warp >> 1;
#pragma unroll
    for (int mc = 0; mc < 2; mc++) {
        float slo = 0.f, qlo = 0.f, shi = 0.f, qhi = 0.f;
#pragma unroll
        for (int nc = 0; nc < 8; nc++) {
            slo += acc[mc][nc][0] + acc[mc][nc][1];
            qlo += acc[mc][nc][0] * acc[mc][nc][0] + acc[mc][nc][1] * acc[mc][nc][1];
            shi += acc[mc][nc][2] + acc[mc][nc][3];
            qhi += acc[mc][nc][2] * acc[mc][nc][2] + acc[mc][nc][3] * acc[mc][nc][3];
        }
        slo += __shfl_xor_sync(0xffffffffu, slo, 1); slo += __shfl_xor_sync(0xffffffffu, slo, 2);
        qlo += __shfl_xor_sync(0xffffffffu, qlo, 1); qlo += __shfl_xor_sync(0xffffffffu, qlo, 2);
        shi += __shfl_xor_sync(0xffffffffu, shi, 1); shi += __shfl_xor_sync(0xffffffffu, shi, 2);
        qhi += __shfl_xor_sync(0xffffffffu, qhi, 1); qhi += __shfl_xor_sync(0xffffffffu, qhi, 2);
        if (q == 0) {
            int rlo = wm + mc * 16 + g;
            redS[rlo * 4 + ng] = slo;  redQ[rlo * 4 + ng] = qlo;
            redS[(rlo + 8) * 4 + ng] = shi;  redQ[(rlo + 8) * 4 + ng] = qhi;
        }
    }
    __syncthreads();

    // epilogue part 3: normalize + store (fp32 + fp16)
    unsigned* hw = reinterpret_cast<unsigned*>(g_h16);
#pragma unroll
    for (int mc = 0; mc < 2; mc++) {
        int rl = wm + mc * 16 + g;
        float slo = redS[rl*4] + redS[rl*4+1] + redS[rl*4+2] + redS[rl*4+3];
        float qlo = redQ[rl*4] + redQ[rl*4+1] + redQ[rl*4+2] + redQ[rl*4+3];
        float shi = redS[(rl+8)*4] + redS[(rl+8)*4+1] + redS[(rl+8)*4+2] + redS[(rl+8)*4+3];
        float qhi = redQ[(rl+8)*4] + redQ[(rl+8)*4+1] + redQ[(rl+8)*4+2] + redQ[(rl+8)*4+3];
        float mulo = slo * (1.0f / DD);
        float muhi = shi * (1.0f / DD);
        float rslo = rsqrtf(qlo * (1.0f / DD) - mulo * mulo + LN_EPS);
        float rshi = rsqrtf(qhi * (1.0f / DD) - muhi * muhi + LN_EPS);
        int rowlo = bm + rl;
#pragma unroll
        for (int nc = 0; nc < 8; nc++) {
            int col = wn + nc * 8 + 2 * q;
            float2 ga = *(const float2*)&gamma[col];
            float2 be = *(const float2*)&beta[col];
            float v0 = (acc[mc][nc][0] - mulo) * rslo * ga.x + be.x;
            float v1 = (acc[mc][nc][1] - mulo) * rslo * ga.y + be.y;
            float v2 = (acc[mc][nc][2] - muhi) * rshi * ga.x + be.x;
            float v3 = (acc[mc][nc][3] - muhi) * rshi * ga.y + be.y;
            *(float2*)&g_h[(size_t)rowlo * DD + col]       = make_float2(v0, v1);
            *(float2*)&g_h[(size_t)(rowlo + 8) * DD + col] = make_float2(v2, v3);
            hw[(size_t)rowlo * (DD/2) + col/2]       = pkh2(v0, v1);
            hw[(size_t)(rowlo + 8) * (DD/2) + col/2] = pkh2(v2, v3);
        }
    }
}

// ============================================================
// 5. Head
// ============================================================
__global__ void head_kernel(const float* __restrict__ Wo,
                            const float* __restrict__ bo,
                            float* __restrict__ out) {
    int b = blockIdx.x / 3;
    int j = blockIdx.x - b * 3;
    int lane = threadIdx.x;
    const float* hr = g_h + (size_t)(b * TT + (TT - 1)) * DD;
    float s = 0.0f;
    for (int d = lane; d < DD; d += 32)
        s = fmaf(hr[d], Wo[d * 3 + j], s);
#pragma unroll
    for (int o = 16; o > 0; o >>= 1)
        s += __shfl_xor_sync(0xffffffffu, s, o);
    if (lane == 0) out[b * 3 + j] = s + bo[j];
}

// ============================================================
// launch
// ============================================================
extern "C" void kernel_launch(void* const* d_in, const int* in_sizes, int n_in,
                              void* d_out, int out_size) {
    const float* x    = (const float*)d_in[0];
    const float* Wp   = (const float*)d_in[1];
    const float* bp   = (const float*)d_in[2];
    const float* pos  = (const float*)d_in[3];
    const float* Wqkv = (const float*)d_in[4];
    const float* bqkv = (const float*)d_in[5];
    const float* Wout = (const float*)d_in[6];
    const float* bout = (const float*)d_in[7];
    const float* ln_g = (const float*)d_in[8];
    const float* ln_b = (const float*)d_in[9];
    const float* Wo   = (const float*)d_in[10];
    const float* bo   = (const float*)d_in[11];
    float* out = (float*)d_out;

    cudaFuncSetAttribute(qkv_gemm_kernel, cudaFuncAttributeMaxDynamicSharedMemorySize, QSMEM_BYTES);
    cudaFuncSetAttribute(wout_ln_kernel,  cudaFuncAttributeMaxDynamicSharedMemorySize, WSMEM_BYTES);

    __half* d_wqkv16 = nullptr;
    __half* d_wout16 = nullptr;
    cudaGetSymbolAddress((void**)&d_wqkv16, g_wqkv16);
    cudaGetSymbolAddress((void**)&d_wout16, g_wout16);

    transp_kernel<<<dim3(DD/32, (3*DD)/32, LL), dim3(32, 8)>>>(Wqkv, d_wqkv16, 3*DD);
    transp_kernel<<<dim3(DD/32, DD/32, LL),     dim3(32, 8)>>>(Wout, d_wout16, DD);
    proj_kernel<<<(NROW * DD + 255) / 256, 256>>>(x, Wp, bp, pos);

    for (int l = 0; l < LL; l++) {
        qkv_gemm_kernel<<<dim3((3 * DD) / 128, NROW / 128), 256, QSMEM_BYTES>>>(
            l, bqkv + (size_t)l * 3 * DD);
        attn_tc_kernel<<<dim3(TT / 128, HH, BB), 128>>>();
        wout_ln_kernel<<<NROW / 64, 256, WSMEM_BYTES>>>(
            l, bout + (size_t)l * DD, ln_g + (size_t)l * DD, ln_b + (size_t)l * DD);
    }

    head_kernel<<<24, 32>>>(Wo, bo, out);
}

// round 10
// speedup vs baseline: 7.2576x; 1.0425x over previous
#include <cuda_runtime.h>
#include <cuda_fp16.h>
#include <math.h>

// Problem constants
#define BB 8
#define TT 1024
#define IN_DIM 16
#define DD 256
#define HH 8
#define DK 32
#define LL 4
#define NROW (BB*TT)
#define LN_EPS 1e-5f

// -------- scratch (device globals) --------
__device__ float  g_h[NROW*DD];           // fp32 residual stream
__device__ __half g_h16[NROW*DD];         // fp16 hidden (GEMM A input)
__device__ __half g_qkvh[NROW*3*DD];      // fp16 qkv
__device__ __half g_attnh[NROW*DD];       // fp16 attention out
__device__ __half g_wqkv16[LL*3*DD*DD];   // fp16 Wqkv TRANSPOSED [l][n][k]
__device__ __half g_wout16[LL*DD*DD];     // fp16 Wout TRANSPOSED [l][n][k]
__device__ float  g_mk[BB*HH];            // per (b,h) max key norm

// -------- helpers --------
__device__ __forceinline__ void mma16h(float* d, const unsigned* a, unsigned b0, unsigned b1) {
    asm volatile(
        "mma.sync.aligned.m16n8k16.row.col.f32.f16.f16.f32 "
        "{%0,%1,%2,%3}, {%4,%5,%6,%7}, {%8,%9}, {%0,%1,%2,%3};\n"
        : "+f"(d[0]), "+f"(d[1]), "+f"(d[2]), "+f"(d[3])
        : "r"(a[0]), "r"(a[1]), "r"(a[2]), "r"(a[3]), "r"(b0), "r"(b1));
}
__device__ __forceinline__ unsigned pkh2(float lo, float hi) {
    __half2 h = __floats2half2_rn(lo, hi);
    return *reinterpret_cast<unsigned*>(&h);
}
__device__ __forceinline__ unsigned prmt(unsigned a, unsigned b, unsigned sel) {
    unsigned r;
    asm("prmt.b32 %0, %1, %2, %3;" : "=r"(r) : "r"(a), "r"(b), "r"(sel));
    return r;
}
__device__ __forceinline__ void cp16(void* smem, const void* g) {
    unsigned a = (unsigned)__cvta_generic_to_shared(smem);
    asm volatile("cp.async.cg.shared.global [%0], [%1], 16;\n" :: "r"(a), "l"(g));
}
__device__ __forceinline__ void cp_commit() { asm volatile("cp.async.commit_group;\n"); }
template<int N> __device__ __forceinline__ void cp_wait() {
    asm volatile("cp.async.wait_group %0;\n" :: "n"(N));
}

// ============================================================
// 0. Weight transpose + fp16 convert (once per launch).
// ============================================================
__global__ void transp_kernel(const float* __restrict__ src,
                              __half* __restrict__ dst, int N) {
    __shared__ float tile[32][33];
    int k0 = blockIdx.x * 32, n0 = blockIdx.y * 32;
    const float* s = src + (size_t)blockIdx.z * DD * N;
    __half* d = dst + (size_t)blockIdx.z * DD * N;
    for (int i = threadIdx.y; i < 32; i += 8)
        tile[i][threadIdx.x] = s[(size_t)(k0 + i) * N + n0 + threadIdx.x];
    __syncthreads();
    for (int i = threadIdx.y; i < 32; i += 8)
        d[(size_t)(n0 + i) * DD + k0 + threadIdx.x] = __float2half_rn(tile[threadIdx.x][i]);
}

// ============================================================
// 1. Projection: h = x @ Wp + bp + pos  (fp32 + fp16 copy)
// ============================================================
__global__ void proj_kernel(const float* __restrict__ x,
                            const float* __restrict__ Wp,
                            const float* __restrict__ bp,
                            const float* __restrict__ pos) {
    int idx = blockIdx.x * blockDim.x + threadIdx.x;
    if (idx >= NROW * DD) return;
    int row = idx / DD;
    int col = idx - row * DD;
    int t = row & (TT - 1);
    const float* xr = x + row * IN_DIM;
    float s = bp[col] + pos[t * DD + col];
#pragma unroll
    for (int i = 0; i < IN_DIM; i++)
        s = fmaf(xr[i], Wp[i * DD + col], s);
    g_h[idx] = s;
    g_h16[idx] = __float2half_rn(s);
}

// ============================================================
// 1b. Max key norm per (b,h): M_k = max_j ||k_j||.
//     Rigorous softmax bound: q.k <= ||q||*M_k (Cauchy-Schwarz).
// ============================================================
__global__ void knorm_kernel() {
    int h = blockIdx.x, b = blockIdx.y;
    const __half* kg = g_qkvh + (size_t)b * TT * (3 * DD) + DD + h * DK;
    float mx = 0.0f;
    for (int j = threadIdx.x; j < TT; j += 128) {
        const uint4* p = (const uint4*)(kg + (size_t)j * (3 * DD));
        float s = 0.0f;
#pragma unroll
        for (int c = 0; c < 4; c++) {
            uint4 w = p[c];
            unsigned ws[4] = {w.x, w.y, w.z, w.w};
#pragma unroll
            for (int i = 0; i < 4; i++) {
                float2 f = __half22float2(*reinterpret_cast<__half2*>(&ws[i]));
                s = fmaf(f.x, f.x, s);
                s = fmaf(f.y, f.y, s);
            }
        }
        mx = fmaxf(mx, s);
    }
#pragma unroll
    for (int o = 16; o > 0; o >>= 1)
        mx = fmaxf(mx, __shfl_xor_sync(0xffffffffu, mx, o));
    __shared__ float sm[4];
    if ((threadIdx.x & 31) == 0) sm[threadIdx.x >> 5] = mx;
    __syncthreads();
    if (threadIdx.x == 0) {
        float m = fmaxf(fmaxf(sm[0], sm[1]), fmaxf(sm[2], sm[3]));
        g_mk[b * HH + h] = sqrtf(m);
    }
}

// ============================================================
// 2. QKV GEMM (fp16 m16n8k16): g_qkvh = g_h16 @ W^T + bqkv
// ============================================================
#define QST_A 2560      // words per A stage (128*20)
#define QST_B 2560      // words per B stage (128*20)
#define QSMEM_BYTES ((4*(QST_A+QST_B))*4)

extern __shared__ float dynsmem[];

__global__ __launch_bounds__(256, 2)
void qkv_gemm_kernel(int layer, const float* __restrict__ bias) {
    unsigned* As = (unsigned*)dynsmem;          // [4][128][20]
    unsigned* Bs = As + 4 * QST_A;              // [4][128][20]
    const __half* __restrict__ A = g_h16;
    const __half* __restrict__ Bmat = g_wqkv16 + (size_t)layer * 3 * DD * DD; // [n][k]
    const int N = 3 * DD;

    const int tid  = threadIdx.x;
    const int lane = tid & 31;
    const int g    = lane >> 2;
    const int q    = lane & 3;
    const int warp = tid >> 5;
    const int wm   = (warp & 1) * 64;
    const int wn   = (warp >> 1) * 32;
    const int bm   = blockIdx.y * 128;
    const int bn   = blockIdx.x * 128;

    auto issue = [&](int s) {
        int k0 = s * 32;
        unsigned* Asb = As + (s & 3) * QST_A;
        unsigned* Bsb = Bs + (s & 3) * QST_B;
#pragma unroll
        for (int p = 0; p < 2; p++) {
            int c = tid + p * 256;
            int r = c >> 2, cw = (c & 3) * 4;
            cp16(&Asb[r * 20 + cw], A + (size_t)(bm + r) * DD + k0 + cw * 2);
        }
#pragma unroll
        for (int p = 0; p < 2; p++) {
            int c = tid + p * 256;
            int r = c >> 2, cw = (c & 3) * 4;
            cp16(&Bsb[r * 20 + cw], Bmat + (size_t)(bn + r) * DD + k0 + cw * 2);
        }
    };

    float acc[4][4][4];
#pragma unroll
    for (int mc = 0; mc < 4; mc++)
#pragma unroll
        for (int nc = 0; nc < 4; nc++)
#pragma unroll
            for (int i = 0; i < 4; i++) acc[mc][nc][i] = 0.0f;

    issue(0); cp_commit();
    issue(1); cp_commit();
    issue(2); cp_commit();

    const int NS = DD / 32;   // 8
    for (int s = 0; s < NS; s++) {
        cp_wait<2>();
        __syncthreads();
        if (s + 3 < NS) issue(s + 3);
        cp_commit();

        const unsigned* Asb = As + (s & 3) * QST_A;
        const unsigned* Bsb = Bs + (s & 3) * QST_B;
#pragma unroll
        for (int kc = 0; kc < 2; kc++) {
            int kb = kc * 8;
            unsigned af[4][4], bf[4][2];
#pragma unroll
            for (int mc = 0; mc < 4; mc++) {
                int r = wm + mc * 16 + g;
                af[mc][0] = Asb[r * 20 + kb + q];
                af[mc][1] = Asb[(r + 8) * 20 + kb + q];
                af[mc][2] = Asb[r * 20 + kb + q + 4];
                af[mc][3] = Asb[(r + 8) * 20 + kb + q + 4];
            }
#pragma unroll
            for (int nc = 0; nc < 4; nc++) {
                int cc = wn + nc * 8 + g;
                bf[nc][0] = Bsb[cc * 20 + kb + q];
                bf[nc][1] = Bsb[cc * 20 + kb + q + 4];
            }
#pragma unroll
            for (int mc = 0; mc < 4; mc++)
#pragma unroll
                for (int nc = 0; nc < 4; nc++)
                    mma16h(acc[mc][nc], af[mc], bf[nc][0], bf[nc][1]);
        }
    }

    // epilogue: + bias, pack to fp16
    unsigned* qkw = reinterpret_cast<unsigned*>(g_qkvh);
#pragma unroll
    for (int mc = 0; mc < 4; mc++) {
#pragma unroll
        for (int nc = 0; nc < 4; nc++) {
            int row = bm + wm + mc * 16 + g;
            int col = bn + wn + nc * 8 + 2 * q;
            float2 bi = *(const float2*)&bias[col];
            qkw[(size_t)row * (N/2) + col/2] =
                pkh2(acc[mc][nc][0] + bi.x, acc[mc][nc][1] + bi.y);
            qkw[(size_t)(row + 8) * (N/2) + col/2] =
                pkh2(acc[mc][nc][2] + bi.x, acc[mc][nc][3] + bi.y);
        }
    }
}

// ============================================================
// 3. Flash attention, fp16 MMA, BOUNDED no-running-max softmax:
//    p' = exp2(s*qs + (B - ||q||*M_k*qs)) <= 2^B = 2048 (fp16 safe
//    by Cauchy-Schwarz; B=11 leaves 32x headroom). The 2^B bias
//    cancels in o = sum(p'v)/sum(p'). No max tree, no shuffles,
//    no rescales in the loop; l quad-reduced once at the end.
// ============================================================
__global__ __launch_bounds__(128, 4)
void attn_tc_kernel() {
    __shared__ unsigned Khs[2][32][20];   // [key][dim half2-word]
    __shared__ unsigned Vhs[2][16][40];   // [keypair][dim]

    const int tid  = threadIdx.x;
    const int lane = tid & 31;
    const int g    = lane >> 2;
    const int q    = lane & 3;
    const int warp = tid >> 5;
    const int h    = blockIdx.y;
    const int b    = blockIdx.z;
    const int qrow0 = blockIdx.x * 128 + warp * 32;

    const float qs = 0.17677669529663687f * 1.4426950408889634f; // scale*log2e
    const int RW = 3 * DD;
    const int RWW = RW / 2;

    const __half* kg = g_qkvh + (size_t)b * TT * RW + DD + h * DK;
    const __half* vg = g_qkvh + (size_t)b * TT * RW + 2 * DD + h * DK;
    const unsigned* qw = reinterpret_cast<const unsigned*>(
        g_qkvh + (size_t)(b * TT + qrow0) * RW + h * DK);

    const int kkey = tid >> 2;            // 0..31
    const int kwg  = (tid & 3) * 4;       // word offset 0,4,8,12
    const int vj  = tid >> 3;             // 0..15
    const int vdg = (tid & 7) * 4;        // dims vdg..vdg+3

    // prologue tile 0
    cp16(&Khs[0][kkey][kwg], kg + (size_t)kkey * RW + kwg * 2);
    cp_commit();
    {
        uint2 wa = *(const uint2*)(vg + (size_t)(2 * vj) * RW + vdg);
        uint2 wb = *(const uint2*)(vg + (size_t)(2 * vj + 1) * RW + vdg);
        uint4 p;
        p.x = prmt(wa.x, wb.x, 0x5410); p.y = prmt(wa.x, wb.x, 0x7632);
        p.z = prmt(wa.y, wb.y, 0x5410); p.w = prmt(wa.y, wb.y, 0x7632);
        *(uint4*)&Vhs[0][vj][vdg] = p;
    }

    // Q A-fragments (fp16 words straight from memory)
    unsigned qa[2][2][4];
#pragma unroll
    for (int mc = 0; mc < 2; mc++)
#pragma unroll
        for (int kc = 0; kc < 2; kc++) {
            int r = mc * 16 + g;
            qa[mc][kc][0] = qw[(size_t)r * RWW + kc * 8 + q];
            qa[mc][kc][1] = qw[(size_t)(r + 8) * RWW + kc * 8 + q];
            qa[mc][kc][2] = qw[(size_t)r * RWW + kc * 8 + q + 4];
            qa[mc][kc][3] = qw[(size_t)(r + 8) * RWW + kc * 8 + q + 4];
        }

    // Per-row exp bias: eb = B - ||q||*M_k*qs  (B=11)
    const float Mk = g_mk[b * HH + h];
    float eb[2][2];
#pragma unroll
    for (int mc = 0; mc < 2; mc++) {
        float a0 = 0.0f, a1 = 0.0f;
#pragma unroll
        for (int kc = 0; kc < 2; kc++) {
            float2 f;
            f = __half22float2(*reinterpret_cast<__half2*>(&qa[mc][kc][0]));
            a0 = fmaf(f.x, f.x, fmaf(f.y, f.y, a0));
            f = __half22float2(*reinterpret_cast<__half2*>(&qa[mc][kc][2]));
            a0 = fmaf(f.x, f.x, fmaf(f.y, f.y, a0));
            f = __half22float2(*reinterpret_cast<__half2*>(&qa[mc][kc][1]));
            a1 = fmaf(f.x, f.x, fmaf(f.y, f.y, a1));
            f = __half22float2(*reinterpret_cast<__half2*>(&qa[mc][kc][3]));
            a1 = fmaf(f.x, f.x, fmaf(f.y, f.y, a1));
        }
        a0 += __shfl_xor_sync(0xffffffffu, a0, 1);
        a0 += __shfl_xor_sync(0xffffffffu, a0, 2);
        a1 += __shfl_xor_sync(0xffffffffu, a1, 1);
        a1 += __shfl_xor_sync(0xffffffffu, a1, 2);
        eb[mc][0] = 11.0f - sqrtf(a0) * Mk * qs;
        eb[mc][1] = 11.0f - sqrtf(a1) * Mk * qs;
    }

    float oacc[2][4][4];
    float lp[2][2];
#pragma unroll
    for (int mc = 0; mc < 2; mc++) {
        lp[mc][0] = 0.0f; lp[mc][1] = 0.0f;
#pragma unroll
        for (int nc = 0; nc < 4; nc++)
#pragma unroll
            for (int i = 0; i < 4; i++) oacc[mc][nc][i] = 0.0f;
    }

    const int NT = TT / 32;
    for (int t = 0; t < NT; t++) {
        int buf = t & 1;
        int nb  = buf ^ 1;
        uint2 wa, wb;
        if (t + 1 < NT) {
            int k0 = (t + 1) * 32;
            cp16(&Khs[nb][kkey][kwg], kg + (size_t)(k0 + kkey) * RW + kwg * 2);
            cp_commit();
            wa = *(const uint2*)(vg + (size_t)(k0 + 2 * vj) * RW + vdg);
            wb = *(const uint2*)(vg + (size_t)(k0 + 2 * vj + 1) * RW + vdg);
            cp_wait<1>();
        } else {
            cp_wait<0>();
        }
        __syncthreads();

        // ---- S = Q K^T (fp16 k16) ----
        float sf[2][4][4];
#pragma unroll
        for (int mc = 0; mc < 2; mc++)
#pragma unroll
            for (int nc = 0; nc < 4; nc++)
#pragma unroll
                for (int i = 0; i < 4; i++) sf[mc][nc][i] = 0.0f;

#pragma unroll
        for (int nc = 0; nc < 4; nc++) {
#pragma unroll
            for (int kc = 0; kc < 2; kc++) {
                unsigned b0 = Khs[buf][nc * 8 + g][kc * 8 + q];
                unsigned b1 = Khs[buf][nc * 8 + g][kc * 8 + q + 4];
                mma16h(sf[0][nc], qa[0][kc], b0, b1);
                mma16h(sf[1][nc], qa[1][kc], b0, b1);
            }
        }

        // ---- bounded softmax: p' = exp2(s*qs + eb), accumulate l ----
#pragma unroll
        for (int mc = 0; mc < 2; mc++) {
            float e0 = eb[mc][0], e1 = eb[mc][1];
            float s0 = 0.0f, s1 = 0.0f;
#pragma unroll
            for (int nc = 0; nc < 4; nc++) {
                sf[mc][nc][0] = exp2f(fmaf(sf[mc][nc][0], qs, e0));
                sf[mc][nc][1] = exp2f(fmaf(sf[mc][nc][1], qs, e0));
                sf[mc][nc][2] = exp2f(fmaf(sf[mc][nc][2], qs, e1));
                sf[mc][nc][3] = exp2f(fmaf(sf[mc][nc][3], qs, e1));
                s0 += sf[mc][nc][0] + sf[mc][nc][1];
                s1 += sf[mc][nc][2] + sf[mc][nc][3];
            }
            lp[mc][0] += s0;
            lp[mc][1] += s1;
        }

        // ---- O += P V  (fp16; P pack = C-frag identity) ----
#pragma unroll
        for (int kk = 0; kk < 2; kk++) {
            unsigned pa0[4], pa1[4];
            pa0[0] = pkh2(sf[0][2*kk][0],   sf[0][2*kk][1]);
            pa0[1] = pkh2(sf[0][2*kk][2],   sf[0][2*kk][3]);
            pa0[2] = pkh2(sf[0][2*kk+1][0], sf[0][2*kk+1][1]);
            pa0[3] = pkh2(sf[0][2*kk+1][2], sf[0][2*kk+1][3]);
            pa1[0] = pkh2(sf[1][2*kk][0],   sf[1][2*kk][1]);
            pa1[1] = pkh2(sf[1][2*kk][2],   sf[1][2*kk][3]);
            pa1[2] = pkh2(sf[1][2*kk+1][0], sf[1][2*kk+1][1]);
            pa1[3] = pkh2(sf[1][2*kk+1][2], sf[1][2*kk+1][3]);
#pragma unroll
            for (int dn = 0; dn < 4; dn++) {
                unsigned b0 = Vhs[buf][8*kk + q][dn * 8 + g];
                unsigned b1 = Vhs[buf][8*kk + q + 4][dn * 8 + g];
                mma16h(oacc[0][dn], pa0, b0, b1);
                mma16h(oacc[1][dn], pa1, b0, b1);
            }
        }

        // commit prefetched V tile
        if (t + 1 < NT) {
            uint4 p;
            p.x = prmt(wa.x, wb.x, 0x5410); p.y = prmt(wa.x, wb.x, 0x7632);
            p.z = prmt(wa.y, wb.y, 0x5410); p.w = prmt(wa.y, wb.y, 0x7632);
            *(uint4*)&Vhs[nb][vj][vdg] = p;
        }
        __syncthreads();
    }

    // ---- deferred l reduction (once), normalize, store fp16 ----
    unsigned* ow = reinterpret_cast<unsigned*>(g_attnh);
#pragma unroll
    for (int mc = 0; mc < 2; mc++) {
        float l0 = lp[mc][0], l1 = lp[mc][1];
        l0 += __shfl_xor_sync(0xffffffffu, l0, 1);
        l0 += __shfl_xor_sync(0xffffffffu, l0, 2);
        l1 += __shfl_xor_sync(0xffffffffu, l1, 1);
        l1 += __shfl_xor_sync(0xffffffffu, l1, 2);
        float inv0 = 1.0f / l0;
        float inv1 = 1.0f / l1;
        int r0 = b * TT + qrow0 + mc * 16 + g;
#pragma unroll
        for (int dn = 0; dn < 4; dn++) {
            int col = h * DK + dn * 8 + 2 * q;
            ow[(size_t)r0 * (DD/2) + col/2] =
                pkh2(oacc[mc][dn][0] * inv0, oacc[mc][dn][1] * inv0);
            ow[(size_t)(r0 + 8) * (DD/2) + col/2] =
                pkh2(oacc[mc][dn][2] * inv1, oacc[mc][dn][3] * inv1);
        }
    }
}

// ============================================================
// 4. Wout GEMM (fp16) + bias + residual + LayerNorm, fused.
// ============================================================
#define WST_A 1280      // words per A stage (64*20)
#define WST_B 5120      // words per B stage (256*20)
#define WRED_OFF (4*(WST_A+WST_B))
#define WSMEM_BYTES ((WRED_OFF+512)*4)

__global__ __launch_bounds__(256, 2)
void wout_ln_kernel(int layer, const float* __restrict__ bias,
                    const float* __restrict__ gamma,
                    const float* __restrict__ beta) {
    unsigned* As = (unsigned*)dynsmem;
    unsigned* Bs = As + 4 * WST_A;
    float* redS = dynsmem + WRED_OFF;       // [64][4]
    float* redQ = redS + 256;               // [64][4]
    const __half* __restrict__ A = g_attnh;
    const __half* __restrict__ Bmat = g_wout16 + (size_t)layer * DD * DD; // [n][k]

    const int tid  = threadIdx.x;
    const int lane = tid & 31;
    const int g    = lane >> 2;
    const int q    = lane & 3;
    const int warp = tid >> 5;
    const int wm   = (warp & 1) * 32;
    const int wn   = (warp >> 1) * 64;
    const int bm   = blockIdx.x * 64;

    auto issue = [&](int s) {
        int k0 = s * 32;
        unsigned* Asb = As + (s & 3) * WST_A;
        unsigned* Bsb = Bs + (s & 3) * WST_B;
        {
            int r = tid >> 2, cw = (tid & 3) * 4;
            cp16(&Asb[r * 20 + cw], A + (size_t)(bm + r) * DD + k0 + cw * 2);
        }
#pragma unroll
        for (int p = 0; p < 4; p++) {
            int c = tid + p * 256;
            int r = c >> 2, cw = (c & 3) * 4;
            cp16(&Bsb[r * 20 + cw], Bmat + (size_t)r * DD + k0 + cw * 2);
        }
    };

    float acc[2][8][4];
#pragma unroll
    for (int mc = 0; mc < 2; mc++)
#pragma unroll
        for (int nc = 0; nc < 8; nc++)
#pragma unroll
            for (int i = 0; i < 4; i++) acc[mc][nc][i] = 0.0f;

    issue(0); cp_commit();
    issue(1); cp_commit();
    issue(2); cp_commit();

    const int NS = DD / 32;    // 8
    for (int s = 0; s < NS; s++) {
        cp_wait<2>();
        __syncthreads();
        if (s + 3 < NS) issue(s + 3);
        cp_commit();

        const unsigned* Asb = As + (s & 3) * WST_A;
        const unsigned* Bsb = Bs + (s & 3) * WST_B;
#pragma unroll
        for (int kc = 0; kc < 2; kc++) {
            int kb = kc * 8;
            unsigned af[2][4], bf[8][2];
#pragma unroll
            for (int mc = 0; mc < 2; mc++) {
                int r = wm + mc * 16 + g;
                af[mc][0] = Asb[r * 20 + kb + q];
                af[mc][1] = Asb[(r + 8) * 20 + kb + q];
                af[mc][2] = Asb[r * 20 + kb + q + 4];
                af[mc][3] = Asb[(r + 8) * 20 + kb + q + 4];
            }
#pragma unroll
            for (int nc = 0; nc < 8; nc++) {
                int cc = wn + nc * 8 + g;
                bf[nc][0] = Bsb[cc * 20 + kb + q];
                bf[nc][1] = Bsb[cc * 20 + kb + q + 4];
            }
#pragma unroll
            for (int mc = 0; mc < 2; mc++)
#pragma unroll
                for (int nc = 0; nc < 8; nc++)
                    mma16h(acc[mc][nc], af[mc], bf[nc][0], bf[nc][1]);
        }
    }
    __syncthreads();

    // epilogue part 1: + bias + residual (fp32)
#pragma unroll
    for (int mc = 0; mc < 2; mc++) {
        int rlo = bm + wm + mc * 16 + g;
#pragma unroll
        for (int nc = 0; nc < 8; nc++) {
            int col = wn + nc * 8 + 2 * q;
            float2 bi = *(const float2*)&bias[col];
            float2 h0 = *(const float2*)&g_h[(size_t)rlo * DD + col];
            float2 h1 = *(const float2*)&g_h[(size_t)(rlo + 8) * DD + col];
            acc[mc][nc][0] += bi.x + h0.x;
            acc[mc][nc][1] += bi.y + h0.y;
            acc[mc][nc][2] += bi.x + h1.x;
            acc[mc][nc][3] += bi.y + h1.y;
        }
    }

    // epilogue part 2: row stats
    const int ng = warp >> 1;
#pragma unroll
    for (int mc = 0; mc < 2; mc++) {
        float slo = 0.f, qlo = 0.f, shi = 0.f, qhi = 0.f;
#pragma unroll
        for (int nc = 0; nc < 8; nc++) {
            slo += acc[mc][nc][0] + acc[mc][nc][1];
            qlo += acc[mc][nc][0] * acc[mc][nc][0] + acc[mc][nc][1] * acc[mc][nc][1];
            shi += acc[mc][nc][2] + acc[mc][nc][3];
            qhi += acc[mc][nc][2] * acc[mc][nc][2] + acc[mc][nc][3] * acc[mc][nc][3];
        }
        slo += __shfl_xor_sync(0xffffffffu, slo, 1); slo += __shfl_xor_sync(0xffffffffu, slo, 2);
        qlo += __shfl_xor_sync(0xffffffffu, qlo, 1); qlo += __shfl_xor_sync(0xffffffffu, qlo, 2);
        shi += __shfl_xor_sync(0xffffffffu, shi, 1); shi += __shfl_xor_sync(0xffffffffu, shi, 2);
        qhi += __shfl_xor_sync(0xffffffffu, qhi, 1); qhi += __shfl_xor_sync(0xffffffffu, qhi, 2);
        if (q == 0) {
            int rlo = wm + mc * 16 + g;
            redS[rlo * 4 + ng] = slo;  redQ[rlo * 4 + ng] = qlo;
            redS[(rlo + 8) * 4 + ng] = shi;  redQ[(rlo + 8) * 4 + ng] = qhi;
        }
    }
    __syncthreads();

    // epilogue part 3: normalize + store (fp32 + fp16)
    unsigned* hw = reinterpret_cast<unsigned*>(g_h16);
#pragma unroll
    for (int mc = 0; mc < 2; mc++) {
        int rl = wm + mc * 16 + g;
        float slo = redS[rl*4] + redS[rl*4+1] + redS[rl*4+2] + redS[rl*4+3];
        float qlo = redQ[rl*4] + redQ[rl*4+1] + redQ[rl*4+2] + redQ[rl*4+3];
        float shi = redS[(rl+8)*4] + redS[(rl+8)*4+1] + redS[(rl+8)*4+2] + redS[(rl+8)*4+3];
        float qhi = redQ[(rl+8)*4] + redQ[(rl+8)*4+1] + redQ[(rl+8)*4+2] + redQ[(rl+8)*4+3];
        float mulo = slo * (1.0f / DD);
        float muhi = shi * (1.0f / DD);
        float rslo = rsqrtf(qlo * (1.0f / DD) - mulo * mulo + LN_EPS);
        float rshi = rsqrtf(qhi * (1.0f / DD) - muhi * muhi + LN_EPS);
        int rowlo = bm + rl;
#pragma unroll
        for (int nc = 0; nc < 8; nc++) {
            int col = wn + nc * 8 + 2 * q;
            float2 ga = *(const float2*)&gamma[col];
            float2 be = *(const float2*)&beta[col];
            float v0 = (acc[mc][nc][0] - mulo) * rslo * ga.x + be.x;
            float v1 = (acc[mc][nc][1] - mulo) * rslo * ga.y + be.y;
            float v2 = (acc[mc][nc][2] - muhi) * rshi * ga.x + be.x;
            float v3 = (acc[mc][nc][3] - muhi) * rshi * ga.y + be.y;
            *(float2*)&g_h[(size_t)rowlo * DD + col]       = make_float2(v0, v1);
            *(float2*)&g_h[(size_t)(rowlo + 8) * DD + col] = make_float2(v2, v3);
            hw[(size_t)rowlo * (DD/2) + col/2]       = pkh2(v0, v1);
            hw[(size_t)(rowlo + 8) * (DD/2) + col/2] = pkh2(v2, v3);
        }
    }
}

// ============================================================
// 5. Head
// ============================================================
__global__ void head_kernel(const float* __restrict__ Wo,
                            const float* __restrict__ bo,
                            float* __restrict__ out) {
    int b = blockIdx.x / 3;
    int j = blockIdx.x - b * 3;
    int lane = threadIdx.x;
    const float* hr = g_h + (size_t)(b * TT + (TT - 1)) * DD;
    float s = 0.0f;
    for (int d = lane; d < DD; d += 32)
        s = fmaf(hr[d], Wo[d * 3 + j], s);
#pragma unroll
    for (int o = 16; o > 0; o >>= 1)
        s += __shfl_xor_sync(0xffffffffu, s, o);
    if (lane == 0) out[b * 3 + j] = s + bo[j];
}

// ============================================================
// launch
// ============================================================
extern "C" void kernel_launch(void* const* d_in, const int* in_sizes, int n_in,
                              void* d_out, int out_size) {
    const float* x    = (const float*)d_in[0];
    const float* Wp   = (const float*)d_in[1];
    const float* bp   = (const float*)d_in[2];
    const float* pos  = (const float*)d_in[3];
    const float* Wqkv = (const float*)d_in[4];
    const float* bqkv = (const float*)d_in[5];
    const float* Wout = (const float*)d_in[6];
    const float* bout = (const float*)d_in[7];
    const float* ln_g = (const float*)d_in[8];
    const float* ln_b = (const float*)d_in[9];
    const float* Wo   = (const float*)d_in[10];
    const float* bo   = (const float*)d_in[11];
    float* out = (float*)d_out;

    cudaFuncSetAttribute(qkv_gemm_kernel, cudaFuncAttributeMaxDynamicSharedMemorySize, QSMEM_BYTES);
    cudaFuncSetAttribute(wout_ln_kernel,  cudaFuncAttributeMaxDynamicSharedMemorySize, WSMEM_BYTES);

    __half* d_wqkv16 = nullptr;
    __half* d_wout16 = nullptr;
    cudaGetSymbolAddress((void**)&d_wqkv16, g_wqkv16);
    cudaGetSymbolAddress((void**)&d_wout16, g_wout16);

    transp_kernel<<<dim3(DD/32, (3*DD)/32, LL), dim3(32, 8)>>>(Wqkv, d_wqkv16, 3*DD);
    transp_kernel<<<dim3(DD/32, DD/32, LL),     dim3(32, 8)>>>(Wout, d_wout16, DD);
    proj_kernel<<<(NROW * DD + 255) / 256, 256>>>(x, Wp, bp, pos);

    for (int l = 0; l < LL; l++) {
        qkv_gemm_kernel<<<dim3((3 * DD) / 128, NROW / 128), 256, QSMEM_BYTES>>>(
            l, bqkv + (size_t)l * 3 * DD);
        knorm_kernel<<<dim3(HH, BB), 128>>>();
        attn_tc_kernel<<<dim3(TT / 128, HH, BB), 128>>>();
        wout_ln_kernel<<<NROW / 64, 256, WSMEM_BYTES>>>(
            l, bout + (size_t)l * DD, ln_g + (size_t)l * DD, ln_b + (size_t)l * DD);
    }

    head_kernel<<<24, 32>>>(Wo, bo, out);
}

// round 11
// speedup vs baseline: 7.6197x; 1.0499x over previous
#include <cuda_runtime.h>
#include <cuda_fp16.h>
#include <math.h>

// Problem constants
#define BB 8
#define TT 1024
#define IN_DIM 16
#define DD 256
#define HH 8
#define DK 32
#define LL 4
#define NROW (BB*TT)
#define LN_EPS 1e-5f

// -------- scratch (device globals) --------
__device__ float  g_h[NROW*DD];           // fp32 residual stream
__device__ __half g_h16[NROW*DD];         // fp16 hidden (GEMM A input)
__device__ __half g_qkvh[NROW*3*DD];      // fp16 qkv
__device__ __half g_attnh[NROW*DD];       // fp16 attention out
__device__ __half g_wqkv16[LL*3*DD*DD];   // fp16 Wqkv TRANSPOSED [l][n][k]
__device__ __half g_wout16[LL*DD*DD];     // fp16 Wout TRANSPOSED [l][n][k]
__device__ int    g_mki[LL*BB*HH];        // per (l,b,h) max ||k||^2 (float bits)

// -------- helpers --------
__device__ __forceinline__ void mma16h(float* d, const unsigned* a, unsigned b0, unsigned b1) {
    asm volatile(
        "mma.sync.aligned.m16n8k16.row.col.f32.f16.f16.f32 "
        "{%0,%1,%2,%3}, {%4,%5,%6,%7}, {%8,%9}, {%0,%1,%2,%3};\n"
        : "+f"(d[0]), "+f"(d[1]), "+f"(d[2]), "+f"(d[3])
        : "r"(a[0]), "r"(a[1]), "r"(a[2]), "r"(a[3]), "r"(b0), "r"(b1));
}
__device__ __forceinline__ unsigned pkh2(float lo, float hi) {
    __half2 h = __floats2half2_rn(lo, hi);
    return *reinterpret_cast<unsigned*>(&h);
}
__device__ __forceinline__ unsigned prmt(unsigned a, unsigned b, unsigned sel) {
    unsigned r;
    asm("prmt.b32 %0, %1, %2, %3;" : "=r"(r) : "r"(a), "r"(b), "r"(sel));
    return r;
}
__device__ __forceinline__ void cp16(void* smem, const void* g) {
    unsigned a = (unsigned)__cvta_generic_to_shared(smem);
    asm volatile("cp.async.cg.shared.global [%0], [%1], 16;\n" :: "r"(a), "l"(g));
}
__device__ __forceinline__ void cp_commit() { asm volatile("cp.async.commit_group;\n"); }
template<int N> __device__ __forceinline__ void cp_wait() {
    asm volatile("cp.async.wait_group %0;\n" :: "n"(N));
}

// ============================================================
// 0. Weight transpose + fp16 convert (once per launch).
// ============================================================
__global__ void transp_kernel(const float* __restrict__ src,
                              __half* __restrict__ dst, int N) {
    __shared__ float tile[32][33];
    int k0 = blockIdx.x * 32, n0 = blockIdx.y * 32;
    const float* s = src + (size_t)blockIdx.z * DD * N;
    __half* d = dst + (size_t)blockIdx.z * DD * N;
    for (int i = threadIdx.y; i < 32; i += 8)
        tile[i][threadIdx.x] = s[(size_t)(k0 + i) * N + n0 + threadIdx.x];
    __syncthreads();
    for (int i = threadIdx.y; i < 32; i += 8)
        d[(size_t)(n0 + i) * DD + k0 + threadIdx.x] = __float2half_rn(tile[threadIdx.x][i]);
}

// ============================================================
// 1. Projection: h = x @ Wp + bp + pos  (fp32 + fp16 copy)
//    Also zeroes the per-layer max-key-norm accumulators.
// ============================================================
__global__ void proj_kernel(const float* __restrict__ x,
                            const float* __restrict__ Wp,
                            const float* __restrict__ bp,
                            const float* __restrict__ pos) {
    int idx = blockIdx.x * blockDim.x + threadIdx.x;
    if (idx < LL * BB * HH) g_mki[idx] = 0;
    if (idx >= NROW * DD) return;
    int row = idx / DD;
    int col = idx - row * DD;
    int t = row & (TT - 1);
    const float* xr = x + row * IN_DIM;
    float s = bp[col] + pos[t * DD + col];
#pragma unroll
    for (int i = 0; i < IN_DIM; i++)
        s = fmaf(xr[i], Wp[i * DD + col], s);
    g_h[idx] = s;
    g_h16[idx] = __float2half_rn(s);
}

// ============================================================
// 2. QKV GEMM (fp16 m16n8k16): g_qkvh = g_h16 @ W^T + bqkv
//    Epilogue on K-column blocks also computes max ||k||^2 per
//    (b,h) via warp reduce + atomicMax (float-bits as int).
// ============================================================
#define QST_A 2560      // words per A stage (128*20)
#define QST_B 2560      // words per B stage (128*20)
#define QSMEM_BYTES ((4*(QST_A+QST_B))*4)

extern __shared__ float dynsmem[];

__global__ __launch_bounds__(256, 2)
void qkv_gemm_kernel(int layer, const float* __restrict__ bias) {
    unsigned* As = (unsigned*)dynsmem;          // [4][128][20]
    unsigned* Bs = As + 4 * QST_A;              // [4][128][20]
    const __half* __restrict__ A = g_h16;
    const __half* __restrict__ Bmat = g_wqkv16 + (size_t)layer * 3 * DD * DD; // [n][k]
    const int N = 3 * DD;

    const int tid  = threadIdx.x;
    const int lane = tid & 31;
    const int g    = lane >> 2;
    const int q    = lane & 3;
    const int warp = tid >> 5;
    const int wm   = (warp & 1) * 64;
    const int wn   = (warp >> 1) * 32;
    const int bm   = blockIdx.y * 128;
    const int bn   = blockIdx.x * 128;

    auto issue = [&](int s) {
        int k0 = s * 32;
        unsigned* Asb = As + (s & 3) * QST_A;
        unsigned* Bsb = Bs + (s & 3) * QST_B;
#pragma unroll
        for (int p = 0; p < 2; p++) {
            int c = tid + p * 256;
            int r = c >> 2, cw = (c & 3) * 4;
            cp16(&Asb[r * 20 + cw], A + (size_t)(bm + r) * DD + k0 + cw * 2);
        }
#pragma unroll
        for (int p = 0; p < 2; p++) {
            int c = tid + p * 256;
            int r = c >> 2, cw = (c & 3) * 4;
            cp16(&Bsb[r * 20 + cw], Bmat + (size_t)(bn + r) * DD + k0 + cw * 2);
        }
    };

    float acc[4][4][4];
#pragma unroll
    for (int mc = 0; mc < 4; mc++)
#pragma unroll
        for (int nc = 0; nc < 4; nc++)
#pragma unroll
            for (int i = 0; i < 4; i++) acc[mc][nc][i] = 0.0f;

    issue(0); cp_commit();
    issue(1); cp_commit();
    issue(2); cp_commit();

    const int NS = DD / 32;   // 8
    for (int s = 0; s < NS; s++) {
        cp_wait<2>();
        __syncthreads();
        if (s + 3 < NS) issue(s + 3);
        cp_commit();

        const unsigned* Asb = As + (s & 3) * QST_A;
        const unsigned* Bsb = Bs + (s & 3) * QST_B;
#pragma unroll
        for (int kc = 0; kc < 2; kc++) {
            int kb = kc * 8;
            unsigned af[4][4], bf[4][2];
#pragma unroll
            for (int mc = 0; mc < 4; mc++) {
                int r = wm + mc * 16 + g;
                af[mc][0] = Asb[r * 20 + kb + q];
                af[mc][1] = Asb[(r + 8) * 20 + kb + q];
                af[mc][2] = Asb[r * 20 + kb + q + 4];
                af[mc][3] = Asb[(r + 8) * 20 + kb + q + 4];
            }
#pragma unroll
            for (int nc = 0; nc < 4; nc++) {
                int cc = wn + nc * 8 + g;
                bf[nc][0] = Bsb[cc * 20 + kb + q];
                bf[nc][1] = Bsb[cc * 20 + kb + q + 4];
            }
#pragma unroll
            for (int mc = 0; mc < 4; mc++)
#pragma unroll
                for (int nc = 0; nc < 4; nc++)
                    mma16h(acc[mc][nc], af[mc], bf[nc][0], bf[nc][1]);
        }
    }

    // epilogue: + bias, pack to fp16; K blocks also track max ||k||^2
    unsigned* qkw = reinterpret_cast<unsigned*>(g_qkvh);
    const bool isK = (bn == 256 || bn == 384);   // K cols [256,512)
    float mxss = 0.0f;
#pragma unroll
    for (int mc = 0; mc < 4; mc++) {
        float ssA = 0.0f, ssB = 0.0f;
#pragma unroll
        for (int nc = 0; nc < 4; nc++) {
            int row = bm + wm + mc * 16 + g;
            int col = bn + wn + nc * 8 + 2 * q;
            float2 bi = *(const float2*)&bias[col];
            float v0 = acc[mc][nc][0] + bi.x;
            float v1 = acc[mc][nc][1] + bi.y;
            float v2 = acc[mc][nc][2] + bi.x;
            float v3 = acc[mc][nc][3] + bi.y;
            qkw[(size_t)row * (N/2) + col/2]       = pkh2(v0, v1);
            qkw[(size_t)(row + 8) * (N/2) + col/2] = pkh2(v2, v3);
            ssA = fmaf(v0, v0, fmaf(v1, v1, ssA));
            ssB = fmaf(v2, v2, fmaf(v3, v3, ssB));
        }
        if (isK) {
            ssA += __shfl_xor_sync(0xffffffffu, ssA, 1);
            ssA += __shfl_xor_sync(0xffffffffu, ssA, 2);
            ssB += __shfl_xor_sync(0xffffffffu, ssB, 1);
            ssB += __shfl_xor_sync(0xffffffffu, ssB, 2);
            mxss = fmaxf(mxss, fmaxf(ssA, ssB));
        }
    }
    if (isK) {
        mxss = fmaxf(mxss, __shfl_xor_sync(0xffffffffu, mxss, 4));
        mxss = fmaxf(mxss, __shfl_xor_sync(0xffffffffu, mxss, 8));
        mxss = fmaxf(mxss, __shfl_xor_sync(0xffffffffu, mxss, 16));
        if (lane == 0) {
            int b = bm >> 10;                       // 1024 rows per batch
            int hd = (bn + wn - 256) >> 5;          // head of this warp
            atomicMax(&g_mki[layer * BB * HH + b * HH + hd], __float_as_int(mxss));
        }
    }
}

// ============================================================
// 3. Flash attention, fp16 MMA, BOUNDED no-running-max softmax:
//    p' = exp2(s*qs + (B - ||q||*M_k*qs)) <= 2^11 (Cauchy-Schwarz).
// ============================================================
__global__ __launch_bounds__(128, 4)
void attn_tc_kernel(int layer) {
    __shared__ unsigned Khs[2][32][20];   // [key][dim half2-word]
    __shared__ unsigned Vhs[2][16][40];   // [keypair][dim]

    const int tid  = threadIdx.x;
    const int lane = tid & 31;
    const int g    = lane >> 2;
    const int q    = lane & 3;
    const int warp = tid >> 5;
    const int h    = blockIdx.y;
    const int b    = blockIdx.z;
    const int qrow0 = blockIdx.x * 128 + warp * 32;

    const float qs = 0.17677669529663687f * 1.4426950408889634f; // scale*log2e
    const int RW = 3 * DD;
    const int RWW = RW / 2;

    const __half* kg = g_qkvh + (size_t)b * TT * RW + DD + h * DK;
    const __half* vg = g_qkvh + (size_t)b * TT * RW + 2 * DD + h * DK;
    const unsigned* qw = reinterpret_cast<const unsigned*>(
        g_qkvh + (size_t)(b * TT + qrow0) * RW + h * DK);

    const int kkey = tid >> 2;            // 0..31
    const int kwg  = (tid & 3) * 4;       // word offset 0,4,8,12
    const int vj  = tid >> 3;             // 0..15
    const int vdg = (tid & 7) * 4;        // dims vdg..vdg+3

    // prologue tile 0
    cp16(&Khs[0][kkey][kwg], kg + (size_t)kkey * RW + kwg * 2);
    cp_commit();
    {
        uint2 wa = *(const uint2*)(vg + (size_t)(2 * vj) * RW + vdg);
        uint2 wb = *(const uint2*)(vg + (size_t)(2 * vj + 1) * RW + vdg);
        uint4 p;
        p.x = prmt(wa.x, wb.x, 0x5410); p.y = prmt(wa.x, wb.x, 0x7632);
        p.z = prmt(wa.y, wb.y, 0x5410); p.w = prmt(wa.y, wb.y, 0x7632);
        *(uint4*)&Vhs[0][vj][vdg] = p;
    }

    // Q A-fragments (fp16 words straight from memory)
    unsigned qa[2][2][4];
#pragma unroll
    for (int mc = 0; mc < 2; mc++)
#pragma unroll
        for (int kc = 0; kc < 2; kc++) {
            int r = mc * 16 + g;
            qa[mc][kc][0] = qw[(size_t)r * RWW + kc * 8 + q];
            qa[mc][kc][1] = qw[(size_t)(r + 8) * RWW + kc * 8 + q];
            qa[mc][kc][2] = qw[(size_t)r * RWW + kc * 8 + q + 4];
            qa[mc][kc][3] = qw[(size_t)(r + 8) * RWW + kc * 8 + q + 4];
        }

    // Per-row exp bias: eb = 11 - ||q||*M_k*qs
    const float Mk = sqrtf(__int_as_float(g_mki[layer * BB * HH + b * HH + h]));
    float eb[2][2];
#pragma unroll
    for (int mc = 0; mc < 2; mc++) {
        float a0 = 0.0f, a1 = 0.0f;
#pragma unroll
        for (int kc = 0; kc < 2; kc++) {
            float2 f;
            f = __half22float2(*reinterpret_cast<__half2*>(&qa[mc][kc][0]));
            a0 = fmaf(f.x, f.x, fmaf(f.y, f.y, a0));
            f = __half22float2(*reinterpret_cast<__half2*>(&qa[mc][kc][2]));
            a0 = fmaf(f.x, f.x, fmaf(f.y, f.y, a0));
            f = __half22float2(*reinterpret_cast<__half2*>(&qa[mc][kc][1]));
            a1 = fmaf(f.x, f.x, fmaf(f.y, f.y, a1));
            f = __half22float2(*reinterpret_cast<__half2*>(&qa[mc][kc][3]));
            a1 = fmaf(f.x, f.x, fmaf(f.y, f.y, a1));
        }
        a0 += __shfl_xor_sync(0xffffffffu, a0, 1);
        a0 += __shfl_xor_sync(0xffffffffu, a0, 2);
        a1 += __shfl_xor_sync(0xffffffffu, a1, 1);
        a1 += __shfl_xor_sync(0xffffffffu, a1, 2);
        eb[mc][0] = 11.0f - sqrtf(a0) * Mk * qs;
        eb[mc][1] = 11.0f - sqrtf(a1) * Mk * qs;
    }

    float oacc[2][4][4];
    float lp[2][2];
#pragma unroll
    for (int mc = 0; mc < 2; mc++) {
        lp[mc][0] = 0.0f; lp[mc][1] = 0.0f;
#pragma unroll
        for (int nc = 0; nc < 4; nc++)
#pragma unroll
            for (int i = 0; i < 4; i++) oacc[mc][nc][i] = 0.0f;
    }

    const int NT = TT / 32;
    for (int t = 0; t < NT; t++) {
        int buf = t & 1;
        int nb  = buf ^ 1;
        uint2 wa, wb;
        if (t + 1 < NT) {
            int k0 = (t + 1) * 32;
            cp16(&Khs[nb][kkey][kwg], kg + (size_t)(k0 + kkey) * RW + kwg * 2);
            cp_commit();
            wa = *(const uint2*)(vg + (size_t)(k0 + 2 * vj) * RW + vdg);
            wb = *(const uint2*)(vg + (size_t)(k0 + 2 * vj + 1) * RW + vdg);
            cp_wait<1>();
        } else {
            cp_wait<0>();
        }
        __syncthreads();

        // ---- S = Q K^T (fp16 k16) ----
        float sf[2][4][4];
#pragma unroll
        for (int mc = 0; mc < 2; mc++)
#pragma unroll
            for (int nc = 0; nc < 4; nc++)
#pragma unroll
                for (int i = 0; i < 4; i++) sf[mc][nc][i] = 0.0f;

#pragma unroll
        for (int nc = 0; nc < 4; nc++) {
#pragma unroll
            for (int kc = 0; kc < 2; kc++) {
                unsigned b0 = Khs[buf][nc * 8 + g][kc * 8 + q];
                unsigned b1 = Khs[buf][nc * 8 + g][kc * 8 + q + 4];
                mma16h(sf[0][nc], qa[0][kc], b0, b1);
                mma16h(sf[1][nc], qa[1][kc], b0, b1);
            }
        }

        // ---- bounded softmax: p' = exp2(s*qs + eb), accumulate l ----
#pragma unroll
        for (int mc = 0; mc < 2; mc++) {
            float e0 = eb[mc][0], e1 = eb[mc][1];
            float s0 = 0.0f, s1 = 0.0f;
#pragma unroll
            for (int nc = 0; nc < 4; nc++) {
                sf[mc][nc][0] = exp2f(fmaf(sf[mc][nc][0], qs, e0));
                sf[mc][nc][1] = exp2f(fmaf(sf[mc][nc][1], qs, e0));
                sf[mc][nc][2] = exp2f(fmaf(sf[mc][nc][2], qs, e1));
                sf[mc][nc][3] = exp2f(fmaf(sf[mc][nc][3], qs, e1));
                s0 += sf[mc][nc][0] + sf[mc][nc][1];
                s1 += sf[mc][nc][2] + sf[mc][nc][3];
            }
            lp[mc][0] += s0;
            lp[mc][1] += s1;
        }

        // ---- O += P V  (fp16; P pack = C-frag identity) ----
#pragma unroll
        for (int kk = 0; kk < 2; kk++) {
            unsigned pa0[4], pa1[4];
            pa0[0] = pkh2(sf[0][2*kk][0],   sf[0][2*kk][1]);
            pa0[1] = pkh2(sf[0][2*kk][2],   sf[0][2*kk][3]);
            pa0[2] = pkh2(sf[0][2*kk+1][0], sf[0][2*kk+1][1]);
            pa0[3] = pkh2(sf[0][2*kk+1][2], sf[0][2*kk+1][3]);
            pa1[0] = pkh2(sf[1][2*kk][0],   sf[1][2*kk][1]);
            pa1[1] = pkh2(sf[1][2*kk][2],   sf[1][2*kk][3]);
            pa1[2] = pkh2(sf[1][2*kk+1][0], sf[1][2*kk+1][1]);
            pa1[3] = pkh2(sf[1][2*kk+1][2], sf[1][2*kk+1][3]);
#pragma unroll
            for (int dn = 0; dn < 4; dn++) {
                unsigned b0 = Vhs[buf][8*kk + q][dn * 8 + g];
                unsigned b1 = Vhs[buf][8*kk + q + 4][dn * 8 + g];
                mma16h(oacc[0][dn], pa0, b0, b1);
                mma16h(oacc[1][dn], pa1, b0, b1);
            }
        }

        // commit prefetched V tile
        if (t + 1 < NT) {
            uint4 p;
            p.x = prmt(wa.x, wb.x, 0x5410); p.y = prmt(wa.x, wb.x, 0x7632);
            p.z = prmt(wa.y, wb.y, 0x5410); p.w = prmt(wa.y, wb.y, 0x7632);
            *(uint4*)&Vhs[nb][vj][vdg] = p;
        }
        __syncthreads();
    }

    // ---- deferred l reduction (once), normalize, store fp16 ----
    unsigned* ow = reinterpret_cast<unsigned*>(g_attnh);
#pragma unroll
    for (int mc = 0; mc < 2; mc++) {
        float l0 = lp[mc][0], l1 = lp[mc][1];
        l0 += __shfl_xor_sync(0xffffffffu, l0, 1);
        l0 += __shfl_xor_sync(0xffffffffu, l0, 2);
        l1 += __shfl_xor_sync(0xffffffffu, l1, 1);
        l1 += __shfl_xor_sync(0xffffffffu, l1, 2);
        float inv0 = 1.0f / l0;
        float inv1 = 1.0f / l1;
        int r0 = b * TT + qrow0 + mc * 16 + g;
#pragma unroll
        for (int dn = 0; dn < 4; dn++) {
            int col = h * DK + dn * 8 + 2 * q;
            ow[(size_t)r0 * (DD/2) + col/2] =
                pkh2(oacc[mc][dn][0] * inv0, oacc[mc][dn][1] * inv0);
            ow[(size_t)(r0 + 8) * (DD/2) + col/2] =
                pkh2(oacc[mc][dn][2] * inv1, oacc[mc][dn][3] * inv1);
        }
    }
}

// ============================================================
// 4. Wout GEMM (fp16) + bias + residual + LayerNorm, fused.
//    RETILED: block 32x256 (full rows), 8 warps of 32x32,
//    grid 256 blocks = one full wave at 2 blocks/SM.
// ============================================================
#define WST_A 640       // words per A stage (32*20)
#define WST_B 5120      // words per B stage (256*20)
#define WRED_OFF (4*(WST_A+WST_B))
#define WSMEM_BYTES ((WRED_OFF+512)*4)

__global__ __launch_bounds__(256, 2)
void wout_ln_kernel(int layer, const float* __restrict__ bias,
                    const float* __restrict__ gamma,
                    const float* __restrict__ beta) {
    unsigned* As = (unsigned*)dynsmem;
    unsigned* Bs = As + 4 * WST_A;
    float* redS = dynsmem + WRED_OFF;       // [32][8]
    float* redQ = redS + 256;               // [32][8]
    const __half* __restrict__ A = g_attnh;
    const __half* __restrict__ Bmat = g_wout16 + (size_t)layer * DD * DD; // [n][k]

    const int tid  = threadIdx.x;
    const int lane = tid & 31;
    const int g    = lane >> 2;
    const int q    = lane & 3;
    const int warp = tid >> 5;
    const int wn   = warp * 32;
    const int bm   = blockIdx.x * 32;

    auto issue = [&](int s) {
        int k0 = s * 32;
        unsigned* Asb = As + (s & 3) * WST_A;
        unsigned* Bsb = Bs + (s & 3) * WST_B;
        if (tid < 128) {
            int r = tid >> 2, cw = (tid & 3) * 4;
            cp16(&Asb[r * 20 + cw], A + (size_t)(bm + r) * DD + k0 + cw * 2);
        }
#pragma unroll
        for (int p = 0; p < 4; p++) {
            int c = tid + p * 256;
            int r = c >> 2, cw = (c & 3) * 4;
            cp16(&Bsb[r * 20 + cw], Bmat + (size_t)r * DD + k0 + cw * 2);
        }
    };

    float acc[2][4][4];
#pragma unroll
    for (int mc = 0; mc < 2; mc++)
#pragma unroll
        for (int nc = 0; nc < 4; nc++)
#pragma unroll
            for (int i = 0; i < 4; i++) acc[mc][nc][i] = 0.0f;

    issue(0); cp_commit();
    issue(1); cp_commit();
    issue(2); cp_commit();

    const int NS = DD / 32;    // 8
    for (int s = 0; s < NS; s++) {
        cp_wait<2>();
        __syncthreads();
        if (s + 3 < NS) issue(s + 3);
        cp_commit();

        const unsigned* Asb = As + (s & 3) * WST_A;
        const unsigned* Bsb = Bs + (s & 3) * WST_B;
#pragma unroll
        for (int kc = 0; kc < 2; kc++) {
            int kb = kc * 8;
            unsigned af[2][4], bf[4][2];
#pragma unroll
            for (int mc = 0; mc < 2; mc++) {
                int r = mc * 16 + g;
                af[mc][0] = Asb[r * 20 + kb + q];
                af[mc][1] = Asb[(r + 8) * 20 + kb + q];
                af[mc][2] = Asb[r * 20 + kb + q + 4];
                af[mc][3] = Asb[(r + 8) * 20 + kb + q + 4];
            }
#pragma unroll
            for (int nc = 0; nc < 4; nc++) {
                int cc = wn + nc * 8 + g;
                bf[nc][0] = Bsb[cc * 20 + kb + q];
                bf[nc][1] = Bsb[cc * 20 + kb + q + 4];
            }
#pragma unroll
            for (int mc = 0; mc < 2; mc++)
#pragma unroll
                for (int nc = 0; nc < 4; nc++)
                    mma16h(acc[mc][nc], af[mc], bf[nc][0], bf[nc][1]);
        }
    }
    __syncthreads();

    // epilogue part 1: + bias + residual (fp32), partial row stats
#pragma unroll
    for (int mc = 0; mc < 2; mc++) {
        int rlo = bm + mc * 16 + g;
        float ssA = 0.f, sqA = 0.f, ssB = 0.f, sqB = 0.f;
#pragma unroll
        for (int nc = 0; nc < 4; nc++) {
            int col = wn + nc * 8 + 2 * q;
            float2 bi = *(const float2*)&bias[col];
            float2 h0 = *(const float2*)&g_h[(size_t)rlo * DD + col];
            float2 h1 = *(const float2*)&g_h[(size_t)(rlo + 8) * DD + col];
            acc[mc][nc][0] += bi.x + h0.x;
            acc[mc][nc][1] += bi.y + h0.y;
            acc[mc][nc][2] += bi.x + h1.x;
            acc[mc][nc][3] += bi.y + h1.y;
            ssA += acc[mc][nc][0] + acc[mc][nc][1];
            sqA += acc[mc][nc][0]*acc[mc][nc][0] + acc[mc][nc][1]*acc[mc][nc][1];
            ssB += acc[mc][nc][2] + acc[mc][nc][3];
            sqB += acc[mc][nc][2]*acc[mc][nc][2] + acc[mc][nc][3]*acc[mc][nc][3];
        }
        ssA += __shfl_xor_sync(0xffffffffu, ssA, 1); ssA += __shfl_xor_sync(0xffffffffu, ssA, 2);
        sqA += __shfl_xor_sync(0xffffffffu, sqA, 1); sqA += __shfl_xor_sync(0xffffffffu, sqA, 2);
        ssB += __shfl_xor_sync(0xffffffffu, ssB, 1); ssB += __shfl_xor_sync(0xffffffffu, ssB, 2);
        sqB += __shfl_xor_sync(0xffffffffu, sqB, 1); sqB += __shfl_xor_sync(0xffffffffu, sqB, 2);
        if (q == 0) {
            int rl = mc * 16 + g;
            redS[rl * 8 + warp] = ssA;  redQ[rl * 8 + warp] = sqA;
            redS[(rl + 8) * 8 + warp] = ssB;  redQ[(rl + 8) * 8 + warp] = sqB;
        }
    }
    __syncthreads();

    // epilogue part 2: normalize + store (fp32 + fp16)
    unsigned* hw = reinterpret_cast<unsigned*>(g_h16);
#pragma unroll
    for (int mc = 0; mc < 2; mc++) {
        int rlA = mc * 16 + g;
        int rlB = rlA + 8;
        float sA = 0.f, qA = 0.f, sB = 0.f, qB = 0.f;
#pragma unroll
        for (int w = 0; w < 8; w++) {
            sA += redS[rlA * 8 + w];  qA += redQ[rlA * 8 + w];
            sB += redS[rlB * 8 + w];  qB += redQ[rlB * 8 + w];
        }
        float muA = sA * (1.0f / DD);
        float muB = sB * (1.0f / DD);
        float rsA = rsqrtf(qA * (1.0f / DD) - muA * muA + LN_EPS);
        float rsB = rsqrtf(qB * (1.0f / DD) - muB * muB + LN_EPS);
        int rowA = bm + rlA;
#pragma unroll
        for (int nc = 0; nc < 4; nc++) {
            int col = wn + nc * 8 + 2 * q;
            float2 ga = *(const float2*)&gamma[col];
            float2 be = *(const float2*)&beta[col];
            float v0 = (acc[mc][nc][0] - muA) * rsA * ga.x + be.x;
            float v1 = (acc[mc][nc][1] - muA) * rsA * ga.y + be.y;
            float v2 = (acc[mc][nc][2] - muB) * rsB * ga.x + be.x;
            float v3 = (acc[mc][nc][3] - muB) * rsB * ga.y + be.y;
            *(float2*)&g_h[(size_t)rowA * DD + col]       = make_float2(v0, v1);
            *(float2*)&g_h[(size_t)(rowA + 8) * DD + col] = make_float2(v2, v3);
            hw[(size_t)rowA * (DD/2) + col/2]       = pkh2(v0, v1);
            hw[(size_t)(rowA + 8) * (DD/2) + col/2] = pkh2(v2, v3);
        }
    }
}

// ============================================================
// 5. Head
// ============================================================
__global__ void head_kernel(const float* __restrict__ Wo,
                            const float* __restrict__ bo,
                            float* __restrict__ out) {
    int b = blockIdx.x / 3;
    int j = blockIdx.x - b * 3;
    int lane = threadIdx.x;
    const float* hr = g_h + (size_t)(b * TT + (TT - 1)) * DD;
    float s = 0.0f;
    for (int d = lane; d < DD; d += 32)
        s = fmaf(hr[d], Wo[d * 3 + j], s);
#pragma unroll
    for (int o = 16; o > 0; o >>= 1)
        s += __shfl_xor_sync(0xffffffffu, s, o);
    if (lane == 0) out[b * 3 + j] = s + bo[j];
}

// ============================================================
// launch
// ============================================================
extern "C" void kernel_launch(void* const* d_in, const int* in_sizes, int n_in,
                              void* d_out, int out_size) {
    const float* x    = (const float*)d_in[0];
    const float* Wp   = (const float*)d_in[1];
    const float* bp   = (const float*)d_in[2];
    const float* pos  = (const float*)d_in[3];
    const float* Wqkv = (const float*)d_in[4];
    const float* bqkv = (const float*)d_in[5];
    const float* Wout = (const float*)d_in[6];
    const float* bout = (const float*)d_in[7];
    const float* ln_g = (const float*)d_in[8];
    const float* ln_b = (const float*)d_in[9];
    const float* Wo   = (const float*)d_in[10];
    const float* bo   = (const float*)d_in[11];
    float* out = (float*)d_out;

    cudaFuncSetAttribute(qkv_gemm_kernel, cudaFuncAttributeMaxDynamicSharedMemorySize, QSMEM_BYTES);
    cudaFuncSetAttribute(wout_ln_kernel,  cudaFuncAttributeMaxDynamicSharedMemorySize, WSMEM_BYTES);

    __half* d_wqkv16 = nullptr;
    __half* d_wout16 = nullptr;
    cudaGetSymbolAddress((void**)&d_wqkv16, g_wqkv16);
    cudaGetSymbolAddress((void**)&d_wout16, g_wout16);

    transp_kernel<<<dim3(DD/32, (3*DD)/32, LL), dim3(32, 8)>>>(Wqkv, d_wqkv16, 3*DD);
    transp_kernel<<<dim3(DD/32, DD/32, LL),     dim3(32, 8)>>>(Wout, d_wout16, DD);
    proj_kernel<<<(NROW * DD + 255) / 256, 256>>>(x, Wp, bp, pos);

    for (int l = 0; l < LL; l++) {
        qkv_gemm_kernel<<<dim3((3 * DD) / 128, NROW / 128), 256, QSMEM_BYTES>>>(
            l, bqkv + (size_t)l * 3 * DD);
        attn_tc_kernel<<<dim3(TT / 128, HH, BB), 128>>>(l);
        wout_ln_kernel<<<NROW / 32, 256, WSMEM_BYTES>>>(
            l, bout + (size_t)l * DD, ln_g + (size_t)l * DD, ln_b + (size_t)l * DD);
    }

    head_kernel<<<24, 32>>>(Wo, bo, out);
}

// round 12
// speedup vs baseline: 8.0108x; 1.0513x over previous
#include <cuda_runtime.h>
#include <cuda_fp16.h>
#include <math.h>

// Problem constants
#define BB 8
#define TT 1024
#define IN_DIM 16
#define DD 256
#define HH 8
#define DK 32
#define LL 4
#define NROW (BB*TT)
#define LN_EPS 1e-5f

// -------- scratch (device globals) --------
__device__ float  g_h[NROW*DD];           // fp32 residual stream
__device__ __half g_h16[NROW*DD];         // fp16 hidden (GEMM A input)
__device__ __half g_qkvh[NROW*3*DD];      // fp16 qkv
__device__ __half g_attnh[NROW*DD];       // fp16 attention out
__device__ __half g_wqkv16[LL*3*DD*DD];   // fp16 Wqkv TRANSPOSED [l][n][k]
__device__ __half g_wout16[LL*DD*DD];     // fp16 Wout TRANSPOSED [l][n][k]
__device__ int    g_mki[LL*BB*HH];        // per (l,b,h) max ||k||^2 (float bits)

// -------- helpers --------
__device__ __forceinline__ void mma16h(float* d, const unsigned* a, unsigned b0, unsigned b1) {
    asm volatile(
        "mma.sync.aligned.m16n8k16.row.col.f32.f16.f16.f32 "
        "{%0,%1,%2,%3}, {%4,%5,%6,%7}, {%8,%9}, {%0,%1,%2,%3};\n"
        : "+f"(d[0]), "+f"(d[1]), "+f"(d[2]), "+f"(d[3])
        : "r"(a[0]), "r"(a[1]), "r"(a[2]), "r"(a[3]), "r"(b0), "r"(b1));
}
__device__ __forceinline__ unsigned pkh2(float lo, float hi) {
    __half2 h = __floats2half2_rn(lo, hi);
    return *reinterpret_cast<unsigned*>(&h);
}
__device__ __forceinline__ unsigned ex2h2(unsigned x) {
    unsigned r;
    asm("ex2.approx.f16x2 %0, %1;" : "=r"(r) : "r"(x));
    return r;
}
__device__ __forceinline__ unsigned prmt(unsigned a, unsigned b, unsigned sel) {
    unsigned r;
    asm("prmt.b32 %0, %1, %2, %3;" : "=r"(r) : "r"(a), "r"(b), "r"(sel));
    return r;
}
__device__ __forceinline__ void cp16(void* smem, const void* g) {
    unsigned a = (unsigned)__cvta_generic_to_shared(smem);
    asm volatile("cp.async.cg.shared.global [%0], [%1], 16;\n" :: "r"(a), "l"(g));
}
__device__ __forceinline__ void cp_commit() { asm volatile("cp.async.commit_group;\n"); }
template<int N> __device__ __forceinline__ void cp_wait() {
    asm volatile("cp.async.wait_group %0;\n" :: "n"(N));
}

// ============================================================
// 0. Weight transpose + fp16 convert (once per launch).
// ============================================================
__global__ void transp_kernel(const float* __restrict__ src,
                              __half* __restrict__ dst, int N) {
    __shared__ float tile[32][33];
    int k0 = blockIdx.x * 32, n0 = blockIdx.y * 32;
    const float* s = src + (size_t)blockIdx.z * DD * N;
    __half* d = dst + (size_t)blockIdx.z * DD * N;
    for (int i = threadIdx.y; i < 32; i += 8)
        tile[i][threadIdx.x] = s[(size_t)(k0 + i) * N + n0 + threadIdx.x];
    __syncthreads();
    for (int i = threadIdx.y; i < 32; i += 8)
        d[(size_t)(n0 + i) * DD + k0 + threadIdx.x] = __float2half_rn(tile[threadIdx.x][i]);
}

// ============================================================
// 1. Projection: h = x @ Wp + bp + pos  (fp32 + fp16 copy)
//    Also zeroes the per-layer max-key-norm accumulators.
// ============================================================
__global__ void proj_kernel(const float* __restrict__ x,
                            const float* __restrict__ Wp,
                            const float* __restrict__ bp,
                            const float* __restrict__ pos) {
    int idx = blockIdx.x * blockDim.x + threadIdx.x;
    if (idx < LL * BB * HH) g_mki[idx] = 0;
    if (idx >= NROW * DD) return;
    int row = idx / DD;
    int col = idx - row * DD;
    int t = row & (TT - 1);
    const float* xr = x + row * IN_DIM;
    float s = bp[col] + pos[t * DD + col];
#pragma unroll
    for (int i = 0; i < IN_DIM; i++)
        s = fmaf(xr[i], Wp[i * DD + col], s);
    g_h[idx] = s;
    g_h16[idx] = __float2half_rn(s);
}

// ============================================================
// 2. QKV GEMM (fp16 m16n8k16): g_qkvh = g_h16 @ W^T + bqkv
//    K-column blocks also track max ||k||^2 per (b,h).
// ============================================================
#define QST_A 2560      // words per A stage (128*20)
#define QST_B 2560      // words per B stage (128*20)
#define QSMEM_BYTES ((4*(QST_A+QST_B))*4)

extern __shared__ float dynsmem[];

__global__ __launch_bounds__(256, 2)
void qkv_gemm_kernel(int layer, const float* __restrict__ bias) {
    unsigned* As = (unsigned*)dynsmem;          // [4][128][20]
    unsigned* Bs = As + 4 * QST_A;              // [4][128][20]
    const __half* __restrict__ A = g_h16;
    const __half* __restrict__ Bmat = g_wqkv16 + (size_t)layer * 3 * DD * DD; // [n][k]
    const int N = 3 * DD;

    const int tid  = threadIdx.x;
    const int lane = tid & 31;
    const int g    = lane >> 2;
    const int q    = lane & 3;
    const int warp = tid >> 5;
    const int wm   = (warp & 1) * 64;
    const int wn   = (warp >> 1) * 32;
    const int bm   = blockIdx.y * 128;
    const int bn   = blockIdx.x * 128;

    auto issue = [&](int s) {
        int k0 = s * 32;
        unsigned* Asb = As + (s & 3) * QST_A;
        unsigned* Bsb = Bs + (s & 3) * QST_B;
#pragma unroll
        for (int p = 0; p < 2; p++) {
            int c = tid + p * 256;
            int r = c >> 2, cw = (c & 3) * 4;
            cp16(&Asb[r * 20 + cw], A + (size_t)(bm + r) * DD + k0 + cw * 2);
        }
#pragma unroll
        for (int p = 0; p < 2; p++) {
            int c = tid + p * 256;
            int r = c >> 2, cw = (c & 3) * 4;
            cp16(&Bsb[r * 20 + cw], Bmat + (size_t)(bn + r) * DD + k0 + cw * 2);
        }
    };

    float acc[4][4][4];
#pragma unroll
    for (int mc = 0; mc < 4; mc++)
#pragma unroll
        for (int nc = 0; nc < 4; nc++)
#pragma unroll
            for (int i = 0; i < 4; i++) acc[mc][nc][i] = 0.0f;

    issue(0); cp_commit();
    issue(1); cp_commit();
    issue(2); cp_commit();

    const int NS = DD / 32;   // 8
    for (int s = 0; s < NS; s++) {
        cp_wait<2>();
        __syncthreads();
        if (s + 3 < NS) issue(s + 3);
        cp_commit();

        const unsigned* Asb = As + (s & 3) * QST_A;
        const unsigned* Bsb = Bs + (s & 3) * QST_B;
#pragma unroll
        for (int kc = 0; kc < 2; kc++) {
            int kb = kc * 8;
            unsigned af[4][4], bf[4][2];
#pragma unroll
            for (int mc = 0; mc < 4; mc++) {
                int r = wm + mc * 16 + g;
                af[mc][0] = Asb[r * 20 + kb + q];
                af[mc][1] = Asb[(r + 8) * 20 + kb + q];
                af[mc][2] = Asb[r * 20 + kb + q + 4];
                af[mc][3] = Asb[(r + 8) * 20 + kb + q + 4];
            }
#pragma unroll
            for (int nc = 0; nc < 4; nc++) {
                int cc = wn + nc * 8 + g;
                bf[nc][0] = Bsb[cc * 20 + kb + q];
                bf[nc][1] = Bsb[cc * 20 + kb + q + 4];
            }
#pragma unroll
            for (int mc = 0; mc < 4; mc++)
#pragma unroll
                for (int nc = 0; nc < 4; nc++)
                    mma16h(acc[mc][nc], af[mc], bf[nc][0], bf[nc][1]);
        }
    }

    // epilogue: + bias, pack to fp16; K blocks also track max ||k||^2
    unsigned* qkw = reinterpret_cast<unsigned*>(g_qkvh);
    const bool isK = (bn == 256 || bn == 384);   // K cols [256,512)
    float mxss = 0.0f;
#pragma unroll
    for (int mc = 0; mc < 4; mc++) {
        float ssA = 0.0f, ssB = 0.0f;
#pragma unroll
        for (int nc = 0; nc < 4; nc++) {
            int row = bm + wm + mc * 16 + g;
            int col = bn + wn + nc * 8 + 2 * q;
            float2 bi = *(const float2*)&bias[col];
            float v0 = acc[mc][nc][0] + bi.x;
            float v1 = acc[mc][nc][1] + bi.y;
            float v2 = acc[mc][nc][2] + bi.x;
            float v3 = acc[mc][nc][3] + bi.y;
            qkw[(size_t)row * (N/2) + col/2]       = pkh2(v0, v1);
            qkw[(size_t)(row + 8) * (N/2) + col/2] = pkh2(v2, v3);
            ssA = fmaf(v0, v0, fmaf(v1, v1, ssA));
            ssB = fmaf(v2, v2, fmaf(v3, v3, ssB));
        }
        if (isK) {
            ssA += __shfl_xor_sync(0xffffffffu, ssA, 1);
            ssA += __shfl_xor_sync(0xffffffffu, ssA, 2);
            ssB += __shfl_xor_sync(0xffffffffu, ssB, 1);
            ssB += __shfl_xor_sync(0xffffffffu, ssB, 2);
            mxss = fmaxf(mxss, fmaxf(ssA, ssB));
        }
    }
    if (isK) {
        mxss = fmaxf(mxss, __shfl_xor_sync(0xffffffffu, mxss, 4));
        mxss = fmaxf(mxss, __shfl_xor_sync(0xffffffffu, mxss, 8));
        mxss = fmaxf(mxss, __shfl_xor_sync(0xffffffffu, mxss, 16));
        if (lane == 0) {
            int b = bm >> 10;                       // 1024 rows per batch
            int hd = (bn + wn - 256) >> 5;          // head of this warp
            atomicMax(&g_mki[layer * BB * HH + b * HH + hd], __float_as_int(mxss));
        }
    }
}

// ============================================================
// 3. Flash attention, fp16 MMA, bounded softmax via Cauchy-Schwarz,
//    ex2.approx.f16x2 (2 exps / MUFU op, result pre-packed for PV),
//    l computed by ones-column MMA (cols 32..39 of V tile hold 1.0h;
//    every C column of that n8 tile = row-sum of P -> no shuffles).
// ============================================================
__global__ __launch_bounds__(128, 4)
void attn_tc_kernel(int layer) {
    __shared__ unsigned Khs[2][32][20];   // [key][dim half2-word]
    __shared__ unsigned Vhs[2][16][40];   // [keypair][dim]; cols 32..39 = ones

    const int tid  = threadIdx.x;
    const int lane = tid & 31;
    const int g    = lane >> 2;
    const int q    = lane & 3;
    const int warp = tid >> 5;
    const int h    = blockIdx.y;
    const int b    = blockIdx.z;
    const int qrow0 = blockIdx.x * 128 + warp * 32;

    const float qs = 0.17677669529663687f * 1.4426950408889634f; // scale*log2e
    const int RW = 3 * DD;
    const int RWW = RW / 2;

    const __half* kg = g_qkvh + (size_t)b * TT * RW + DD + h * DK;
    const __half* vg = g_qkvh + (size_t)b * TT * RW + 2 * DD + h * DK;
    const unsigned* qw = reinterpret_cast<const unsigned*>(
        g_qkvh + (size_t)(b * TT + qrow0) * RW + h * DK);

    const int kkey = tid >> 2;            // 0..31
    const int kwg  = (tid & 3) * 4;       // word offset 0,4,8,12
    const int vj  = tid >> 3;             // 0..15
    const int vdg = (tid & 7) * 4;        // dims vdg..vdg+3

    // init ones columns (both buffers): 2*16*8 = 256 words, 2/thread
#pragma unroll
    for (int w = 0; w < 2; w++) {
        int id = tid * 2 + w;
        int bufi = id >> 7;
        int rem = id & 127;
        Vhs[bufi][rem >> 3][32 + (rem & 7)] = 0x3C003C00u;   // half2(1,1)
    }

    // prologue tile 0
    cp16(&Khs[0][kkey][kwg], kg + (size_t)kkey * RW + kwg * 2);
    cp_commit();
    {
        uint2 wa = *(const uint2*)(vg + (size_t)(2 * vj) * RW + vdg);
        uint2 wb = *(const uint2*)(vg + (size_t)(2 * vj + 1) * RW + vdg);
        uint4 p;
        p.x = prmt(wa.x, wb.x, 0x5410); p.y = prmt(wa.x, wb.x, 0x7632);
        p.z = prmt(wa.y, wb.y, 0x5410); p.w = prmt(wa.y, wb.y, 0x7632);
        *(uint4*)&Vhs[0][vj][vdg] = p;
    }

    // Q A-fragments (fp16 words straight from memory)
    unsigned qa[2][2][4];
#pragma unroll
    for (int mc = 0; mc < 2; mc++)
#pragma unroll
        for (int kc = 0; kc < 2; kc++) {
            int r = mc * 16 + g;
            qa[mc][kc][0] = qw[(size_t)r * RWW + kc * 8 + q];
            qa[mc][kc][1] = qw[(size_t)(r + 8) * RWW + kc * 8 + q];
            qa[mc][kc][2] = qw[(size_t)r * RWW + kc * 8 + q + 4];
            qa[mc][kc][3] = qw[(size_t)(r + 8) * RWW + kc * 8 + q + 4];
        }

    // Per-row exp bias: eb = 11 - ||q||*M_k*qs
    const float Mk = sqrtf(__int_as_float(g_mki[layer * BB * HH + b * HH + h]));
    float eb[2][2];
#pragma unroll
    for (int mc = 0; mc < 2; mc++) {
        float a0 = 0.0f, a1 = 0.0f;
#pragma unroll
        for (int kc = 0; kc < 2; kc++) {
            float2 f;
            f = __half22float2(*reinterpret_cast<__half2*>(&qa[mc][kc][0]));
            a0 = fmaf(f.x, f.x, fmaf(f.y, f.y, a0));
            f = __half22float2(*reinterpret_cast<__half2*>(&qa[mc][kc][2]));
            a0 = fmaf(f.x, f.x, fmaf(f.y, f.y, a0));
            f = __half22float2(*reinterpret_cast<__half2*>(&qa[mc][kc][1]));
            a1 = fmaf(f.x, f.x, fmaf(f.y, f.y, a1));
            f = __half22float2(*reinterpret_cast<__half2*>(&qa[mc][kc][3]));
            a1 = fmaf(f.x, f.x, fmaf(f.y, f.y, a1));
        }
        a0 += __shfl_xor_sync(0xffffffffu, a0, 1);
        a0 += __shfl_xor_sync(0xffffffffu, a0, 2);
        a1 += __shfl_xor_sync(0xffffffffu, a1, 1);
        a1 += __shfl_xor_sync(0xffffffffu, a1, 2);
        eb[mc][0] = 11.0f - sqrtf(a0) * Mk * qs;
        eb[mc][1] = 11.0f - sqrtf(a1) * Mk * qs;
    }

    float oacc[2][4][4];
    float lacc[2][4];
#pragma unroll
    for (int mc = 0; mc < 2; mc++) {
#pragma unroll
        for (int i = 0; i < 4; i++) lacc[mc][i] = 0.0f;
#pragma unroll
        for (int nc = 0; nc < 4; nc++)
#pragma unroll
            for (int i = 0; i < 4; i++) oacc[mc][nc][i] = 0.0f;
    }

    const int NT = TT / 32;
    for (int t = 0; t < NT; t++) {
        int buf = t & 1;
        int nb  = buf ^ 1;
        uint2 wa, wb;
        if (t + 1 < NT) {
            int k0 = (t + 1) * 32;
            cp16(&Khs[nb][kkey][kwg], kg + (size_t)(k0 + kkey) * RW + kwg * 2);
            cp_commit();
            wa = *(const uint2*)(vg + (size_t)(k0 + 2 * vj) * RW + vdg);
            wb = *(const uint2*)(vg + (size_t)(k0 + 2 * vj + 1) * RW + vdg);
            cp_wait<1>();
        } else {
            cp_wait<0>();
        }
        __syncthreads();

        // ---- S = Q K^T (fp16 k16) ----
        float sf[2][4][4];
#pragma unroll
        for (int mc = 0; mc < 2; mc++)
#pragma unroll
            for (int nc = 0; nc < 4; nc++)
#pragma unroll
                for (int i = 0; i < 4; i++) sf[mc][nc][i] = 0.0f;

#pragma unroll
        for (int nc = 0; nc < 4; nc++) {
#pragma unroll
            for (int kc = 0; kc < 2; kc++) {
                unsigned b0 = Khs[buf][nc * 8 + g][kc * 8 + q];
                unsigned b1 = Khs[buf][nc * 8 + g][kc * 8 + q + 4];
                mma16h(sf[0][nc], qa[0][kc], b0, b1);
                mma16h(sf[1][nc], qa[1][kc], b0, b1);
            }
        }

        // ---- fused softmax + PV: p = ex2h2(pack(s*qs+eb)), then MMA.
        //      ones-column MMA accumulates l on the tensor pipe. ----
#pragma unroll
        for (int kk = 0; kk < 2; kk++) {
            unsigned pa0[4], pa1[4];
#pragma unroll
            for (int j = 0; j < 2; j++) {
                int nc = 2 * kk + j;
                pa0[2*j]   = ex2h2(pkh2(fmaf(sf[0][nc][0], qs, eb[0][0]),
                                        fmaf(sf[0][nc][1], qs, eb[0][0])));
                pa0[2*j+1] = ex2h2(pkh2(fmaf(sf[0][nc][2], qs, eb[0][1]),
                                        fmaf(sf[0][nc][3], qs, eb[0][1])));
                pa1[2*j]   = ex2h2(pkh2(fmaf(sf[1][nc][0], qs, eb[1][0]),
                                        fmaf(sf[1][nc][1], qs, eb[1][0])));
                pa1[2*j+1] = ex2h2(pkh2(fmaf(sf[1][nc][2], qs, eb[1][1]),
                                        fmaf(sf[1][nc][3], qs, eb[1][1])));
            }
#pragma unroll
            for (int dn = 0; dn < 4; dn++) {
                unsigned b0 = Vhs[buf][8*kk + q][dn * 8 + g];
                unsigned b1 = Vhs[buf][8*kk + q + 4][dn * 8 + g];
                mma16h(oacc[0][dn], pa0, b0, b1);
                mma16h(oacc[1][dn], pa1, b0, b1);
            }
            // l += P @ ones
            unsigned o0 = Vhs[buf][8*kk + q][32 + g];
            unsigned o1 = Vhs[buf][8*kk + q + 4][32 + g];
            mma16h(lacc[0], pa0, o0, o1);
            mma16h(lacc[1], pa1, o0, o1);
        }

        // commit prefetched V tile
        if (t + 1 < NT) {
            uint4 p;
            p.x = prmt(wa.x, wb.x, 0x5410); p.y = prmt(wa.x, wb.x, 0x7632);
            p.z = prmt(wa.y, wb.y, 0x5410); p.w = prmt(wa.y, wb.y, 0x7632);
            *(uint4*)&Vhs[nb][vj][vdg] = p;
        }
        __syncthreads();
    }

    // ---- normalize (l from ones-MMA: no shuffles), store fp16 ----
    unsigned* ow = reinterpret_cast<unsigned*>(g_attnh);
#pragma unroll
    for (int mc = 0; mc < 2; mc++) {
        float inv0 = 1.0f / lacc[mc][0];
        float inv1 = 1.0f / lacc[mc][2];
        int r0 = b * TT + qrow0 + mc * 16 + g;
#pragma unroll
        for (int dn = 0; dn < 4; dn++) {
            int col = h * DK + dn * 8 + 2 * q;
            ow[(size_t)r0 * (DD/2) + col/2] =
                pkh2(oacc[mc][dn][0] * inv0, oacc[mc][dn][1] * inv0);
            ow[(size_t)(r0 + 8) * (DD/2) + col/2] =
                pkh2(oacc[mc][dn][2] * inv1, oacc[mc][dn][3] * inv1);
        }
    }
}

// ============================================================
// 4. Wout GEMM (fp16) + bias + residual + LayerNorm, fused.
//    Block 32x256 (full rows), 8 warps of 32x32, 256 blocks.
// ============================================================
#define WST_A 640       // words per A stage (32*20)
#define WST_B 5120      // words per B stage (256*20)
#define WRED_OFF (4*(WST_A+WST_B))
#define WSMEM_BYTES ((WRED_OFF+512)*4)

__global__ __launch_bounds__(256, 2)
void wout_ln_kernel(int layer, const float* __restrict__ bias,
                    const float* __restrict__ gamma,
                    const float* __restrict__ beta) {
    unsigned* As = (unsigned*)dynsmem;
    unsigned* Bs = As + 4 * WST_A;
    float* redS = dynsmem + WRED_OFF;       // [32][8]
    float* redQ = redS + 256;               // [32][8]
    const __half* __restrict__ A = g_attnh;
    const __half* __restrict__ Bmat = g_wout16 + (size_t)layer * DD * DD; // [n][k]

    const int tid  = threadIdx.x;
    const int lane = tid & 31;
    const int g    = lane >> 2;
    const int q    = lane & 3;
    const int warp = tid >> 5;
    const int wn   = warp * 32;
    const int bm   = blockIdx.x * 32;

    auto issue = [&](int s) {
        int k0 = s * 32;
        unsigned* Asb = As + (s & 3) * WST_A;
        unsigned* Bsb = Bs + (s & 3) * WST_B;
        if (tid < 128) {
            int r = tid >> 2, cw = (tid & 3) * 4;
            cp16(&Asb[r * 20 + cw], A + (size_t)(bm + r) * DD + k0 + cw * 2);
        }
#pragma unroll
        for (int p = 0; p < 4; p++) {
            int c = tid + p * 256;
            int r = c >> 2, cw = (c & 3) * 4;
            cp16(&Bsb[r * 20 + cw], Bmat + (size_t)r * DD + k0 + cw * 2);
        }
    };

    float acc[2][4][4];
#pragma unroll
    for (int mc = 0; mc < 2; mc++)
#pragma unroll
        for (int nc = 0; nc < 4; nc++)
#pragma unroll
            for (int i = 0; i < 4; i++) acc[mc][nc][i] = 0.0f;

    issue(0); cp_commit();
    issue(1); cp_commit();
    issue(2); cp_commit();

    const int NS = DD / 32;    // 8
    for (int s = 0; s < NS; s++) {
        cp_wait<2>();
        __syncthreads();
        if (s + 3 < NS) issue(s + 3);
        cp_commit();

        const unsigned* Asb = As + (s & 3) * WST_A;
        const unsigned* Bsb = Bs + (s & 3) * WST_B;
#pragma unroll
        for (int kc = 0; kc < 2; kc++) {
            int kb = kc * 8;
            unsigned af[2][4], bf[4][2];
#pragma unroll
            for (int mc = 0; mc < 2; mc++) {
                int r = mc * 16 + g;
                af[mc][0] = Asb[r * 20 + kb + q];
                af[mc][1] = Asb[(r + 8) * 20 + kb + q];
                af[mc][2] = Asb[r * 20 + kb + q + 4];
                af[mc][3] = Asb[(r + 8) * 20 + kb + q + 4];
            }
#pragma unroll
            for (int nc = 0; nc < 4; nc++) {
                int cc = wn + nc * 8 + g;
                bf[nc][0] = Bsb[cc * 20 + kb + q];
                bf[nc][1] = Bsb[cc * 20 + kb + q + 4];
            }
#pragma unroll
            for (int mc = 0; mc < 2; mc++)
#pragma unroll
                for (int nc = 0; nc < 4; nc++)
                    mma16h(acc[mc][nc], af[mc], bf[nc][0], bf[nc][1]);
        }
    }
    __syncthreads();

    // epilogue part 1: + bias + residual (fp32), partial row stats
#pragma unroll
    for (int mc = 0; mc < 2; mc++) {
        int rlo = bm + mc * 16 + g;
        float ssA = 0.f, sqA = 0.f, ssB = 0.f, sqB = 0.f;
#pragma unroll
        for (int nc = 0; nc < 4; nc++) {
            int col = wn + nc * 8 + 2 * q;
            float2 bi = *(const float2*)&bias[col];
            float2 h0 = *(const float2*)&g_h[(size_t)rlo * DD + col];
            float2 h1 = *(const float2*)&g_h[(size_t)(rlo + 8) * DD + col];
            acc[mc][nc][0] += bi.x + h0.x;
            acc[mc][nc][1] += bi.y + h0.y;
            acc[mc][nc][2] += bi.x + h1.x;
            acc[mc][nc][3] += bi.y + h1.y;
            ssA += acc[mc][nc][0] + acc[mc][nc][1];
            sqA += acc[mc][nc][0]*acc[mc][nc][0] + acc[mc][nc][1]*acc[mc][nc][1];
            ssB += acc[mc][nc][2] + acc[mc][nc][3];
            sqB += acc[mc][nc][2]*acc[mc][nc][2] + acc[mc][nc][3]*acc[mc][nc][3];
        }
        ssA += __shfl_xor_sync(0xffffffffu, ssA, 1); ssA += __shfl_xor_sync(0xffffffffu, ssA, 2);
        sqA += __shfl_xor_sync(0xffffffffu, sqA, 1); sqA += __shfl_xor_sync(0xffffffffu, sqA, 2);
        ssB += __shfl_xor_sync(0xffffffffu, ssB, 1); ssB += __shfl_xor_sync(0xffffffffu, ssB, 2);
        sqB += __shfl_xor_sync(0xffffffffu, sqB, 1); sqB += __shfl_xor_sync(0xffffffffu, sqB, 2);
        if (q == 0) {
            int rl = mc * 16 + g;
            redS[rl * 8 + warp] = ssA;  redQ[rl * 8 + warp] = sqA;
            redS[(rl + 8) * 8 + warp] = ssB;  redQ[(rl + 8) * 8 + warp] = sqB;
        }
    }
    __syncthreads();

    // epilogue part 2: normalize + store (fp32 + fp16)
    unsigned* hw = reinterpret_cast<unsigned*>(g_h16);
#pragma unroll
    for (int mc = 0; mc < 2; mc++) {
        int rlA = mc * 16 + g;
        int rlB = rlA + 8;
        float sA = 0.f, qA = 0.f, sB = 0.f, qB = 0.f;
#pragma unroll
        for (int w = 0; w < 8; w++) {
            sA += redS[rlA * 8 + w];  qA += redQ[rlA * 8 + w];
            sB += redS[rlB * 8 + w];  qB += redQ[rlB * 8 + w];
        }
        float muA = sA * (1.0f / DD);
        float muB = sB * (1.0f / DD);
        float rsA = rsqrtf(qA * (1.0f / DD) - muA * muA + LN_EPS);
        float rsB = rsqrtf(qB * (1.0f / DD) - muB * muB + LN_EPS);
        int rowA = bm + rlA;
#pragma unroll
        for (int nc = 0; nc < 4; nc++) {
            int col = wn + nc * 8 + 2 * q;
            float2 ga = *(const float2*)&gamma[col];
            float2 be = *(const float2*)&beta[col];
            float v0 = (acc[mc][nc][0] - muA) * rsA * ga.x + be.x;
            float v1 = (acc[mc][nc][1] - muA) * rsA * ga.y + be.y;
            float v2 = (acc[mc][nc][2] - muB) * rsB * ga.x + be.x;
            float v3 = (acc[mc][nc][3] - muB) * rsB * ga.y + be.y;
            *(float2*)&g_h[(size_t)rowA * DD + col]       = make_float2(v0, v1);
            *(float2*)&g_h[(size_t)(rowA + 8) * DD + col] = make_float2(v2, v3);
            hw[(size_t)rowA * (DD/2) + col/2]       = pkh2(v0, v1);
            hw[(size_t)(rowA + 8) * (DD/2) + col/2] = pkh2(v2, v3);
        }
    }
}

// ============================================================
// 5. Head
// ============================================================
__global__ void head_kernel(const float* __restrict__ Wo,
                            const float* __restrict__ bo,
                            float* __restrict__ out) {
    int b = blockIdx.x / 3;
    int j = blockIdx.x - b * 3;
    int lane = threadIdx.x;
    const float* hr = g_h + (size_t)(b * TT + (TT - 1)) * DD;
    float s = 0.0f;
    for (int d = lane; d < DD; d += 32)
        s = fmaf(hr[d], Wo[d * 3 + j], s);
#pragma unroll
    for (int o = 16; o > 0; o >>= 1)
        s += __shfl_xor_sync(0xffffffffu, s, o);
    if (lane == 0) out[b * 3 + j] = s + bo[j];
}

// ============================================================
// launch
// ============================================================
extern "C" void kernel_launch(void* const* d_in, const int* in_sizes, int n_in,
                              void* d_out, int out_size) {
    const float* x    = (const float*)d_in[0];
    const float* Wp   = (const float*)d_in[1];
    const float* bp   = (const float*)d_in[2];
    const float* pos  = (const float*)d_in[3];
    const float* Wqkv = (const float*)d_in[4];
    const float* bqkv = (const float*)d_in[5];
    const float* Wout = (const float*)d_in[6];
    const float* bout = (const float*)d_in[7];
    const float* ln_g = (const float*)d_in[8];
    const float* ln_b = (const float*)d_in[9];
    const float* Wo   = (const float*)d_in[10];
    const float* bo   = (const float*)d_in[11];
    float* out = (float*)d_out;

    cudaFuncSetAttribute(qkv_gemm_kernel, cudaFuncAttributeMaxDynamicSharedMemorySize, QSMEM_BYTES);
    cudaFuncSetAttribute(wout_ln_kernel,  cudaFuncAttributeMaxDynamicSharedMemorySize, WSMEM_BYTES);

    __half* d_wqkv16 = nullptr;
    __half* d_wout16 = nullptr;
    cudaGetSymbolAddress((void**)&d_wqkv16, g_wqkv16);
    cudaGetSymbolAddress((void**)&d_wout16, g_wout16);

    transp_kernel<<<dim3(DD/32, (3*DD)/32, LL), dim3(32, 8)>>>(Wqkv, d_wqkv16, 3*DD);
    transp_kernel<<<dim3(DD/32, DD/32, LL),     dim3(32, 8)>>>(Wout, d_wout16, DD);
    proj_kernel<<<(NROW * DD + 255) / 256, 256>>>(x, Wp, bp, pos);

    for (int l = 0; l < LL; l++) {
        qkv_gemm_kernel<<<dim3((3 * DD) / 128, NROW / 128), 256, QSMEM_BYTES>>>(
            l, bqkv + (size_t)l * 3 * DD);
        attn_tc_kernel<<<dim3(TT / 128, HH, BB), 128>>>(l);
        wout_ln_kernel<<<NROW / 32, 256, WSMEM_BYTES>>>(
            l, bout + (size_t)l * DD, ln_g + (size_t)l * DD, ln_b + (size_t)l * DD);
    }

    head_kernel<<<24, 32>>>(Wo, bo, out);
}